// round 1
// baseline (speedup 1.0000x reference)
#include <cuda_runtime.h>
#include <math.h>

#define TKN 4096
#define SEQ 2048
#define DIM 1024
#define NH 16
#define HD 64
#define NE 8
#define HID 4096
#define CAP 1280
#define NA 8192   // TOP_K * TKN

// ---------------- scratch (static device globals; no allocation) ----------------
__device__ float g_h[TKN * DIM];
__device__ float g_qkv[TKN * 3 * DIM];
__device__ float g_o[TKN * DIM];
__device__ float g_x2[TKN * DIM];
__device__ float g_h2[TKN * DIM];
__device__ float g_probs[TKN * NE];
__device__ int   g_eid[NA];
__device__ float g_wflat[NA];
__device__ int   g_pos[NA];
__device__ float g_buf[NE * CAP * DIM];
__device__ float g_hh[(size_t)NE * CAP * HID];
__device__ float g_oute[NE * CAP * DIM];

// ---------------- utility ----------------
__device__ __forceinline__ float gelu_f(float x) {
    float x3 = x * x * x;
    float t = tanhf(0.7978845608028654f * (x + 0.044715f * x3));
    return 0.5f * x * (1.0f + t);
}

// ---------------- zero capacity buffer ----------------
__global__ void zero_buf_kernel() {
    size_t i = (size_t)blockIdx.x * blockDim.x + threadIdx.x;
    float4* p = (float4*)g_buf;
    if (i < (size_t)NE * CAP * DIM / 4) p[i] = make_float4(0.f, 0.f, 0.f, 0.f);
}

// ---------------- layernorm: one block per row ----------------
__global__ __launch_bounds__(256) void ln_kernel(const float* __restrict__ x,
                                                 const float* __restrict__ g,
                                                 const float* __restrict__ b,
                                                 float* __restrict__ out) {
    int row = blockIdx.x, tid = threadIdx.x;
    const float4* xr = (const float4*)(x + (size_t)row * DIM);
    float4 v = xr[tid];
    float s = v.x + v.y + v.z + v.w;
    float q = v.x * v.x + v.y * v.y + v.z * v.z + v.w * v.w;
    __shared__ float ss[8], sq[8];
    #pragma unroll
    for (int o = 16; o; o >>= 1) {
        s += __shfl_xor_sync(0xffffffffu, s, o);
        q += __shfl_xor_sync(0xffffffffu, q, o);
    }
    int w = tid >> 5;
    if ((tid & 31) == 0) { ss[w] = s; sq[w] = q; }
    __syncthreads();
    __shared__ float mu_s, rs_s;
    if (tid == 0) {
        float S = 0.f, Q = 0.f;
        #pragma unroll
        for (int i = 0; i < 8; i++) { S += ss[i]; Q += sq[i]; }
        float mu = S / DIM;
        float var = Q / DIM - mu * mu;
        mu_s = mu;
        rs_s = rsqrtf(var + 1e-6f);
    }
    __syncthreads();
    float mu = mu_s, rs = rs_s;
    float4 gg = ((const float4*)g)[tid];
    float4 bb = ((const float4*)b)[tid];
    float4 o4;
    o4.x = (v.x - mu) * rs * gg.x + bb.x;
    o4.y = (v.y - mu) * rs * gg.y + bb.y;
    o4.z = (v.z - mu) * rs * gg.z + bb.z;
    o4.w = (v.w - mu) * rs * gg.w + bb.w;
    ((float4*)(out + (size_t)row * DIM))[tid] = o4;
}

// ---------------- tiled SGEMM: C = A(MxK) @ W(KxN) + bias, epilogues ----------------
#define EPI_BIAS 0
#define EPI_BIAS_RES 1
#define EPI_BIAS_GELU 2

template <int EPI>
__global__ __launch_bounds__(256) void gemm_kernel(
    const float* __restrict__ A, const float* __restrict__ W,
    const float* __restrict__ bias, const float* __restrict__ res,
    float* __restrict__ C, int M, int N, int K,
    size_t aSz, size_t wSz, size_t biasSz, size_t cSz) {
    int z = blockIdx.z;
    A += aSz * z; W += wSz * z; bias += biasSz * z; C += cSz * z;
    __shared__ float As[8][128];
    __shared__ float Bs[8][128];
    int tid = threadIdx.x;
    int m0 = blockIdx.y * 128, n0 = blockIdx.x * 128;
    int arow = tid >> 1, acol = (tid & 1) * 4;
    int brow = tid >> 5, bcol = (tid & 31) * 4;
    const float* Ap = A + (size_t)(m0 + arow) * K + acol;
    const float* Wp = W + (size_t)brow * N + n0 + bcol;
    float4 aR = *(const float4*)Ap;
    float4 bR = *(const float4*)Wp;
    float acc[8][8];
    #pragma unroll
    for (int i = 0; i < 8; i++)
        #pragma unroll
        for (int j = 0; j < 8; j++) acc[i][j] = 0.f;
    int tx = tid & 15, ty = tid >> 4;
    int nk = K >> 3;
    int kt = 0;
    while (true) {
        __syncthreads();
        As[acol + 0][arow] = aR.x;
        As[acol + 1][arow] = aR.y;
        As[acol + 2][arow] = aR.z;
        As[acol + 3][arow] = aR.w;
        *(float4*)&Bs[brow][bcol] = bR;
        __syncthreads();
        kt++;
        if (kt < nk) {
            aR = *(const float4*)(Ap + kt * 8);
            bR = *(const float4*)(Wp + (size_t)kt * 8 * N);
        }
        #pragma unroll
        for (int k = 0; k < 8; k++) {
            float a[8], bv[8];
            *(float4*)&a[0] = *(float4*)&As[k][ty * 8];
            *(float4*)&a[4] = *(float4*)&As[k][ty * 8 + 4];
            *(float4*)&bv[0] = *(float4*)&Bs[k][tx * 8];
            *(float4*)&bv[4] = *(float4*)&Bs[k][tx * 8 + 4];
            #pragma unroll
            for (int i = 0; i < 8; i++)
                #pragma unroll
                for (int j = 0; j < 8; j++) acc[i][j] += a[i] * bv[j];
        }
        if (kt == nk) break;
    }
    #pragma unroll
    for (int i = 0; i < 8; i++) {
        int r = m0 + ty * 8 + i;
        #pragma unroll
        for (int j = 0; j < 8; j += 4) {
            int c = n0 + tx * 8 + j;
            float4 bb = *(const float4*)&bias[c];
            float4 v;
            v.x = acc[i][j + 0] + bb.x;
            v.y = acc[i][j + 1] + bb.y;
            v.z = acc[i][j + 2] + bb.z;
            v.w = acc[i][j + 3] + bb.w;
            if (EPI == EPI_BIAS_RES) {
                float4 rr = *(const float4*)&res[(size_t)r * N + c];
                v.x += rr.x; v.y += rr.y; v.z += rr.z; v.w += rr.w;
            }
            if (EPI == EPI_BIAS_GELU) {
                v.x = gelu_f(v.x); v.y = gelu_f(v.y);
                v.z = gelu_f(v.z); v.w = gelu_f(v.w);
            }
            *(float4*)&C[(size_t)r * N + c] = v;
        }
    }
}

// ---------------- RoPE in-place on q,k inside g_qkv ----------------
__global__ void rope_kernel(const float* __restrict__ cosT, const float* __restrict__ sinT) {
    int idx = blockIdx.x * blockDim.x + threadIdx.x;  // 2*TKN*NH*32 = 4194304
    if (idx >= 2 * TKN * NH * 32) return;
    int i = idx & 31;
    int h = (idx >> 5) & 15;
    int t = (idx >> 9) & 4095;
    int qk = idx >> 21;
    int s = t & (SEQ - 1);
    size_t base = (size_t)t * 3072 + (size_t)qk * 1024 + h * 64;
    float c0 = cosT[s * 64 + i], s0 = sinT[s * 64 + i];
    float c1 = cosT[s * 64 + i + 32], s1 = sinT[s * 64 + i + 32];
    float a = g_qkv[base + i];
    float b = g_qkv[base + i + 32];
    g_qkv[base + i] = a * c0 - b * s0;
    g_qkv[base + i + 32] = b * c1 + a * s1;
}

// ---------------- fused flash attention (fp32, online softmax) ----------------
// grid (SEQ/128, NH, B). 128 threads; each thread owns one query row.
__global__ __launch_bounds__(128) void flash_kernel() {
    int b = blockIdx.z, h = blockIdx.y, q0 = blockIdx.x * 128;
    int t = threadIdx.x;
    __shared__ float QsT[64][132];
    __shared__ float Ks[16][64];
    __shared__ float Vs[16][64];

    // Load Q tile (post-RoPE), transposed so per-thread column reads are conflict-free.
    size_t qbase = ((size_t)(b * SEQ + q0)) * 3072 + h * 64;
    #pragma unroll
    for (int i = 0; i < 16; i++) {
        int i4 = i * 128 + t;                // 2048 float4 = 128 rows x 16
        int row = i4 >> 4;
        int c = (i4 & 15) * 4;
        float4 v = *(const float4*)&g_qkv[qbase + (size_t)row * 3072 + c];
        QsT[c + 0][row] = v.x;
        QsT[c + 1][row] = v.y;
        QsT[c + 2][row] = v.z;
        QsT[c + 3][row] = v.w;
    }
    float acc[64];
    #pragma unroll
    for (int d = 0; d < 64; d++) acc[d] = 0.f;
    float m = -1e30f, l = 0.f;
    __syncthreads();

    for (int kk0 = 0; kk0 < SEQ; kk0 += 16) {
        size_t kbase = ((size_t)(b * SEQ + kk0)) * 3072 + h * 64;
        #pragma unroll
        for (int i = 0; i < 2; i++) {
            int i4 = i * 128 + t;            // 256 float4 = 16 rows x 16
            int row = i4 >> 4;
            int c = (i4 & 15) * 4;
            *(float4*)&Ks[row][c] = *(const float4*)&g_qkv[kbase + (size_t)row * 3072 + 1024 + c];
            *(float4*)&Vs[row][c] = *(const float4*)&g_qkv[kbase + (size_t)row * 3072 + 2048 + c];
        }
        __syncthreads();

        float s[16];
        #pragma unroll
        for (int j = 0; j < 16; j++) s[j] = 0.f;
        #pragma unroll
        for (int k4 = 0; k4 < 16; k4++) {
            float q0v = QsT[k4 * 4 + 0][t];
            float q1v = QsT[k4 * 4 + 1][t];
            float q2v = QsT[k4 * 4 + 2][t];
            float q3v = QsT[k4 * 4 + 3][t];
            #pragma unroll
            for (int j = 0; j < 16; j++) {
                float4 kv = *(const float4*)&Ks[j][k4 * 4];
                s[j] += q0v * kv.x + q1v * kv.y + q2v * kv.z + q3v * kv.w;
            }
        }
        float mt = m;
        #pragma unroll
        for (int j = 0; j < 16; j++) { s[j] *= 0.125f; mt = fmaxf(mt, s[j]); }
        float corr = __expf(m - mt);
        m = mt;
        l *= corr;
        #pragma unroll
        for (int d = 0; d < 64; d++) acc[d] *= corr;
        #pragma unroll
        for (int j = 0; j < 16; j++) {
            float p = __expf(s[j] - mt);
            l += p;
            #pragma unroll
            for (int d4 = 0; d4 < 16; d4++) {
                float4 vv = *(const float4*)&Vs[j][d4 * 4];
                acc[d4 * 4 + 0] += p * vv.x;
                acc[d4 * 4 + 1] += p * vv.y;
                acc[d4 * 4 + 2] += p * vv.z;
                acc[d4 * 4 + 3] += p * vv.w;
            }
        }
        __syncthreads();
    }
    float inv = 1.0f / l;
    size_t obase = ((size_t)(b * SEQ + q0 + t)) * DIM + h * 64;
    #pragma unroll
    for (int d4 = 0; d4 < 16; d4++) {
        float4 v;
        v.x = acc[d4 * 4 + 0] * inv;
        v.y = acc[d4 * 4 + 1] * inv;
        v.z = acc[d4 * 4 + 2] * inv;
        v.w = acc[d4 * 4 + 3] * inv;
        *(float4*)&g_o[obase + d4 * 4] = v;
    }
}

// ---------------- gating: softmax over 8 experts + top-2 (warp per token) ----------------
__global__ __launch_bounds__(128) void gate_kernel(const float* __restrict__ gate_w) {
    int t = blockIdx.x * 4 + (threadIdx.x >> 5);
    int lane = threadIdx.x & 31;
    const float* xr = g_h2 + (size_t)t * DIM;
    float p[8];
    #pragma unroll
    for (int e = 0; e < 8; e++) p[e] = 0.f;
    for (int it = 0; it < 32; it++) {
        int d = it * 32 + lane;
        float xv = xr[d];
        const float4* gw = (const float4*)(gate_w + d * 8);
        float4 g0 = gw[0], g1 = gw[1];
        p[0] += xv * g0.x; p[1] += xv * g0.y; p[2] += xv * g0.z; p[3] += xv * g0.w;
        p[4] += xv * g1.x; p[5] += xv * g1.y; p[6] += xv * g1.z; p[7] += xv * g1.w;
    }
    #pragma unroll
    for (int e = 0; e < 8; e++)
        #pragma unroll
        for (int o = 16; o; o >>= 1) p[e] += __shfl_xor_sync(0xffffffffu, p[e], o);
    if (lane == 0) {
        float mx = p[0];
        #pragma unroll
        for (int e = 1; e < 8; e++) mx = fmaxf(mx, p[e]);
        float ex[8], sum = 0.f;
        #pragma unroll
        for (int e = 0; e < 8; e++) { ex[e] = __expf(p[e] - mx); sum += ex[e]; }
        float inv = 1.f / sum;
        float pr[8];
        #pragma unroll
        for (int e = 0; e < 8; e++) { pr[e] = ex[e] * inv; g_probs[t * 8 + e] = pr[e]; }
        int i1 = 0;
        float v1 = pr[0];
        #pragma unroll
        for (int e = 1; e < 8; e++) if (pr[e] > v1) { v1 = pr[e]; i1 = e; }
        int i2 = -1;
        float v2 = -1.f;
        #pragma unroll
        for (int e = 0; e < 8; e++) if (e != i1 && pr[e] > v2) { v2 = pr[e]; i2 = e; }
        float dn = 1.f / (v1 + v2);
        g_eid[t] = i1;
        g_eid[TKN + t] = i2;
        g_wflat[t] = v1 * dn;
        g_wflat[TKN + t] = v2 * dn;
    }
}

// ---------------- per-expert sequential positions (reference cumsum order) ----------------
__global__ void pos_kernel() {
    int e = threadIdx.x >> 5;   // 8 warps, one per expert
    int lane = threadIdx.x & 31;
    int base = 0;
    for (int a0 = 0; a0 < NA; a0 += 32) {
        int ea = g_eid[a0 + lane];
        unsigned mask = __ballot_sync(0xffffffffu, ea == e);
        if (ea == e) g_pos[a0 + lane] = base + __popc(mask & ((1u << lane) - 1));
        base += __popc(mask);
    }
}

// ---------------- scatter kept tokens into capacity buffer ----------------
__global__ __launch_bounds__(256) void scatter_kernel() {
    int a = blockIdx.x;
    int p = g_pos[a];
    if (p >= CAP) return;
    int e = g_eid[a];
    int tok = a & (TKN - 1);
    const float4* src = (const float4*)(g_h2 + (size_t)tok * DIM);
    float4* dst = (float4*)(g_buf + ((size_t)e * CAP + p) * DIM);
    dst[threadIdx.x] = src[threadIdx.x];
}

// ---------------- aux loss ----------------
__global__ __launch_bounds__(256) void aux_kernel(float* __restrict__ out, int out_size) {
    __shared__ float red[256];
    int tid = threadIdx.x;
    float me[8], cnt[8];
    #pragma unroll
    for (int e = 0; e < 8; e++) { me[e] = 0.f; cnt[e] = 0.f; }
    for (int t = tid; t < TKN; t += 256) {
        #pragma unroll
        for (int e = 0; e < 8; e++) me[e] += g_probs[t * 8 + e];
    }
    for (int a = tid; a < NA; a += 256) cnt[g_eid[a]] += 1.f;
    float auxv = 0.f;
    for (int e = 0; e < 8; e++) {
        red[tid] = me[e];
        __syncthreads();
        for (int st = 128; st; st >>= 1) { if (tid < st) red[tid] += red[tid + st]; __syncthreads(); }
        float meS = red[0];
        __syncthreads();
        red[tid] = cnt[e];
        __syncthreads();
        for (int st = 128; st; st >>= 1) { if (tid < st) red[tid] += red[tid + st]; __syncthreads(); }
        float cS = red[0];
        __syncthreads();
        auxv += (meS / (float)TKN) * (cS / (float)NA);
    }
    if (tid == 0 && out_size > TKN * DIM) out[TKN * DIM] = 8.f * auxv;
}

// ---------------- combine: out = x2 + weighted expert outputs ----------------
__global__ __launch_bounds__(256) void final_kernel(float* __restrict__ out) {
    int t = blockIdx.x;
    int tid = threadIdx.x;
    int p1 = g_pos[t], p2 = g_pos[TKN + t];
    int e1 = g_eid[t], e2 = g_eid[TKN + t];
    float w1 = (p1 < CAP) ? g_wflat[t] : 0.f;
    float w2 = (p2 < CAP) ? g_wflat[TKN + t] : 0.f;
    p1 = min(p1, CAP - 1);
    p2 = min(p2, CAP - 1);
    const float4* a = (const float4*)(g_oute + ((size_t)e1 * CAP + p1) * DIM);
    const float4* b = (const float4*)(g_oute + ((size_t)e2 * CAP + p2) * DIM);
    const float4* xr = (const float4*)(g_x2 + (size_t)t * DIM);
    float4 av = a[tid], bv = b[tid], xv = xr[tid];
    float4 r;
    r.x = xv.x + w1 * av.x + w2 * bv.x;
    r.y = xv.y + w1 * av.y + w2 * bv.y;
    r.z = xv.z + w1 * av.z + w2 * bv.z;
    r.w = xv.w + w1 * av.w + w2 * bv.w;
    ((float4*)(out + (size_t)t * DIM))[tid] = r;
}

// ---------------- host ----------------
extern "C" void kernel_launch(void* const* d_in, const int* in_sizes, int n_in,
                              void* d_out, int out_size) {
    const float* x     = (const float*)d_in[0];
    const float* cosT  = (const float*)d_in[1];
    const float* sinT  = (const float*)d_in[2];
    const float* ln1g  = (const float*)d_in[3];
    const float* ln1b  = (const float*)d_in[4];
    const float* ln2g  = (const float*)d_in[5];
    const float* ln2b  = (const float*)d_in[6];
    const float* wqkv  = (const float*)d_in[7];
    const float* bqkv  = (const float*)d_in[8];
    const float* wo    = (const float*)d_in[9];
    const float* bo    = (const float*)d_in[10];
    const float* gatew = (const float*)d_in[11];
    const float* w1    = (const float*)d_in[12];
    const float* b1    = (const float*)d_in[13];
    const float* w2    = (const float*)d_in[14];
    const float* b2    = (const float*)d_in[15];
    float* out = (float*)d_out;

    void *p_h, *p_qkv, *p_o, *p_x2, *p_h2, *p_buf, *p_hh, *p_oute;
    cudaGetSymbolAddress(&p_h, g_h);
    cudaGetSymbolAddress(&p_qkv, g_qkv);
    cudaGetSymbolAddress(&p_o, g_o);
    cudaGetSymbolAddress(&p_x2, g_x2);
    cudaGetSymbolAddress(&p_h2, g_h2);
    cudaGetSymbolAddress(&p_buf, g_buf);
    cudaGetSymbolAddress(&p_hh, g_hh);
    cudaGetSymbolAddress(&p_oute, g_oute);

    zero_buf_kernel<<<(NE * CAP * DIM / 4 + 255) / 256, 256>>>();

    // ln1
    ln_kernel<<<TKN, 256>>>(x, ln1g, ln1b, (float*)p_h);
    // qkv = h @ wqkv + bqkv
    gemm_kernel<EPI_BIAS><<<dim3(3072 / 128, TKN / 128, 1), 256>>>(
        (const float*)p_h, wqkv, bqkv, nullptr, (float*)p_qkv, TKN, 3072, 1024, 0, 0, 0, 0);
    // rope on q,k
    rope_kernel<<<(2 * TKN * NH * 32) / 256, 256>>>(cosT, sinT);
    // attention
    flash_kernel<<<dim3(SEQ / 128, NH, 2), 128>>>();
    // x2 = o @ wo + bo + x
    gemm_kernel<EPI_BIAS_RES><<<dim3(1024 / 128, TKN / 128, 1), 256>>>(
        (const float*)p_o, wo, bo, x, (float*)p_x2, TKN, 1024, 1024, 0, 0, 0, 0);
    // ln2
    ln_kernel<<<TKN, 256>>>((const float*)p_x2, ln2g, ln2b, (float*)p_h2);
    // gating + routing
    gate_kernel<<<TKN / 4, 128>>>(gatew);
    pos_kernel<<<1, 256>>>();
    scatter_kernel<<<NA, 256>>>();
    aux_kernel<<<1, 256>>>(out, out_size);
    // expert FFN (batched over experts in grid.z)
    gemm_kernel<EPI_BIAS_GELU><<<dim3(HID / 128, CAP / 128, NE), 256>>>(
        (const float*)p_buf, w1, b1, nullptr, (float*)p_hh, CAP, HID, DIM,
        (size_t)CAP * DIM, (size_t)DIM * HID, (size_t)HID, (size_t)CAP * HID);
    gemm_kernel<EPI_BIAS><<<dim3(DIM / 128, CAP / 128, NE), 256>>>(
        (const float*)p_hh, w2, b2, nullptr, (float*)p_oute, CAP, DIM, HID,
        (size_t)CAP * HID, (size_t)HID * DIM, (size_t)DIM, (size_t)CAP * DIM);
    // combine + residual
    final_kernel<<<TKN, 256>>>(out);
}

// round 2
// speedup vs baseline: 1.0016x; 1.0016x over previous
#include <cuda_runtime.h>
#include <math.h>

#define TKN 4096
#define SEQ 2048
#define DIM 1024
#define NH 16
#define HD 64
#define NE 8
#define HID 4096
#define CAP 1280
#define NA 8192   // TOP_K * TKN

// ---------------- scratch (static device globals; no allocation) ----------------
__device__ float g_h[TKN * DIM];
__device__ float g_qkv[TKN * 3 * DIM];
__device__ float g_o[TKN * DIM];
__device__ float g_x2[TKN * DIM];
__device__ float g_h2[TKN * DIM];
__device__ float g_probs[TKN * NE];
__device__ int   g_eid[NA];
__device__ float g_wflat[NA];
__device__ int   g_pos[NA];
__device__ float g_buf[NE * CAP * DIM];
__device__ float g_hh[(size_t)NE * CAP * HID];
__device__ float g_oute[NE * CAP * DIM];

// ---------------- utility ----------------
__device__ __forceinline__ float gelu_f(float x) {
    float x3 = x * x * x;
    float t = tanhf(0.7978845608028654f * (x + 0.044715f * x3));
    return 0.5f * x * (1.0f + t);
}

// ---------------- zero capacity buffer ----------------
__global__ void zero_buf_kernel() {
    size_t i = (size_t)blockIdx.x * blockDim.x + threadIdx.x;
    float4* p = (float4*)g_buf;
    if (i < (size_t)NE * CAP * DIM / 4) p[i] = make_float4(0.f, 0.f, 0.f, 0.f);
}

// ---------------- layernorm: one block per row ----------------
__global__ __launch_bounds__(256) void ln_kernel(const float* __restrict__ x,
                                                 const float* __restrict__ g,
                                                 const float* __restrict__ b,
                                                 float* __restrict__ out) {
    int row = blockIdx.x, tid = threadIdx.x;
    const float4* xr = (const float4*)(x + (size_t)row * DIM);
    float4 v = xr[tid];
    float s = v.x + v.y + v.z + v.w;
    float q = v.x * v.x + v.y * v.y + v.z * v.z + v.w * v.w;
    __shared__ float ss[8], sq[8];
    #pragma unroll
    for (int o = 16; o; o >>= 1) {
        s += __shfl_xor_sync(0xffffffffu, s, o);
        q += __shfl_xor_sync(0xffffffffu, q, o);
    }
    int w = tid >> 5;
    if ((tid & 31) == 0) { ss[w] = s; sq[w] = q; }
    __syncthreads();
    __shared__ float mu_s, rs_s;
    if (tid == 0) {
        float S = 0.f, Q = 0.f;
        #pragma unroll
        for (int i = 0; i < 8; i++) { S += ss[i]; Q += sq[i]; }
        float mu = S / DIM;
        float var = Q / DIM - mu * mu;
        mu_s = mu;
        rs_s = rsqrtf(var + 1e-6f);
    }
    __syncthreads();
    float mu = mu_s, rs = rs_s;
    float4 gg = ((const float4*)g)[tid];
    float4 bb = ((const float4*)b)[tid];
    float4 o4;
    o4.x = (v.x - mu) * rs * gg.x + bb.x;
    o4.y = (v.y - mu) * rs * gg.y + bb.y;
    o4.z = (v.z - mu) * rs * gg.z + bb.z;
    o4.w = (v.w - mu) * rs * gg.w + bb.w;
    ((float4*)(out + (size_t)row * DIM))[tid] = o4;
}

// ---------------- tiled SGEMM: C = A(MxK) @ W(KxN) + bias, epilogues ----------------
#define EPI_BIAS 0
#define EPI_BIAS_RES 1
#define EPI_BIAS_GELU 2

template <int EPI>
__global__ __launch_bounds__(256) void gemm_kernel(
    const float* __restrict__ A, const float* __restrict__ W,
    const float* __restrict__ bias, const float* __restrict__ res,
    float* __restrict__ C, int M, int N, int K,
    size_t aSz, size_t wSz, size_t biasSz, size_t cSz) {
    int z = blockIdx.z;
    A += aSz * z; W += wSz * z; bias += biasSz * z; C += cSz * z;
    __shared__ float As[8][128];
    __shared__ float Bs[8][128];
    int tid = threadIdx.x;
    int m0 = blockIdx.y * 128, n0 = blockIdx.x * 128;
    int arow = tid >> 1, acol = (tid & 1) * 4;
    int brow = tid >> 5, bcol = (tid & 31) * 4;
    const float* Ap = A + (size_t)(m0 + arow) * K + acol;
    const float* Wp = W + (size_t)brow * N + n0 + bcol;
    float4 aR = *(const float4*)Ap;
    float4 bR = *(const float4*)Wp;
    float acc[8][8];
    #pragma unroll
    for (int i = 0; i < 8; i++)
        #pragma unroll
        for (int j = 0; j < 8; j++) acc[i][j] = 0.f;
    int tx = tid & 15, ty = tid >> 4;
    int nk = K >> 3;
    int kt = 0;
    while (true) {
        __syncthreads();
        As[acol + 0][arow] = aR.x;
        As[acol + 1][arow] = aR.y;
        As[acol + 2][arow] = aR.z;
        As[acol + 3][arow] = aR.w;
        *(float4*)&Bs[brow][bcol] = bR;
        __syncthreads();
        kt++;
        if (kt < nk) {
            aR = *(const float4*)(Ap + kt * 8);
            bR = *(const float4*)(Wp + (size_t)kt * 8 * N);
        }
        #pragma unroll
        for (int k = 0; k < 8; k++) {
            float a[8], bv[8];
            *(float4*)&a[0] = *(float4*)&As[k][ty * 8];
            *(float4*)&a[4] = *(float4*)&As[k][ty * 8 + 4];
            *(float4*)&bv[0] = *(float4*)&Bs[k][tx * 8];
            *(float4*)&bv[4] = *(float4*)&Bs[k][tx * 8 + 4];
            #pragma unroll
            for (int i = 0; i < 8; i++)
                #pragma unroll
                for (int j = 0; j < 8; j++) acc[i][j] += a[i] * bv[j];
        }
        if (kt == nk) break;
    }
    #pragma unroll
    for (int i = 0; i < 8; i++) {
        int r = m0 + ty * 8 + i;
        #pragma unroll
        for (int j = 0; j < 8; j += 4) {
            int c = n0 + tx * 8 + j;
            float4 bb = *(const float4*)&bias[c];
            float4 v;
            v.x = acc[i][j + 0] + bb.x;
            v.y = acc[i][j + 1] + bb.y;
            v.z = acc[i][j + 2] + bb.z;
            v.w = acc[i][j + 3] + bb.w;
            if (EPI == EPI_BIAS_RES) {
                float4 rr = *(const float4*)&res[(size_t)r * N + c];
                v.x += rr.x; v.y += rr.y; v.z += rr.z; v.w += rr.w;
            }
            if (EPI == EPI_BIAS_GELU) {
                v.x = gelu_f(v.x); v.y = gelu_f(v.y);
                v.z = gelu_f(v.z); v.w = gelu_f(v.w);
            }
            *(float4*)&C[(size_t)r * N + c] = v;
        }
    }
}

// ---------------- RoPE in-place on q,k inside g_qkv ----------------
__global__ void rope_kernel(const float* __restrict__ cosT, const float* __restrict__ sinT) {
    int idx = blockIdx.x * blockDim.x + threadIdx.x;  // 2*TKN*NH*32 = 4194304
    if (idx >= 2 * TKN * NH * 32) return;
    int i = idx & 31;
    int h = (idx >> 5) & 15;
    int t = (idx >> 9) & 4095;
    int qk = idx >> 21;
    int s = t & (SEQ - 1);
    size_t base = (size_t)t * 3072 + (size_t)qk * 1024 + h * 64;
    float c0 = cosT[s * 64 + i], s0 = sinT[s * 64 + i];
    float c1 = cosT[s * 64 + i + 32], s1 = sinT[s * 64 + i + 32];
    float a = g_qkv[base + i];
    float b = g_qkv[base + i + 32];
    g_qkv[base + i] = a * c0 - b * s0;
    g_qkv[base + i + 32] = b * c1 + a * s1;
}

// ---------------- fused flash attention (fp32, online softmax) ----------------
// grid (SEQ/128, NH, B). 128 threads; each thread owns one query row.
__global__ __launch_bounds__(128) void flash_kernel() {
    int b = blockIdx.z, h = blockIdx.y, q0 = blockIdx.x * 128;
    int t = threadIdx.x;
    __shared__ float QsT[64][132];
    __shared__ float Ks[16][64];
    __shared__ float Vs[16][64];

    // Load Q tile (post-RoPE), transposed so per-thread column reads are conflict-free.
    size_t qbase = ((size_t)(b * SEQ + q0)) * 3072 + h * 64;
    #pragma unroll
    for (int i = 0; i < 16; i++) {
        int i4 = i * 128 + t;                // 2048 float4 = 128 rows x 16
        int row = i4 >> 4;
        int c = (i4 & 15) * 4;
        float4 v = *(const float4*)&g_qkv[qbase + (size_t)row * 3072 + c];
        QsT[c + 0][row] = v.x;
        QsT[c + 1][row] = v.y;
        QsT[c + 2][row] = v.z;
        QsT[c + 3][row] = v.w;
    }
    float acc[64];
    #pragma unroll
    for (int d = 0; d < 64; d++) acc[d] = 0.f;
    float m = -1e30f, l = 0.f;
    __syncthreads();

    for (int kk0 = 0; kk0 < SEQ; kk0 += 16) {
        size_t kbase = ((size_t)(b * SEQ + kk0)) * 3072 + h * 64;
        #pragma unroll
        for (int i = 0; i < 2; i++) {
            int i4 = i * 128 + t;            // 256 float4 = 16 rows x 16
            int row = i4 >> 4;
            int c = (i4 & 15) * 4;
            *(float4*)&Ks[row][c] = *(const float4*)&g_qkv[kbase + (size_t)row * 3072 + 1024 + c];
            *(float4*)&Vs[row][c] = *(const float4*)&g_qkv[kbase + (size_t)row * 3072 + 2048 + c];
        }
        __syncthreads();

        float s[16];
        #pragma unroll
        for (int j = 0; j < 16; j++) s[j] = 0.f;
        #pragma unroll
        for (int k4 = 0; k4 < 16; k4++) {
            float q0v = QsT[k4 * 4 + 0][t];
            float q1v = QsT[k4 * 4 + 1][t];
            float q2v = QsT[k4 * 4 + 2][t];
            float q3v = QsT[k4 * 4 + 3][t];
            #pragma unroll
            for (int j = 0; j < 16; j++) {
                float4 kv = *(const float4*)&Ks[j][k4 * 4];
                s[j] += q0v * kv.x + q1v * kv.y + q2v * kv.z + q3v * kv.w;
            }
        }
        float mt = m;
        #pragma unroll
        for (int j = 0; j < 16; j++) { s[j] *= 0.125f; mt = fmaxf(mt, s[j]); }
        float corr = __expf(m - mt);
        m = mt;
        l *= corr;
        #pragma unroll
        for (int d = 0; d < 64; d++) acc[d] *= corr;
        #pragma unroll
        for (int j = 0; j < 16; j++) {
            float p = __expf(s[j] - mt);
            l += p;
            #pragma unroll
            for (int d4 = 0; d4 < 16; d4++) {
                float4 vv = *(const float4*)&Vs[j][d4 * 4];
                acc[d4 * 4 + 0] += p * vv.x;
                acc[d4 * 4 + 1] += p * vv.y;
                acc[d4 * 4 + 2] += p * vv.z;
                acc[d4 * 4 + 3] += p * vv.w;
            }
        }
        __syncthreads();
    }
    float inv = 1.0f / l;
    size_t obase = ((size_t)(b * SEQ + q0 + t)) * DIM + h * 64;
    #pragma unroll
    for (int d4 = 0; d4 < 16; d4++) {
        float4 v;
        v.x = acc[d4 * 4 + 0] * inv;
        v.y = acc[d4 * 4 + 1] * inv;
        v.z = acc[d4 * 4 + 2] * inv;
        v.w = acc[d4 * 4 + 3] * inv;
        *(float4*)&g_o[obase + d4 * 4] = v;
    }
}

// ---------------- gating: softmax over 8 experts + top-2 (warp per token) ----------------
__global__ __launch_bounds__(128) void gate_kernel(const float* __restrict__ gate_w) {
    int t = blockIdx.x * 4 + (threadIdx.x >> 5);
    int lane = threadIdx.x & 31;
    const float* xr = g_h2 + (size_t)t * DIM;
    float p[8];
    #pragma unroll
    for (int e = 0; e < 8; e++) p[e] = 0.f;
    for (int it = 0; it < 32; it++) {
        int d = it * 32 + lane;
        float xv = xr[d];
        const float4* gw = (const float4*)(gate_w + d * 8);
        float4 g0 = gw[0], g1 = gw[1];
        p[0] += xv * g0.x; p[1] += xv * g0.y; p[2] += xv * g0.z; p[3] += xv * g0.w;
        p[4] += xv * g1.x; p[5] += xv * g1.y; p[6] += xv * g1.z; p[7] += xv * g1.w;
    }
    #pragma unroll
    for (int e = 0; e < 8; e++)
        #pragma unroll
        for (int o = 16; o; o >>= 1) p[e] += __shfl_xor_sync(0xffffffffu, p[e], o);
    if (lane == 0) {
        float mx = p[0];
        #pragma unroll
        for (int e = 1; e < 8; e++) mx = fmaxf(mx, p[e]);
        float ex[8], sum = 0.f;
        #pragma unroll
        for (int e = 0; e < 8; e++) { ex[e] = __expf(p[e] - mx); sum += ex[e]; }
        float inv = 1.f / sum;
        float pr[8];
        #pragma unroll
        for (int e = 0; e < 8; e++) { pr[e] = ex[e] * inv; g_probs[t * 8 + e] = pr[e]; }
        int i1 = 0;
        float v1 = pr[0];
        #pragma unroll
        for (int e = 1; e < 8; e++) if (pr[e] > v1) { v1 = pr[e]; i1 = e; }
        int i2 = -1;
        float v2 = -1.f;
        #pragma unroll
        for (int e = 0; e < 8; e++) if (e != i1 && pr[e] > v2) { v2 = pr[e]; i2 = e; }
        float dn = 1.f / (v1 + v2);
        g_eid[t] = i1;
        g_eid[TKN + t] = i2;
        g_wflat[t] = v1 * dn;
        g_wflat[TKN + t] = v2 * dn;
    }
}

// ---------------- per-expert sequential positions (reference cumsum order) ----------------
__global__ void pos_kernel() {
    int e = threadIdx.x >> 5;   // 8 warps, one per expert
    int lane = threadIdx.x & 31;
    int base = 0;
    for (int a0 = 0; a0 < NA; a0 += 32) {
        int ea = g_eid[a0 + lane];
        unsigned mask = __ballot_sync(0xffffffffu, ea == e);
        if (ea == e) g_pos[a0 + lane] = base + __popc(mask & ((1u << lane) - 1));
        base += __popc(mask);
    }
}

// ---------------- scatter kept tokens into capacity buffer ----------------
__global__ __launch_bounds__(256) void scatter_kernel() {
    int a = blockIdx.x;
    int p = g_pos[a];
    if (p >= CAP) return;
    int e = g_eid[a];
    int tok = a & (TKN - 1);
    const float4* src = (const float4*)(g_h2 + (size_t)tok * DIM);
    float4* dst = (float4*)(g_buf + ((size_t)e * CAP + p) * DIM);
    dst[threadIdx.x] = src[threadIdx.x];
}

// ---------------- aux loss ----------------
__global__ __launch_bounds__(256) void aux_kernel(float* __restrict__ out, int out_size) {
    __shared__ float red[256];
    int tid = threadIdx.x;
    float me[8], cnt[8];
    #pragma unroll
    for (int e = 0; e < 8; e++) { me[e] = 0.f; cnt[e] = 0.f; }
    for (int t = tid; t < TKN; t += 256) {
        #pragma unroll
        for (int e = 0; e < 8; e++) me[e] += g_probs[t * 8 + e];
    }
    for (int a = tid; a < NA; a += 256) cnt[g_eid[a]] += 1.f;
    float auxv = 0.f;
    for (int e = 0; e < 8; e++) {
        red[tid] = me[e];
        __syncthreads();
        for (int st = 128; st; st >>= 1) { if (tid < st) red[tid] += red[tid + st]; __syncthreads(); }
        float meS = red[0];
        __syncthreads();
        red[tid] = cnt[e];
        __syncthreads();
        for (int st = 128; st; st >>= 1) { if (tid < st) red[tid] += red[tid + st]; __syncthreads(); }
        float cS = red[0];
        __syncthreads();
        auxv += (meS / (float)TKN) * (cS / (float)NA);
    }
    if (tid == 0 && out_size > TKN * DIM) out[TKN * DIM] = 8.f * auxv;
}

// ---------------- combine: out = x2 + weighted expert outputs ----------------
__global__ __launch_bounds__(256) void final_kernel(float* __restrict__ out) {
    int t = blockIdx.x;
    int tid = threadIdx.x;
    int p1 = g_pos[t], p2 = g_pos[TKN + t];
    int e1 = g_eid[t], e2 = g_eid[TKN + t];
    float w1 = (p1 < CAP) ? g_wflat[t] : 0.f;
    float w2 = (p2 < CAP) ? g_wflat[TKN + t] : 0.f;
    p1 = min(p1, CAP - 1);
    p2 = min(p2, CAP - 1);
    const float4* a = (const float4*)(g_oute + ((size_t)e1 * CAP + p1) * DIM);
    const float4* b = (const float4*)(g_oute + ((size_t)e2 * CAP + p2) * DIM);
    const float4* xr = (const float4*)(g_x2 + (size_t)t * DIM);
    float4 av = a[tid], bv = b[tid], xv = xr[tid];
    float4 r;
    r.x = xv.x + w1 * av.x + w2 * bv.x;
    r.y = xv.y + w1 * av.y + w2 * bv.y;
    r.z = xv.z + w1 * av.z + w2 * bv.z;
    r.w = xv.w + w1 * av.w + w2 * bv.w;
    ((float4*)(out + (size_t)t * DIM))[tid] = r;
}

// ---------------- host ----------------
extern "C" void kernel_launch(void* const* d_in, const int* in_sizes, int n_in,
                              void* d_out, int out_size) {
    const float* x     = (const float*)d_in[0];
    const float* cosT  = (const float*)d_in[1];
    const float* sinT  = (const float*)d_in[2];
    const float* ln1g  = (const float*)d_in[3];
    const float* ln1b  = (const float*)d_in[4];
    const float* ln2g  = (const float*)d_in[5];
    const float* ln2b  = (const float*)d_in[6];
    const float* wqkv  = (const float*)d_in[7];
    const float* bqkv  = (const float*)d_in[8];
    const float* wo    = (const float*)d_in[9];
    const float* bo    = (const float*)d_in[10];
    const float* gatew = (const float*)d_in[11];
    const float* w1    = (const float*)d_in[12];
    const float* b1    = (const float*)d_in[13];
    const float* w2    = (const float*)d_in[14];
    const float* b2    = (const float*)d_in[15];
    float* out = (float*)d_out;

    void *p_h, *p_qkv, *p_o, *p_x2, *p_h2, *p_buf, *p_hh, *p_oute;
    cudaGetSymbolAddress(&p_h, g_h);
    cudaGetSymbolAddress(&p_qkv, g_qkv);
    cudaGetSymbolAddress(&p_o, g_o);
    cudaGetSymbolAddress(&p_x2, g_x2);
    cudaGetSymbolAddress(&p_h2, g_h2);
    cudaGetSymbolAddress(&p_buf, g_buf);
    cudaGetSymbolAddress(&p_hh, g_hh);
    cudaGetSymbolAddress(&p_oute, g_oute);

    zero_buf_kernel<<<(NE * CAP * DIM / 4 + 255) / 256, 256>>>();

    // ln1
    ln_kernel<<<TKN, 256>>>(x, ln1g, ln1b, (float*)p_h);
    // qkv = h @ wqkv + bqkv
    gemm_kernel<EPI_BIAS><<<dim3(3072 / 128, TKN / 128, 1), 256>>>(
        (const float*)p_h, wqkv, bqkv, nullptr, (float*)p_qkv, TKN, 3072, 1024, 0, 0, 0, 0);
    // rope on q,k
    rope_kernel<<<(2 * TKN * NH * 32) / 256, 256>>>(cosT, sinT);
    // attention
    flash_kernel<<<dim3(SEQ / 128, NH, 2), 128>>>();
    // x2 = o @ wo + bo + x
    gemm_kernel<EPI_BIAS_RES><<<dim3(1024 / 128, TKN / 128, 1), 256>>>(
        (const float*)p_o, wo, bo, x, (float*)p_x2, TKN, 1024, 1024, 0, 0, 0, 0);
    // ln2
    ln_kernel<<<TKN, 256>>>((const float*)p_x2, ln2g, ln2b, (float*)p_h2);
    // gating + routing
    gate_kernel<<<TKN / 4, 128>>>(gatew);
    pos_kernel<<<1, 256>>>();
    scatter_kernel<<<NA, 256>>>();
    aux_kernel<<<1, 256>>>(out, out_size);
    // expert FFN (batched over experts in grid.z)
    gemm_kernel<EPI_BIAS_GELU><<<dim3(HID / 128, CAP / 128, NE), 256>>>(
        (const float*)p_buf, w1, b1, nullptr, (float*)p_hh, CAP, HID, DIM,
        (size_t)CAP * DIM, (size_t)DIM * HID, (size_t)HID, (size_t)CAP * HID);
    gemm_kernel<EPI_BIAS><<<dim3(DIM / 128, CAP / 128, NE), 256>>>(
        (const float*)p_hh, w2, b2, nullptr, (float*)p_oute, CAP, DIM, HID,
        (size_t)CAP * HID, (size_t)HID * DIM, (size_t)DIM, (size_t)CAP * DIM);
    // combine + residual
    final_kernel<<<TKN, 256>>>(out);
}

// round 4
// speedup vs baseline: 1.8329x; 1.8300x over previous
#include <cuda_runtime.h>
#include <cuda_bf16.h>
#include <math.h>
#include <stdint.h>

#define TKN 4096
#define SEQ 2048
#define DIM 1024
#define NH 16
#define NE 8
#define HID 4096
#define CAP 1280
#define NA 8192
#define KC1 3072
#define KC2 12288

// ---------------- scratch ----------------
__device__ float g_qkv[TKN * 3 * DIM];
__device__ float g_x2[TKN * DIM];
__device__ float g_h2[TKN * DIM];
__device__ float g_probs[TKN * NE];
__device__ int   g_eid[NA];
__device__ float g_wflat[NA];
__device__ int   g_pos[NA];
__device__ float g_oute[NE * CAP * DIM];

__device__ __nv_bfloat16 g_acat[(size_t)TKN * KC1];
__device__ __nv_bfloat16 g_ocat[(size_t)TKN * KC1];
__device__ __nv_bfloat16 g_bufcat[(size_t)NE * CAP * KC1];
__device__ __nv_bfloat16 g_hhcat[(size_t)NE * CAP * KC2];
__device__ __nv_bfloat16 g_wqkvcat[(size_t)3072 * KC1];
__device__ __nv_bfloat16 g_wocat[(size_t)1024 * KC1];
__device__ __nv_bfloat16 g_w1cat[(size_t)NE * HID * KC1];
__device__ __nv_bfloat16 g_w2cat[(size_t)NE * DIM * KC2];

// ---------------- helpers ----------------
__device__ __forceinline__ uint32_t smem_u32(const void* p) {
    uint32_t a;
    asm("{ .reg .u64 t; cvta.to.shared.u64 t, %1; cvt.u32.u64 %0, t; }" : "=r"(a) : "l"(p));
    return a;
}
__device__ __forceinline__ void ldsm4(uint32_t* r, uint32_t a) {
    asm volatile("ldmatrix.sync.aligned.m8n8.x4.shared.b16 {%0,%1,%2,%3}, [%4];"
                 : "=r"(r[0]), "=r"(r[1]), "=r"(r[2]), "=r"(r[3]) : "r"(a));
}
__device__ __forceinline__ void ldsm2(uint32_t* r, uint32_t a) {
    asm volatile("ldmatrix.sync.aligned.m8n8.x2.shared.b16 {%0,%1}, [%2];"
                 : "=r"(r[0]), "=r"(r[1]) : "r"(a));
}
__device__ __forceinline__ void mma16816(float* c, const uint32_t* a, const uint32_t* b) {
    asm volatile(
        "mma.sync.aligned.m16n8k16.row.col.f32.bf16.bf16.f32 "
        "{%0,%1,%2,%3}, {%4,%5,%6,%7}, {%8,%9}, {%0,%1,%2,%3};"
        : "+f"(c[0]), "+f"(c[1]), "+f"(c[2]), "+f"(c[3])
        : "r"(a[0]), "r"(a[1]), "r"(a[2]), "r"(a[3]), "r"(b[0]), "r"(b[1]));
}
__device__ __forceinline__ void cpa16(uint32_t dst, const void* src) {
    asm volatile("cp.async.cg.shared.global [%0], [%1], 16;" :: "r"(dst), "l"(src));
}
#define CPA_COMMIT() asm volatile("cp.async.commit_group;")
#define CPA_WAIT2()  asm volatile("cp.async.wait_group 2;")

__device__ __forceinline__ float gelu_f(float x) {
    float x3 = x * x * x;
    float t = tanhf(0.7978845608028654f * (x + 0.044715f * x3));
    return 0.5f * x * (1.0f + t);
}
// write split pair into A-side cat layout [hi | lo | hi], slabs of `stride`
__device__ __forceinline__ void put_cat(__nv_bfloat16* p, int stride, float a, float b) {
    __nv_bfloat16 ah = __float2bfloat16(a), bh = __float2bfloat16(b);
    __nv_bfloat16 al = __float2bfloat16(a - __bfloat162float(ah));
    __nv_bfloat16 bl = __float2bfloat16(b - __bfloat162float(bh));
    __nv_bfloat162 hi; hi.x = ah; hi.y = bh;
    __nv_bfloat162 lo; lo.x = al; lo.y = bl;
    *(__nv_bfloat162*)(p) = hi;
    *(__nv_bfloat162*)(p + stride) = lo;
    *(__nv_bfloat162*)(p + 2 * stride) = hi;
}

// ---------------- zero expert capacity buffer ----------------
__global__ void zero_buf_kernel() {
    size_t i = (size_t)blockIdx.x * blockDim.x + threadIdx.x;
    size_t n = (size_t)NE * CAP * KC1 / 8;
    uint4* p = (uint4*)g_bufcat;
    if (i < n) p[i] = make_uint4(0u, 0u, 0u, 0u);
}

// ---------------- weight transpose + split: W[K][N] fp32 -> Wt[N][3K] = [hi|hi|lo] ----------------
__global__ __launch_bounds__(256) void wconv_kernel(const float* __restrict__ W,
                                                    __nv_bfloat16* __restrict__ Wt,
                                                    int K, int N, size_t wOff, size_t oOff) {
    int z = blockIdx.z;
    W += wOff * z; Wt += oOff * z;
    __shared__ float t[32][33];
    int n0 = blockIdx.x * 32, k0 = blockIdx.y * 32;
    int tx = threadIdx.x, ty = threadIdx.y;
    #pragma unroll
    for (int j = 0; j < 4; j++)
        t[ty + 8 * j][tx] = W[(size_t)(k0 + ty + 8 * j) * N + n0 + tx];
    __syncthreads();
    int Kc = 3 * K;
    #pragma unroll
    for (int j = 0; j < 4; j++) {
        int n = n0 + ty + 8 * j;
        int k = k0 + tx;
        float v = t[tx][ty + 8 * j];
        __nv_bfloat16 hi = __float2bfloat16(v);
        __nv_bfloat16 lo = __float2bfloat16(v - __bfloat162float(hi));
        __nv_bfloat16* p = Wt + (size_t)n * Kc;
        p[k] = hi;
        p[K + k] = hi;
        p[2 * K + k] = lo;
    }
}

// ---------------- layernorm ----------------
template <bool CAT>
__global__ __launch_bounds__(256) void ln_kernel(const float* __restrict__ x,
                                                 const float* __restrict__ g,
                                                 const float* __restrict__ b,
                                                 float* __restrict__ outf,
                                                 __nv_bfloat16* __restrict__ outc) {
    int row = blockIdx.x, tid = threadIdx.x;
    const float4* xr = (const float4*)(x + (size_t)row * DIM);
    float4 v = xr[tid];
    float s = v.x + v.y + v.z + v.w;
    float q = v.x * v.x + v.y * v.y + v.z * v.z + v.w * v.w;
    __shared__ float ss[8], sq[8];
    #pragma unroll
    for (int o = 16; o; o >>= 1) {
        s += __shfl_xor_sync(0xffffffffu, s, o);
        q += __shfl_xor_sync(0xffffffffu, q, o);
    }
    int w = tid >> 5;
    if ((tid & 31) == 0) { ss[w] = s; sq[w] = q; }
    __syncthreads();
    __shared__ float mu_s, rs_s;
    if (tid == 0) {
        float S = 0.f, Q = 0.f;
        #pragma unroll
        for (int i = 0; i < 8; i++) { S += ss[i]; Q += sq[i]; }
        float mu = S / DIM;
        mu_s = mu;
        rs_s = rsqrtf(Q / DIM - mu * mu + 1e-6f);
    }
    __syncthreads();
    float mu = mu_s, rs = rs_s;
    float4 gg = ((const float4*)g)[tid];
    float4 bb = ((const float4*)b)[tid];
    float4 o4;
    o4.x = (v.x - mu) * rs * gg.x + bb.x;
    o4.y = (v.y - mu) * rs * gg.y + bb.y;
    o4.z = (v.z - mu) * rs * gg.z + bb.z;
    o4.w = (v.w - mu) * rs * gg.w + bb.w;
    if (CAT) {
        __nv_bfloat16* p = outc + (size_t)row * KC1 + tid * 4;
        put_cat(p, DIM, o4.x, o4.y);
        put_cat(p + 2, DIM, o4.z, o4.w);
    } else {
        ((float4*)(outf + (size_t)row * DIM))[tid] = o4;
    }
}

// ---------------- HMMA GEMM: C[128x256 per CTA] = Acat(MxKc) @ Bcat(NxKc)^T ----------------
#define EPI_PLAIN 0
#define EPI_WO 1
#define EPI_W1 2
#define STAGE_BYTES 49152
#define GSMEM (3 * STAGE_BYTES)

template <int EPI>
__global__ __launch_bounds__(512, 1) void tgemm(
    const __nv_bfloat16* __restrict__ A, const __nv_bfloat16* __restrict__ Bt,
    const float* __restrict__ bias, const float* __restrict__ res,
    float* __restrict__ Cf, __nv_bfloat16* __restrict__ Cb,
    int Kc, int Nstr, int HIDN,
    size_t aOff, size_t bOff, size_t biasOff, size_t cOff) {
    extern __shared__ __align__(1024) char smem[];
    const uint32_t sb = smem_u32(smem);
    const int tid = threadIdx.x;
    const int z = blockIdx.z;
    A += aOff * z; Bt += bOff * z; bias += biasOff * z;
    if (EPI == EPI_W1) Cb += cOff * z; else Cf += cOff * z;
    const int m0 = blockIdx.y * 128;
    const int n0 = blockIdx.x * 256;
    const int nk = Kc >> 6;

    auto loadStage = [&](int kt, int ss) {
        uint32_t sbase = sb + ss * STAGE_BYTES;
        const __nv_bfloat16* Ag = A + (size_t)m0 * Kc + kt * 64;
        #pragma unroll
        for (int i = 0; i < 2; i++) {
            int id = tid + i * 512;
            int r = id >> 3, c = id & 7;
            cpa16(sbase + r * 128 + ((c ^ (r & 7)) << 4), Ag + (size_t)r * Kc + c * 8);
        }
        const __nv_bfloat16* Bg = Bt + (size_t)n0 * Kc + kt * 64;
        #pragma unroll
        for (int i = 0; i < 4; i++) {
            int id = tid + i * 512;
            int r = id >> 3, c = id & 7;
            cpa16(sbase + 16384 + r * 128 + ((c ^ (r & 7)) << 4), Bg + (size_t)r * Kc + c * 8);
        }
        CPA_COMMIT();
    };

    loadStage(0, 0);
    loadStage(1, 1);
    loadStage(2, 2);

    const int lane = tid & 31, wid = tid >> 5;
    const int wm = wid & 1, wn = wid >> 1;      // 2 x 8 warps
    const int arl = lane & 15, akc = lane >> 4; // A ldmatrix lane row / k-chunk
    const int brl = lane & 7, bkc = (lane >> 3) & 1;

    int arow[4], brow[4];
    #pragma unroll
    for (int mf = 0; mf < 4; mf++) arow[mf] = wm * 64 + mf * 16 + arl;
    #pragma unroll
    for (int nf = 0; nf < 4; nf++) brow[nf] = wn * 32 + nf * 8 + brl;

    float acc[4][4][4];
    #pragma unroll
    for (int mf = 0; mf < 4; mf++)
        #pragma unroll
        for (int nf = 0; nf < 4; nf++)
            #pragma unroll
            for (int i = 0; i < 4; i++) acc[mf][nf][i] = 0.f;

    for (int kt = 0; kt < nk; kt++) {
        CPA_WAIT2();
        __syncthreads();
        int ss = kt % 3;
        uint32_t Au = sb + ss * STAGE_BYTES;
        uint32_t Bu = Au + 16384;
        #pragma unroll
        for (int j = 0; j < 4; j++) {
            uint32_t af[4][4], bf[4][2];
            #pragma unroll
            for (int mf = 0; mf < 4; mf++) {
                int r = arow[mf];
                ldsm4(af[mf], Au + r * 128 + (((j * 2 + akc) ^ (r & 7)) << 4));
            }
            #pragma unroll
            for (int nf = 0; nf < 4; nf++) {
                int r = brow[nf];
                ldsm2(bf[nf], Bu + r * 128 + (((j * 2 + bkc) ^ (r & 7)) << 4));
            }
            #pragma unroll
            for (int mf = 0; mf < 4; mf++)
                #pragma unroll
                for (int nf = 0; nf < 4; nf++)
                    mma16816(acc[mf][nf], af[mf], bf[nf]);
        }
        __syncthreads();
        if (kt + 3 < nk) loadStage(kt + 3, ss);
        else CPA_COMMIT();
    }

    // epilogue
    const int quad = lane >> 2, tq = lane & 3;
    #pragma unroll
    for (int mf = 0; mf < 4; mf++) {
        #pragma unroll
        for (int nf = 0; nf < 4; nf++) {
            int m = m0 + wm * 64 + mf * 16 + quad;
            int n = n0 + wn * 32 + nf * 8 + tq * 2;
            const float* c = acc[mf][nf];
            float b0 = bias[n], b1 = bias[n + 1];
            if (EPI == EPI_W1) {
                float v0 = gelu_f(c[0] + b0), v1 = gelu_f(c[1] + b1);
                put_cat(Cb + (size_t)m * (3 * HIDN) + n, HIDN, v0, v1);
                v0 = gelu_f(c[2] + b0); v1 = gelu_f(c[3] + b1);
                put_cat(Cb + (size_t)(m + 8) * (3 * HIDN) + n, HIDN, v0, v1);
            } else {
                float2 v = make_float2(c[0] + b0, c[1] + b1);
                float2 w = make_float2(c[2] + b0, c[3] + b1);
                if (EPI == EPI_WO) {
                    float2 r1 = *(const float2*)&res[(size_t)m * Nstr + n];
                    float2 r2 = *(const float2*)&res[(size_t)(m + 8) * Nstr + n];
                    v.x += r1.x; v.y += r1.y;
                    w.x += r2.x; w.y += r2.y;
                }
                *(float2*)&Cf[(size_t)m * Nstr + n] = v;
                *(float2*)&Cf[(size_t)(m + 8) * Nstr + n] = w;
            }
        }
    }
}

// ---------------- RoPE in-place on q,k ----------------
__global__ void rope_kernel(const float* __restrict__ cosT, const float* __restrict__ sinT) {
    int idx = blockIdx.x * blockDim.x + threadIdx.x;
    if (idx >= 2 * TKN * NH * 32) return;
    int i = idx & 31;
    int h = (idx >> 5) & 15;
    int t = (idx >> 9) & 4095;
    int qk = idx >> 21;
    int s = t & (SEQ - 1);
    size_t base = (size_t)t * 3072 + (size_t)qk * 1024 + h * 64;
    float c0 = cosT[s * 64 + i], s0 = sinT[s * 64 + i];
    float c1 = cosT[s * 64 + i + 32], s1 = sinT[s * 64 + i + 32];
    float a = g_qkv[base + i];
    float b = g_qkv[base + i + 32];
    g_qkv[base + i] = a * c0 - b * s0;
    g_qkv[base + i + 32] = b * c1 + a * s1;
}

// ---------------- flash attention (fp32); writes split bf16 for wo GEMM ----------------
__global__ __launch_bounds__(128) void flash_kernel() {
    int b = blockIdx.z, h = blockIdx.y, q0 = blockIdx.x * 128;
    int t = threadIdx.x;
    __shared__ float QsT[64][132];
    __shared__ float Ks[16][64];
    __shared__ float Vs[16][64];
    size_t qbase = ((size_t)(b * SEQ + q0)) * 3072 + h * 64;
    #pragma unroll
    for (int i = 0; i < 16; i++) {
        int i4 = i * 128 + t;
        int row = i4 >> 4;
        int c = (i4 & 15) * 4;
        float4 v = *(const float4*)&g_qkv[qbase + (size_t)row * 3072 + c];
        QsT[c + 0][row] = v.x;
        QsT[c + 1][row] = v.y;
        QsT[c + 2][row] = v.z;
        QsT[c + 3][row] = v.w;
    }
    float acc[64];
    #pragma unroll
    for (int d = 0; d < 64; d++) acc[d] = 0.f;
    float m = -1e30f, l = 0.f;
    __syncthreads();
    for (int kk0 = 0; kk0 < SEQ; kk0 += 16) {
        size_t kbase = ((size_t)(b * SEQ + kk0)) * 3072 + h * 64;
        #pragma unroll
        for (int i = 0; i < 2; i++) {
            int i4 = i * 128 + t;
            int row = i4 >> 4;
            int c = (i4 & 15) * 4;
            *(float4*)&Ks[row][c] = *(const float4*)&g_qkv[kbase + (size_t)row * 3072 + 1024 + c];
            *(float4*)&Vs[row][c] = *(const float4*)&g_qkv[kbase + (size_t)row * 3072 + 2048 + c];
        }
        __syncthreads();
        float s[16];
        #pragma unroll
        for (int j = 0; j < 16; j++) s[j] = 0.f;
        #pragma unroll
        for (int k4 = 0; k4 < 16; k4++) {
            float q0v = QsT[k4 * 4 + 0][t];
            float q1v = QsT[k4 * 4 + 1][t];
            float q2v = QsT[k4 * 4 + 2][t];
            float q3v = QsT[k4 * 4 + 3][t];
            #pragma unroll
            for (int j = 0; j < 16; j++) {
                float4 kv = *(const float4*)&Ks[j][k4 * 4];
                s[j] += q0v * kv.x + q1v * kv.y + q2v * kv.z + q3v * kv.w;
            }
        }
        float mt = m;
        #pragma unroll
        for (int j = 0; j < 16; j++) { s[j] *= 0.125f; mt = fmaxf(mt, s[j]); }
        float corr = __expf(m - mt);
        m = mt;
        l *= corr;
        #pragma unroll
        for (int d = 0; d < 64; d++) acc[d] *= corr;
        #pragma unroll
        for (int j = 0; j < 16; j++) {
            float p = __expf(s[j] - mt);
            l += p;
            #pragma unroll
            for (int d4 = 0; d4 < 16; d4++) {
                float4 vv = *(const float4*)&Vs[j][d4 * 4];
                acc[d4 * 4 + 0] += p * vv.x;
                acc[d4 * 4 + 1] += p * vv.y;
                acc[d4 * 4 + 2] += p * vv.z;
                acc[d4 * 4 + 3] += p * vv.w;
            }
        }
        __syncthreads();
    }
    float inv = 1.0f / l;
    size_t obase = ((size_t)(b * SEQ + q0 + t)) * KC1 + h * 64;
    #pragma unroll
    for (int d4 = 0; d4 < 16; d4++) {
        __nv_bfloat16* p = g_ocat + obase + d4 * 4;
        put_cat(p, DIM, acc[d4 * 4 + 0] * inv, acc[d4 * 4 + 1] * inv);
        put_cat(p + 2, DIM, acc[d4 * 4 + 2] * inv, acc[d4 * 4 + 3] * inv);
    }
}

// ---------------- gating ----------------
__global__ __launch_bounds__(128) void gate_kernel(const float* __restrict__ gate_w) {
    int t = blockIdx.x * 4 + (threadIdx.x >> 5);
    int lane = threadIdx.x & 31;
    const float* xr = g_h2 + (size_t)t * DIM;
    float p[8];
    #pragma unroll
    for (int e = 0; e < 8; e++) p[e] = 0.f;
    for (int it = 0; it < 32; it++) {
        int d = it * 32 + lane;
        float xv = xr[d];
        const float4* gw = (const float4*)(gate_w + d * 8);
        float4 g0 = gw[0], g1 = gw[1];
        p[0] += xv * g0.x; p[1] += xv * g0.y; p[2] += xv * g0.z; p[3] += xv * g0.w;
        p[4] += xv * g1.x; p[5] += xv * g1.y; p[6] += xv * g1.z; p[7] += xv * g1.w;
    }
    #pragma unroll
    for (int e = 0; e < 8; e++)
        #pragma unroll
        for (int o = 16; o; o >>= 1) p[e] += __shfl_xor_sync(0xffffffffu, p[e], o);
    if (lane == 0) {
        float mx = p[0];
        #pragma unroll
        for (int e = 1; e < 8; e++) mx = fmaxf(mx, p[e]);
        float ex[8], sum = 0.f;
        #pragma unroll
        for (int e = 0; e < 8; e++) { ex[e] = __expf(p[e] - mx); sum += ex[e]; }
        float inv = 1.f / sum;
        float pr[8];
        #pragma unroll
        for (int e = 0; e < 8; e++) { pr[e] = ex[e] * inv; g_probs[t * 8 + e] = pr[e]; }
        int i1 = 0;
        float v1 = pr[0];
        #pragma unroll
        for (int e = 1; e < 8; e++) if (pr[e] > v1) { v1 = pr[e]; i1 = e; }
        int i2 = -1;
        float v2 = -1.f;
        #pragma unroll
        for (int e = 0; e < 8; e++) if (e != i1 && pr[e] > v2) { v2 = pr[e]; i2 = e; }
        float dn = 1.f / (v1 + v2);
        g_eid[t] = i1;
        g_eid[TKN + t] = i2;
        g_wflat[t] = v1 * dn;
        g_wflat[TKN + t] = v2 * dn;
    }
}

// ---------------- per-expert positions ----------------
__global__ void pos_kernel() {
    int e = threadIdx.x >> 5;
    int lane = threadIdx.x & 31;
    int base = 0;
    for (int a0 = 0; a0 < NA; a0 += 32) {
        int ea = g_eid[a0 + lane];
        unsigned mask = __ballot_sync(0xffffffffu, ea == e);
        if (ea == e) g_pos[a0 + lane] = base + __popc(mask & ((1u << lane) - 1));
        base += __popc(mask);
    }
}

// ---------------- scatter tokens (split bf16) into capacity buffer ----------------
__global__ __launch_bounds__(256) void scatter_kernel() {
    int a = blockIdx.x;
    int p = g_pos[a];
    if (p >= CAP) return;
    int e = g_eid[a];
    int tok = a & (TKN - 1);
    float4 v = ((const float4*)(g_h2 + (size_t)tok * DIM))[threadIdx.x];
    __nv_bfloat16* dst = g_bufcat + ((size_t)e * CAP + p) * KC1 + threadIdx.x * 4;
    put_cat(dst, DIM, v.x, v.y);
    put_cat(dst + 2, DIM, v.z, v.w);
}

// ---------------- aux loss ----------------
__global__ __launch_bounds__(256) void aux_kernel(float* __restrict__ out, int out_size) {
    __shared__ float red[256];
    int tid = threadIdx.x;
    float me[8], cnt[8];
    #pragma unroll
    for (int e = 0; e < 8; e++) { me[e] = 0.f; cnt[e] = 0.f; }
    for (int t = tid; t < TKN; t += 256) {
        #pragma unroll
        for (int e = 0; e < 8; e++) me[e] += g_probs[t * 8 + e];
    }
    for (int a = tid; a < NA; a += 256) cnt[g_eid[a]] += 1.f;
    float auxv = 0.f;
    for (int e = 0; e < 8; e++) {
        red[tid] = me[e];
        __syncthreads();
        for (int st = 128; st; st >>= 1) { if (tid < st) red[tid] += red[tid + st]; __syncthreads(); }
        float meS = red[0];
        __syncthreads();
        red[tid] = cnt[e];
        __syncthreads();
        for (int st = 128; st; st >>= 1) { if (tid < st) red[tid] += red[tid + st]; __syncthreads(); }
        float cS = red[0];
        __syncthreads();
        auxv += (meS / (float)TKN) * (cS / (float)NA);
    }
    if (tid == 0 && out_size > TKN * DIM) out[TKN * DIM] = 8.f * auxv;
}

// ---------------- combine ----------------
__global__ __launch_bounds__(256) void final_kernel(float* __restrict__ out) {
    int t = blockIdx.x;
    int tid = threadIdx.x;
    int p1 = g_pos[t], p2 = g_pos[TKN + t];
    int e1 = g_eid[t], e2 = g_eid[TKN + t];
    float w1 = (p1 < CAP) ? g_wflat[t] : 0.f;
    float w2 = (p2 < CAP) ? g_wflat[TKN + t] : 0.f;
    p1 = min(p1, CAP - 1);
    p2 = min(p2, CAP - 1);
    const float4* a = (const float4*)(g_oute + ((size_t)e1 * CAP + p1) * DIM);
    const float4* b = (const float4*)(g_oute + ((size_t)e2 * CAP + p2) * DIM);
    const float4* xr = (const float4*)(g_x2 + (size_t)t * DIM);
    float4 av = a[tid], bv = b[tid], xv = xr[tid];
    float4 r;
    r.x = xv.x + w1 * av.x + w2 * bv.x;
    r.y = xv.y + w1 * av.y + w2 * bv.y;
    r.z = xv.z + w1 * av.z + w2 * bv.z;
    r.w = xv.w + w1 * av.w + w2 * bv.w;
    ((float4*)(out + (size_t)t * DIM))[tid] = r;
}

// ---------------- host ----------------
extern "C" void kernel_launch(void* const* d_in, const int* in_sizes, int n_in,
                              void* d_out, int out_size) {
    const float* x     = (const float*)d_in[0];
    const float* cosT  = (const float*)d_in[1];
    const float* sinT  = (const float*)d_in[2];
    const float* ln1g  = (const float*)d_in[3];
    const float* ln1b  = (const float*)d_in[4];
    const float* ln2g  = (const float*)d_in[5];
    const float* ln2b  = (const float*)d_in[6];
    const float* wqkv  = (const float*)d_in[7];
    const float* bqkv  = (const float*)d_in[8];
    const float* wo    = (const float*)d_in[9];
    const float* bo    = (const float*)d_in[10];
    const float* gatew = (const float*)d_in[11];
    const float* w1    = (const float*)d_in[12];
    const float* b1    = (const float*)d_in[13];
    const float* w2    = (const float*)d_in[14];
    const float* b2    = (const float*)d_in[15];
    float* out = (float*)d_out;

    void *p_qkv, *p_x2, *p_h2, *p_oute;
    void *p_acat, *p_ocat, *p_bufcat, *p_hhcat, *p_wqkvc, *p_woc, *p_w1c, *p_w2c;
    cudaGetSymbolAddress(&p_qkv, g_qkv);
    cudaGetSymbolAddress(&p_x2, g_x2);
    cudaGetSymbolAddress(&p_h2, g_h2);
    cudaGetSymbolAddress(&p_oute, g_oute);
    cudaGetSymbolAddress(&p_acat, g_acat);
    cudaGetSymbolAddress(&p_ocat, g_ocat);
    cudaGetSymbolAddress(&p_bufcat, g_bufcat);
    cudaGetSymbolAddress(&p_hhcat, g_hhcat);
    cudaGetSymbolAddress(&p_wqkvc, g_wqkvcat);
    cudaGetSymbolAddress(&p_woc, g_wocat);
    cudaGetSymbolAddress(&p_w1c, g_w1cat);
    cudaGetSymbolAddress(&p_w2c, g_w2cat);

    static int attr_done = 0;
    if (!attr_done) {
        cudaFuncSetAttribute(tgemm<EPI_PLAIN>, cudaFuncAttributeMaxDynamicSharedMemorySize, GSMEM);
        cudaFuncSetAttribute(tgemm<EPI_WO>, cudaFuncAttributeMaxDynamicSharedMemorySize, GSMEM);
        cudaFuncSetAttribute(tgemm<EPI_W1>, cudaFuncAttributeMaxDynamicSharedMemorySize, GSMEM);
        attr_done = 1;
    }

    dim3 wb(32, 8);
    wconv_kernel<<<dim3(96, 32, 1), wb>>>(wqkv, (__nv_bfloat16*)p_wqkvc, 1024, 3072, 0, 0);
    wconv_kernel<<<dim3(32, 32, 1), wb>>>(wo, (__nv_bfloat16*)p_woc, 1024, 1024, 0, 0);
    wconv_kernel<<<dim3(128, 32, 8), wb>>>(w1, (__nv_bfloat16*)p_w1c, 1024, 4096,
                                           (size_t)DIM * HID, (size_t)HID * KC1);
    wconv_kernel<<<dim3(32, 128, 8), wb>>>(w2, (__nv_bfloat16*)p_w2c, 4096, 1024,
                                           (size_t)HID * DIM, (size_t)DIM * KC2);
    zero_buf_kernel<<<(int)(((size_t)NE * CAP * KC1 / 8 + 255) / 256), 256>>>();

    // ln1 -> split bf16
    ln_kernel<true><<<TKN, 256>>>(x, ln1g, ln1b, nullptr, (__nv_bfloat16*)p_acat);
    // qkv = h @ wqkv + bqkv
    tgemm<EPI_PLAIN><<<dim3(12, 32, 1), 512, GSMEM>>>(
        (const __nv_bfloat16*)p_acat, (const __nv_bfloat16*)p_wqkvc, bqkv, nullptr,
        (float*)p_qkv, nullptr, KC1, 3072, 0, 0, 0, 0, 0);
    rope_kernel<<<(2 * TKN * NH * 32) / 256, 256>>>(cosT, sinT);
    flash_kernel<<<dim3(SEQ / 128, NH, 2), 128>>>();
    // x2 = o@wo + bo + x
    tgemm<EPI_WO><<<dim3(4, 32, 1), 512, GSMEM>>>(
        (const __nv_bfloat16*)p_ocat, (const __nv_bfloat16*)p_woc, bo, x,
        (float*)p_x2, nullptr, KC1, 1024, 0, 0, 0, 0, 0);
    // ln2 -> fp32
    ln_kernel<false><<<TKN, 256>>>((const float*)p_x2, ln2g, ln2b, (float*)p_h2, nullptr);
    gate_kernel<<<TKN / 4, 128>>>(gatew);
    pos_kernel<<<1, 256>>>();
    scatter_kernel<<<NA, 256>>>();
    aux_kernel<<<1, 256>>>(out, out_size);
    // hh = gelu(buf@w1 + b1) -> split bf16
    tgemm<EPI_W1><<<dim3(16, 10, 8), 512, GSMEM>>>(
        (const __nv_bfloat16*)p_bufcat, (const __nv_bfloat16*)p_w1c, b1, nullptr,
        nullptr, (__nv_bfloat16*)p_hhcat, KC1, 0, HID,
        (size_t)CAP * KC1, (size_t)HID * KC1, (size_t)HID, (size_t)CAP * KC2);
    // oute = hh@w2 + b2
    tgemm<EPI_PLAIN><<<dim3(4, 10, 8), 512, GSMEM>>>(
        (const __nv_bfloat16*)p_hhcat, (const __nv_bfloat16*)p_w2c, b2, nullptr,
        (float*)p_oute, nullptr, KC2, 1024, 0,
        (size_t)CAP * KC2, (size_t)DIM * KC2, (size_t)DIM, (size_t)CAP * DIM);
    final_kernel<<<TKN, 256>>>(out);
}

// round 6
// speedup vs baseline: 2.3904x; 1.3041x over previous
#include <cuda_runtime.h>
#include <cuda_bf16.h>
#include <math.h>
#include <stdint.h>

#define TKN 4096
#define SEQ 2048
#define DIM 1024
#define NH 16
#define NE 8
#define HID 4096
#define CAP 1280
#define NA 8192
#define KC1 3072
#define KC2 12288

// ---------------- scratch ----------------
__device__ float g_qkv[TKN * 3 * DIM];
__device__ float g_x2[TKN * DIM];
__device__ float g_h2[TKN * DIM];
__device__ float g_probs[TKN * NE];
__device__ int   g_eid[NA];
__device__ float g_wflat[NA];
__device__ int   g_pos[NA];
__device__ float g_oute[NE * CAP * DIM];

__device__ __nv_bfloat16 g_acat[(size_t)TKN * KC1];
__device__ __nv_bfloat16 g_ocat[(size_t)TKN * KC1];
__device__ __nv_bfloat16 g_bufcat[(size_t)NE * CAP * KC1];
__device__ __nv_bfloat16 g_hhcat[(size_t)NE * CAP * KC2];
__device__ __nv_bfloat16 g_wqkvcat[(size_t)3072 * KC1];
__device__ __nv_bfloat16 g_wocat[(size_t)1024 * KC1];
__device__ __nv_bfloat16 g_w1cat[(size_t)NE * HID * KC1];
__device__ __nv_bfloat16 g_w2cat[(size_t)NE * DIM * KC2];

// ---------------- helpers ----------------
__device__ __forceinline__ uint32_t smem_u32(const void* p) {
    uint32_t a;
    asm("{ .reg .u64 t; cvta.to.shared.u64 t, %1; cvt.u32.u64 %0, t; }" : "=r"(a) : "l"(p));
    return a;
}
__device__ __forceinline__ void ldsm4(uint32_t* r, uint32_t a) {
    asm volatile("ldmatrix.sync.aligned.m8n8.x4.shared.b16 {%0,%1,%2,%3}, [%4];"
                 : "=r"(r[0]), "=r"(r[1]), "=r"(r[2]), "=r"(r[3]) : "r"(a));
}
__device__ __forceinline__ void ldsm4t(uint32_t* r, uint32_t a) {
    asm volatile("ldmatrix.sync.aligned.m8n8.x4.trans.shared.b16 {%0,%1,%2,%3}, [%4];"
                 : "=r"(r[0]), "=r"(r[1]), "=r"(r[2]), "=r"(r[3]) : "r"(a));
}
__device__ __forceinline__ void mma2(float* c, const uint32_t* a, uint32_t b0, uint32_t b1) {
    asm volatile(
        "mma.sync.aligned.m16n8k16.row.col.f32.bf16.bf16.f32 "
        "{%0,%1,%2,%3}, {%4,%5,%6,%7}, {%8,%9}, {%0,%1,%2,%3};"
        : "+f"(c[0]), "+f"(c[1]), "+f"(c[2]), "+f"(c[3])
        : "r"(a[0]), "r"(a[1]), "r"(a[2]), "r"(a[3]), "r"(b0), "r"(b1));
}
__device__ __forceinline__ void cpa16(uint32_t dst, const void* src) {
    asm volatile("cp.async.cg.shared.global [%0], [%1], 16;" :: "r"(dst), "l"(src));
}
#define CPA_COMMIT() asm volatile("cp.async.commit_group;")
#define CPA_WAIT2()  asm volatile("cp.async.wait_group 2;")

__device__ __forceinline__ float gelu_f(float x) {
    float x3 = x * x * x;
    float t = tanhf(0.7978845608028654f * (x + 0.044715f * x3));
    return 0.5f * x * (1.0f + t);
}
// write split pair into A-side cat layout [hi | lo | hi], slabs of `stride`
__device__ __forceinline__ void put_cat(__nv_bfloat16* p, int stride, float a, float b) {
    __nv_bfloat16 ah = __float2bfloat16(a), bh = __float2bfloat16(b);
    __nv_bfloat16 al = __float2bfloat16(a - __bfloat162float(ah));
    __nv_bfloat16 bl = __float2bfloat16(b - __bfloat162float(bh));
    __nv_bfloat162 hi; hi.x = ah; hi.y = bh;
    __nv_bfloat162 lo; lo.x = al; lo.y = bl;
    *(__nv_bfloat162*)(p) = hi;
    *(__nv_bfloat162*)(p + stride) = lo;
    *(__nv_bfloat162*)(p + 2 * stride) = hi;
}
// split 8 floats into hi/lo 16B chunks
__device__ __forceinline__ void split_store(char* dst_hi, char* dst_lo, float4 v0, float4 v1) {
    float f[8] = {v0.x, v0.y, v0.z, v0.w, v1.x, v1.y, v1.z, v1.w};
    uint32_t hw[4], lw[4];
    #pragma unroll
    for (int k = 0; k < 4; k++) {
        __nv_bfloat16 b0 = __float2bfloat16(f[2 * k]), b1 = __float2bfloat16(f[2 * k + 1]);
        __nv_bfloat16 e0 = __float2bfloat16(f[2 * k] - __bfloat162float(b0));
        __nv_bfloat16 e1 = __float2bfloat16(f[2 * k + 1] - __bfloat162float(b1));
        hw[k] = ((uint32_t)__bfloat16_as_ushort(b1) << 16) | __bfloat16_as_ushort(b0);
        lw[k] = ((uint32_t)__bfloat16_as_ushort(e1) << 16) | __bfloat16_as_ushort(e0);
    }
    *(uint4*)dst_hi = make_uint4(hw[0], hw[1], hw[2], hw[3]);
    *(uint4*)dst_lo = make_uint4(lw[0], lw[1], lw[2], lw[3]);
}

// ---------------- zero expert capacity buffer ----------------
__global__ void zero_buf_kernel() {
    size_t i = (size_t)blockIdx.x * blockDim.x + threadIdx.x;
    size_t n = (size_t)NE * CAP * KC1 / 8;
    uint4* p = (uint4*)g_bufcat;
    if (i < n) p[i] = make_uint4(0u, 0u, 0u, 0u);
}

// ---------------- weight transpose + split: W[K][N] fp32 -> Wt[N][3K] = [hi|hi|lo] ----------------
__global__ __launch_bounds__(256) void wconv_kernel(const float* __restrict__ W,
                                                    __nv_bfloat16* __restrict__ Wt,
                                                    int K, int N, size_t wOff, size_t oOff) {
    int z = blockIdx.z;
    W += wOff * z; Wt += oOff * z;
    __shared__ float t[32][33];
    int n0 = blockIdx.x * 32, k0 = blockIdx.y * 32;
    int tx = threadIdx.x, ty = threadIdx.y;
    #pragma unroll
    for (int j = 0; j < 4; j++)
        t[ty + 8 * j][tx] = W[(size_t)(k0 + ty + 8 * j) * N + n0 + tx];
    __syncthreads();
    int Kc = 3 * K;
    #pragma unroll
    for (int j = 0; j < 4; j++) {
        int n = n0 + ty + 8 * j;
        int k = k0 + tx;
        float v = t[tx][ty + 8 * j];
        __nv_bfloat16 hi = __float2bfloat16(v);
        __nv_bfloat16 lo = __float2bfloat16(v - __bfloat162float(hi));
        __nv_bfloat16* p = Wt + (size_t)n * Kc;
        p[k] = hi;
        p[K + k] = hi;
        p[2 * K + k] = lo;
    }
}

// ---------------- layernorm ----------------
template <bool CAT>
__global__ __launch_bounds__(256) void ln_kernel(const float* __restrict__ x,
                                                 const float* __restrict__ g,
                                                 const float* __restrict__ b,
                                                 float* __restrict__ outf,
                                                 __nv_bfloat16* __restrict__ outc) {
    int row = blockIdx.x, tid = threadIdx.x;
    const float4* xr = (const float4*)(x + (size_t)row * DIM);
    float4 v = xr[tid];
    float s = v.x + v.y + v.z + v.w;
    float q = v.x * v.x + v.y * v.y + v.z * v.z + v.w * v.w;
    __shared__ float ss[8], sq[8];
    #pragma unroll
    for (int o = 16; o; o >>= 1) {
        s += __shfl_xor_sync(0xffffffffu, s, o);
        q += __shfl_xor_sync(0xffffffffu, q, o);
    }
    int w = tid >> 5;
    if ((tid & 31) == 0) { ss[w] = s; sq[w] = q; }
    __syncthreads();
    __shared__ float mu_s, rs_s;
    if (tid == 0) {
        float S = 0.f, Q = 0.f;
        #pragma unroll
        for (int i = 0; i < 8; i++) { S += ss[i]; Q += sq[i]; }
        float mu = S / DIM;
        mu_s = mu;
        rs_s = rsqrtf(Q / DIM - mu * mu + 1e-6f);
    }
    __syncthreads();
    float mu = mu_s, rs = rs_s;
    float4 gg = ((const float4*)g)[tid];
    float4 bb = ((const float4*)b)[tid];
    float4 o4;
    o4.x = (v.x - mu) * rs * gg.x + bb.x;
    o4.y = (v.y - mu) * rs * gg.y + bb.y;
    o4.z = (v.z - mu) * rs * gg.z + bb.z;
    o4.w = (v.w - mu) * rs * gg.w + bb.w;
    if (CAT) {
        __nv_bfloat16* p = outc + (size_t)row * KC1 + tid * 4;
        put_cat(p, DIM, o4.x, o4.y);
        put_cat(p + 2, DIM, o4.z, o4.w);
    } else {
        ((float4*)(outf + (size_t)row * DIM))[tid] = o4;
    }
}

// ---------------- HMMA GEMM: C[128x256 per CTA] = Acat(MxKc) @ Bcat(NxKc)^T ----------------
#define EPI_PLAIN 0
#define EPI_WO 1
#define EPI_W1 2
#define STAGE_BYTES 49152
#define GSMEM (3 * STAGE_BYTES)

template <int EPI>
__global__ __launch_bounds__(512, 1) void tgemm(
    const __nv_bfloat16* __restrict__ A, const __nv_bfloat16* __restrict__ Bt,
    const float* __restrict__ bias, const float* __restrict__ res,
    float* __restrict__ Cf, __nv_bfloat16* __restrict__ Cb,
    int Kc, int Nstr, int HIDN,
    size_t aOff, size_t bOff, size_t biasOff, size_t cOff) {
    extern __shared__ __align__(1024) char smem[];
    const uint32_t sb = smem_u32(smem);
    const int tid = threadIdx.x;
    const int z = blockIdx.z;
    A += aOff * z; Bt += bOff * z; bias += biasOff * z;
    if (EPI == EPI_W1) Cb += cOff * z; else Cf += cOff * z;
    const int m0 = blockIdx.y * 128;
    const int n0 = blockIdx.x * 256;
    const int nk = Kc >> 6;

    auto loadStage = [&](int kt, int ss) {
        uint32_t sbase = sb + ss * STAGE_BYTES;
        const __nv_bfloat16* Ag = A + (size_t)m0 * Kc + kt * 64;
        #pragma unroll
        for (int i = 0; i < 2; i++) {
            int id = tid + i * 512;
            int r = id >> 3, c = id & 7;
            cpa16(sbase + r * 128 + ((c ^ (r & 7)) << 4), Ag + (size_t)r * Kc + c * 8);
        }
        const __nv_bfloat16* Bg = Bt + (size_t)n0 * Kc + kt * 64;
        #pragma unroll
        for (int i = 0; i < 4; i++) {
            int id = tid + i * 512;
            int r = id >> 3, c = id & 7;
            cpa16(sbase + 16384 + r * 128 + ((c ^ (r & 7)) << 4), Bg + (size_t)r * Kc + c * 8);
        }
        CPA_COMMIT();
    };

    loadStage(0, 0);
    loadStage(1, 1);
    loadStage(2, 2);

    const int lane = tid & 31, wid = tid >> 5;
    const int wm = wid & 1, wn = wid >> 1;
    const int arl = lane & 15, akc = lane >> 4;

    int arow[4];
    #pragma unroll
    for (int mf = 0; mf < 4; mf++) arow[mf] = wm * 64 + mf * 16 + arl;

    float acc[4][4][4];
    #pragma unroll
    for (int mf = 0; mf < 4; mf++)
        #pragma unroll
        for (int nf = 0; nf < 4; nf++)
            #pragma unroll
            for (int i = 0; i < 4; i++) acc[mf][nf][i] = 0.f;

    for (int kt = 0; kt < nk; kt++) {
        CPA_WAIT2();
        __syncthreads();
        int ss = kt % 3;
        uint32_t Au = sb + ss * STAGE_BYTES;
        uint32_t Bu = Au + 16384;
        #pragma unroll
        for (int j = 0; j < 4; j++) {
            uint32_t af[4][4];
            #pragma unroll
            for (int mf = 0; mf < 4; mf++) {
                int r = arow[mf];
                ldsm4(af[mf], Au + r * 128 + (((j * 2 + akc) ^ (r & 7)) << 4));
            }
            uint32_t bf[2][4];
            #pragma unroll
            for (int pr = 0; pr < 2; pr++) {
                int r = wn * 32 + pr * 16 + arl;
                ldsm4(bf[pr], Bu + r * 128 + (((j * 2 + akc) ^ (r & 7)) << 4));
            }
            #pragma unroll
            for (int mf = 0; mf < 4; mf++) {
                mma2(acc[mf][0], af[mf], bf[0][0], bf[0][2]);
                mma2(acc[mf][1], af[mf], bf[0][1], bf[0][3]);
                mma2(acc[mf][2], af[mf], bf[1][0], bf[1][2]);
                mma2(acc[mf][3], af[mf], bf[1][1], bf[1][3]);
            }
        }
        __syncthreads();
        if (kt + 3 < nk) loadStage(kt + 3, ss);
        else CPA_COMMIT();
    }

    const int quad = lane >> 2, tq = lane & 3;
    #pragma unroll
    for (int mf = 0; mf < 4; mf++) {
        #pragma unroll
        for (int nf = 0; nf < 4; nf++) {
            int m = m0 + wm * 64 + mf * 16 + quad;
            int n = n0 + wn * 32 + nf * 8 + tq * 2;
            const float* c = acc[mf][nf];
            float b0 = bias[n], b1 = bias[n + 1];
            if (EPI == EPI_W1) {
                float v0 = gelu_f(c[0] + b0), v1 = gelu_f(c[1] + b1);
                put_cat(Cb + (size_t)m * (3 * HIDN) + n, HIDN, v0, v1);
                v0 = gelu_f(c[2] + b0); v1 = gelu_f(c[3] + b1);
                put_cat(Cb + (size_t)(m + 8) * (3 * HIDN) + n, HIDN, v0, v1);
            } else {
                float2 v = make_float2(c[0] + b0, c[1] + b1);
                float2 w = make_float2(c[2] + b0, c[3] + b1);
                if (EPI == EPI_WO) {
                    float2 r1 = *(const float2*)&res[(size_t)m * Nstr + n];
                    float2 r2 = *(const float2*)&res[(size_t)(m + 8) * Nstr + n];
                    v.x += r1.x; v.y += r1.y;
                    w.x += r2.x; w.y += r2.y;
                }
                *(float2*)&Cf[(size_t)m * Nstr + n] = v;
                *(float2*)&Cf[(size_t)(m + 8) * Nstr + n] = w;
            }
        }
    }
}

// ---------------- RoPE in-place on q,k ----------------
__global__ void rope_kernel(const float* __restrict__ cosT, const float* __restrict__ sinT) {
    int idx = blockIdx.x * blockDim.x + threadIdx.x;
    if (idx >= 2 * TKN * NH * 32) return;
    int i = idx & 31;
    int h = (idx >> 5) & 15;
    int t = (idx >> 9) & 4095;
    int qk = idx >> 21;
    int s = t & (SEQ - 1);
    size_t base = (size_t)t * 3072 + (size_t)qk * 1024 + h * 64;
    float c0 = cosT[s * 64 + i], s0 = sinT[s * 64 + i];
    float c1 = cosT[s * 64 + i + 32], s1 = sinT[s * 64 + i + 32];
    float a = g_qkv[base + i];
    float b = g_qkv[base + i + 32];
    g_qkv[base + i] = a * c0 - b * s0;
    g_qkv[base + i + 32] = b * c1 + a * s1;
}

// ---------------- HMMA flash attention, bf16-split, online softmax ----------------
// grid (16, NH, 2), 256 threads (8 warps; warp w owns query rows w*16..+15).
// smem: Q[128][128] (hi|lo) @0, K[64][128] (hi|lo) @32768, V[64][128] (hi|lo) @49152
#define FSMEM 65536
__global__ __launch_bounds__(256, 2) void flash2_kernel() {
    extern __shared__ __align__(1024) char fsm[];
    const uint32_t Qu = smem_u32(fsm);
    const uint32_t Ku = Qu + 32768;
    const uint32_t Vu = Qu + 49152;
    const int b = blockIdx.z, h = blockIdx.y, q0 = blockIdx.x * 128;
    const int tid = threadIdx.x, lane = tid & 31, w = tid >> 5;
    const int arl = lane & 15, akc = lane >> 4;
    const int tq = lane & 3, quad = lane >> 2;

    // Q load + split (hi: chunks 0-7, lo: 8-15)
    #pragma unroll
    for (int i = 0; i < 4; i++) {
        int id = tid + i * 256;
        int r = id >> 3, ch = id & 7;
        const float* src = g_qkv + ((size_t)(b * SEQ + q0 + r)) * 3072 + h * 64 + ch * 8;
        float4 v0 = *(const float4*)src;
        float4 v1 = *(const float4*)(src + 4);
        split_store(fsm + r * 256 + ((ch ^ (r & 7)) << 4),
                    fsm + r * 256 + (((8 + ch) ^ (r & 7)) << 4), v0, v1);
    }

    float accO[8][4];
    #pragma unroll
    for (int nf = 0; nf < 8; nf++)
        #pragma unroll
        for (int i = 0; i < 4; i++) accO[nf][i] = 0.f;
    float m0 = -1e30f, m1 = -1e30f, l0 = 0.f, l1 = 0.f;
    const int qr = w * 16 + arl;

    for (int kt = 0; kt < SEQ / 64; kt++) {
        __syncthreads();
        #pragma unroll
        for (int i = 0; i < 2; i++) {
            int id = tid + i * 256;
            int r = id >> 3, ch = id & 7;
            const float* src = g_qkv + ((size_t)(b * SEQ + kt * 64 + r)) * 3072 + 1024 + h * 64 + ch * 8;
            float4 v0 = *(const float4*)src;
            float4 v1 = *(const float4*)(src + 4);
            split_store(fsm + 32768 + r * 256 + ((ch ^ (r & 7)) << 4),
                        fsm + 32768 + r * 256 + (((8 + ch) ^ (r & 7)) << 4), v0, v1);
            const float* sv = src + 1024;
            float4 u0 = *(const float4*)sv;
            float4 u1 = *(const float4*)(sv + 4);
            split_store(fsm + 49152 + r * 256 + ((ch ^ (r & 7)) << 4),
                        fsm + 49152 + r * 256 + (((8 + ch) ^ (r & 7)) << 4), u0, u1);
        }
        __syncthreads();

        // scores: 128x64 per CTA (16x64 per warp)
        float accS[8][4];
        #pragma unroll
        for (int nf = 0; nf < 8; nf++)
            #pragma unroll
            for (int i = 0; i < 4; i++) accS[nf][i] = 0.f;
        #pragma unroll
        for (int j = 0; j < 4; j++) {
            uint32_t ah[4], al[4];
            ldsm4(ah, Qu + qr * 256 + (((j * 2 + akc) ^ (qr & 7)) << 4));
            ldsm4(al, Qu + qr * 256 + (((8 + j * 2 + akc) ^ (qr & 7)) << 4));
            #pragma unroll
            for (int pr = 0; pr < 4; pr++) {
                int kr = pr * 16 + arl;
                uint32_t bh[4], bl[4];
                ldsm4(bh, Ku + kr * 256 + (((j * 2 + akc) ^ (kr & 7)) << 4));
                ldsm4(bl, Ku + kr * 256 + (((8 + j * 2 + akc) ^ (kr & 7)) << 4));
                mma2(accS[2 * pr], ah, bh[0], bh[2]);
                mma2(accS[2 * pr], al, bh[0], bh[2]);
                mma2(accS[2 * pr], ah, bl[0], bl[2]);
                mma2(accS[2 * pr + 1], ah, bh[1], bh[3]);
                mma2(accS[2 * pr + 1], al, bh[1], bh[3]);
                mma2(accS[2 * pr + 1], ah, bl[1], bl[3]);
            }
        }
        // online softmax
        float mt0 = m0, mt1 = m1;
        #pragma unroll
        for (int nf = 0; nf < 8; nf++) {
            #pragma unroll
            for (int i = 0; i < 4; i++) accS[nf][i] *= 0.125f;
            mt0 = fmaxf(mt0, fmaxf(accS[nf][0], accS[nf][1]));
            mt1 = fmaxf(mt1, fmaxf(accS[nf][2], accS[nf][3]));
        }
        #pragma unroll
        for (int o = 1; o <= 2; o <<= 1) {
            mt0 = fmaxf(mt0, __shfl_xor_sync(0xffffffffu, mt0, o));
            mt1 = fmaxf(mt1, __shfl_xor_sync(0xffffffffu, mt1, o));
        }
        float c0 = __expf(m0 - mt0), c1 = __expf(m1 - mt1);
        m0 = mt0; m1 = mt1;
        l0 *= c0; l1 *= c1;
        #pragma unroll
        for (int nf = 0; nf < 8; nf++) {
            accO[nf][0] *= c0; accO[nf][1] *= c0;
            accO[nf][2] *= c1; accO[nf][3] *= c1;
        }
        uint32_t ph[8][2], pl[8][2];
        #pragma unroll
        for (int nf = 0; nf < 8; nf++) {
            float p0 = __expf(accS[nf][0] - mt0);
            float p1 = __expf(accS[nf][1] - mt0);
            float p2 = __expf(accS[nf][2] - mt1);
            float p3 = __expf(accS[nf][3] - mt1);
            l0 += p0 + p1; l1 += p2 + p3;
            __nv_bfloat16 h0 = __float2bfloat16(p0), h1 = __float2bfloat16(p1);
            __nv_bfloat16 h2 = __float2bfloat16(p2), h3 = __float2bfloat16(p3);
            ph[nf][0] = ((uint32_t)__bfloat16_as_ushort(h1) << 16) | __bfloat16_as_ushort(h0);
            ph[nf][1] = ((uint32_t)__bfloat16_as_ushort(h3) << 16) | __bfloat16_as_ushort(h2);
            __nv_bfloat16 e0 = __float2bfloat16(p0 - __bfloat162float(h0));
            __nv_bfloat16 e1 = __float2bfloat16(p1 - __bfloat162float(h1));
            __nv_bfloat16 e2 = __float2bfloat16(p2 - __bfloat162float(h2));
            __nv_bfloat16 e3 = __float2bfloat16(p3 - __bfloat162float(h3));
            pl[nf][0] = ((uint32_t)__bfloat16_as_ushort(e1) << 16) | __bfloat16_as_ushort(e0);
            pl[nf][1] = ((uint32_t)__bfloat16_as_ushort(e3) << 16) | __bfloat16_as_ushort(e2);
        }
        // PV: O += P(16x64) @ V(64x64)
        #pragma unroll
        for (int kf = 0; kf < 4; kf++) {
            uint32_t pah[4] = {ph[2 * kf][0], ph[2 * kf][1], ph[2 * kf + 1][0], ph[2 * kf + 1][1]};
            uint32_t pal[4] = {pl[2 * kf][0], pl[2 * kf][1], pl[2 * kf + 1][0], pl[2 * kf + 1][1]};
            int vr = kf * 16 + arl;
            #pragma unroll
            for (int dp = 0; dp < 4; dp++) {
                uint32_t vh[4], vl[4];
                ldsm4t(vh, Vu + vr * 256 + (((dp * 2 + akc) ^ (vr & 7)) << 4));
                ldsm4t(vl, Vu + vr * 256 + (((8 + dp * 2 + akc) ^ (vr & 7)) << 4));
                mma2(accO[2 * dp], pah, vh[0], vh[1]);
                mma2(accO[2 * dp], pal, vh[0], vh[1]);
                mma2(accO[2 * dp], pah, vl[0], vl[1]);
                mma2(accO[2 * dp + 1], pah, vh[2], vh[3]);
                mma2(accO[2 * dp + 1], pal, vh[2], vh[3]);
                mma2(accO[2 * dp + 1], pah, vl[2], vl[3]);
            }
        }
    }
    #pragma unroll
    for (int o = 1; o <= 2; o <<= 1) {
        l0 += __shfl_xor_sync(0xffffffffu, l0, o);
        l1 += __shfl_xor_sync(0xffffffffu, l1, o);
    }
    float i0 = 1.f / l0, i1 = 1.f / l1;
    int r0 = q0 + w * 16 + quad;
    #pragma unroll
    for (int nf = 0; nf < 8; nf++) {
        int col = h * 64 + nf * 8 + tq * 2;
        put_cat(g_ocat + (size_t)(b * SEQ + r0) * KC1 + col, DIM,
                accO[nf][0] * i0, accO[nf][1] * i0);
        put_cat(g_ocat + (size_t)(b * SEQ + r0 + 8) * KC1 + col, DIM,
                accO[nf][2] * i1, accO[nf][3] * i1);
    }
}

// ---------------- gating ----------------
__global__ __launch_bounds__(128) void gate_kernel(const float* __restrict__ gate_w) {
    int t = blockIdx.x * 4 + (threadIdx.x >> 5);
    int lane = threadIdx.x & 31;
    const float* xr = g_h2 + (size_t)t * DIM;
    float p[8];
    #pragma unroll
    for (int e = 0; e < 8; e++) p[e] = 0.f;
    for (int it = 0; it < 32; it++) {
        int d = it * 32 + lane;
        float xv = xr[d];
        const float4* gw = (const float4*)(gate_w + d * 8);
        float4 g0 = gw[0], g1 = gw[1];
        p[0] += xv * g0.x; p[1] += xv * g0.y; p[2] += xv * g0.z; p[3] += xv * g0.w;
        p[4] += xv * g1.x; p[5] += xv * g1.y; p[6] += xv * g1.z; p[7] += xv * g1.w;
    }
    #pragma unroll
    for (int e = 0; e < 8; e++)
        #pragma unroll
        for (int o = 16; o; o >>= 1) p[e] += __shfl_xor_sync(0xffffffffu, p[e], o);
    if (lane == 0) {
        float mx = p[0];
        #pragma unroll
        for (int e = 1; e < 8; e++) mx = fmaxf(mx, p[e]);
        float ex[8], sum = 0.f;
        #pragma unroll
        for (int e = 0; e < 8; e++) { ex[e] = __expf(p[e] - mx); sum += ex[e]; }
        float inv = 1.f / sum;
        float pr[8];
        #pragma unroll
        for (int e = 0; e < 8; e++) { pr[e] = ex[e] * inv; g_probs[t * 8 + e] = pr[e]; }
        int i1 = 0;
        float v1 = pr[0];
        #pragma unroll
        for (int e = 1; e < 8; e++) if (pr[e] > v1) { v1 = pr[e]; i1 = e; }
        int i2 = -1;
        float v2 = -1.f;
        #pragma unroll
        for (int e = 0; e < 8; e++) if (e != i1 && pr[e] > v2) { v2 = pr[e]; i2 = e; }
        float dn = 1.f / (v1 + v2);
        g_eid[t] = i1;
        g_eid[TKN + t] = i2;
        g_wflat[t] = v1 * dn;
        g_wflat[TKN + t] = v2 * dn;
    }
}

// ---------------- per-expert positions ----------------
__global__ void pos_kernel() {
    int e = threadIdx.x >> 5;
    int lane = threadIdx.x & 31;
    int base = 0;
    for (int a0 = 0; a0 < NA; a0 += 32) {
        int ea = g_eid[a0 + lane];
        unsigned mask = __ballot_sync(0xffffffffu, ea == e);
        if (ea == e) g_pos[a0 + lane] = base + __popc(mask & ((1u << lane) - 1));
        base += __popc(mask);
    }
}

// ---------------- scatter tokens (split bf16) into capacity buffer ----------------
__global__ __launch_bounds__(256) void scatter_kernel() {
    int a = blockIdx.x;
    int p = g_pos[a];
    if (p >= CAP) return;
    int e = g_eid[a];
    int tok = a & (TKN - 1);
    float4 v = ((const float4*)(g_h2 + (size_t)tok * DIM))[threadIdx.x];
    __nv_bfloat16* dst = g_bufcat + ((size_t)e * CAP + p) * KC1 + threadIdx.x * 4;
    put_cat(dst, DIM, v.x, v.y);
    put_cat(dst + 2, DIM, v.z, v.w);
}

// ---------------- aux loss ----------------
__global__ __launch_bounds__(256) void aux_kernel(float* __restrict__ out, int out_size) {
    __shared__ float red[256];
    int tid = threadIdx.x;
    float me[8], cnt[8];
    #pragma unroll
    for (int e = 0; e < 8; e++) { me[e] = 0.f; cnt[e] = 0.f; }
    for (int t = tid; t < TKN; t += 256) {
        #pragma unroll
        for (int e = 0; e < 8; e++) me[e] += g_probs[t * 8 + e];
    }
    for (int a = tid; a < NA; a += 256) cnt[g_eid[a]] += 1.f;
    float auxv = 0.f;
    for (int e = 0; e < 8; e++) {
        red[tid] = me[e];
        __syncthreads();
        for (int st = 128; st; st >>= 1) { if (tid < st) red[tid] += red[tid + st]; __syncthreads(); }
        float meS = red[0];
        __syncthreads();
        red[tid] = cnt[e];
        __syncthreads();
        for (int st = 128; st; st >>= 1) { if (tid < st) red[tid] += red[tid + st]; __syncthreads(); }
        float cS = red[0];
        __syncthreads();
        auxv += (meS / (float)TKN) * (cS / (float)NA);
    }
    if (tid == 0 && out_size > TKN * DIM) out[TKN * DIM] = 8.f * auxv;
}

// ---------------- combine ----------------
__global__ __launch_bounds__(256) void final_kernel(float* __restrict__ out) {
    int t = blockIdx.x;
    int tid = threadIdx.x;
    int p1 = g_pos[t], p2 = g_pos[TKN + t];
    int e1 = g_eid[t], e2 = g_eid[TKN + t];
    float w1 = (p1 < CAP) ? g_wflat[t] : 0.f;
    float w2 = (p2 < CAP) ? g_wflat[TKN + t] : 0.f;
    p1 = min(p1, CAP - 1);
    p2 = min(p2, CAP - 1);
    const float4* a = (const float4*)(g_oute + ((size_t)e1 * CAP + p1) * DIM);
    const float4* b = (const float4*)(g_oute + ((size_t)e2 * CAP + p2) * DIM);
    const float4* xr = (const float4*)(g_x2 + (size_t)t * DIM);
    float4 av = a[tid], bv = b[tid], xv = xr[tid];
    float4 r;
    r.x = xv.x + w1 * av.x + w2 * bv.x;
    r.y = xv.y + w1 * av.y + w2 * bv.y;
    r.z = xv.z + w1 * av.z + w2 * bv.z;
    r.w = xv.w + w1 * av.w + w2 * bv.w;
    ((float4*)(out + (size_t)t * DIM))[tid] = r;
}

// ---------------- host ----------------
extern "C" void kernel_launch(void* const* d_in, const int* in_sizes, int n_in,
                              void* d_out, int out_size) {
    const float* x     = (const float*)d_in[0];
    const float* cosT  = (const float*)d_in[1];
    const float* sinT  = (const float*)d_in[2];
    const float* ln1g  = (const float*)d_in[3];
    const float* ln1b  = (const float*)d_in[4];
    const float* ln2g  = (const float*)d_in[5];
    const float* ln2b  = (const float*)d_in[6];
    const float* wqkv  = (const float*)d_in[7];
    const float* bqkv  = (const float*)d_in[8];
    const float* wo    = (const float*)d_in[9];
    const float* bo    = (const float*)d_in[10];
    const float* gatew = (const float*)d_in[11];
    const float* w1    = (const float*)d_in[12];
    const float* b1    = (const float*)d_in[13];
    const float* w2    = (const float*)d_in[14];
    const float* b2    = (const float*)d_in[15];
    float* out = (float*)d_out;

    void *p_qkv, *p_x2, *p_h2;
    void *p_acat, *p_ocat, *p_bufcat, *p_hhcat, *p_wqkvc, *p_woc, *p_w1c, *p_w2c, *p_oute;
    cudaGetSymbolAddress(&p_qkv, g_qkv);
    cudaGetSymbolAddress(&p_x2, g_x2);
    cudaGetSymbolAddress(&p_h2, g_h2);
    cudaGetSymbolAddress(&p_oute, g_oute);
    cudaGetSymbolAddress(&p_acat, g_acat);
    cudaGetSymbolAddress(&p_ocat, g_ocat);
    cudaGetSymbolAddress(&p_bufcat, g_bufcat);
    cudaGetSymbolAddress(&p_hhcat, g_hhcat);
    cudaGetSymbolAddress(&p_wqkvc, g_wqkvcat);
    cudaGetSymbolAddress(&p_woc, g_wocat);
    cudaGetSymbolAddress(&p_w1c, g_w1cat);
    cudaGetSymbolAddress(&p_w2c, g_w2cat);

    static int attr_done = 0;
    if (!attr_done) {
        cudaFuncSetAttribute(tgemm<EPI_PLAIN>, cudaFuncAttributeMaxDynamicSharedMemorySize, GSMEM);
        cudaFuncSetAttribute(tgemm<EPI_WO>, cudaFuncAttributeMaxDynamicSharedMemorySize, GSMEM);
        cudaFuncSetAttribute(tgemm<EPI_W1>, cudaFuncAttributeMaxDynamicSharedMemorySize, GSMEM);
        cudaFuncSetAttribute(flash2_kernel, cudaFuncAttributeMaxDynamicSharedMemorySize, FSMEM);
        attr_done = 1;
    }

    dim3 wb(32, 8);
    wconv_kernel<<<dim3(96, 32, 1), wb>>>(wqkv, (__nv_bfloat16*)p_wqkvc, 1024, 3072, 0, 0);
    wconv_kernel<<<dim3(32, 32, 1), wb>>>(wo, (__nv_bfloat16*)p_woc, 1024, 1024, 0, 0);
    wconv_kernel<<<dim3(128, 32, 8), wb>>>(w1, (__nv_bfloat16*)p_w1c, 1024, 4096,
                                           (size_t)DIM * HID, (size_t)HID * KC1);
    wconv_kernel<<<dim3(32, 128, 8), wb>>>(w2, (__nv_bfloat16*)p_w2c, 4096, 1024,
                                           (size_t)HID * DIM, (size_t)DIM * KC2);
    zero_buf_kernel<<<(int)(((size_t)NE * CAP * KC1 / 8 + 255) / 256), 256>>>();

    // ln1 -> split bf16
    ln_kernel<true><<<TKN, 256>>>(x, ln1g, ln1b, nullptr, (__nv_bfloat16*)p_acat);
    // qkv = h @ wqkv + bqkv
    tgemm<EPI_PLAIN><<<dim3(12, 32, 1), 512, GSMEM>>>(
        (const __nv_bfloat16*)p_acat, (const __nv_bfloat16*)p_wqkvc, bqkv, nullptr,
        (float*)p_qkv, nullptr, KC1, 3072, 0, 0, 0, 0, 0);
    rope_kernel<<<(2 * TKN * NH * 32) / 256, 256>>>(cosT, sinT);
    flash2_kernel<<<dim3(SEQ / 128, NH, 2), 256, FSMEM>>>();
    // x2 = o@wo + bo + x
    tgemm<EPI_WO><<<dim3(4, 32, 1), 512, GSMEM>>>(
        (const __nv_bfloat16*)p_ocat, (const __nv_bfloat16*)p_woc, bo, x,
        (float*)p_x2, nullptr, KC1, 1024, 0, 0, 0, 0, 0);
    // ln2 -> fp32
    ln_kernel<false><<<TKN, 256>>>((const float*)p_x2, ln2g, ln2b, (float*)p_h2, nullptr);
    gate_kernel<<<TKN / 4, 128>>>(gatew);
    pos_kernel<<<1, 256>>>();
    scatter_kernel<<<NA, 256>>>();
    aux_kernel<<<1, 256>>>(out, out_size);
    // hh = gelu(buf@w1 + b1) -> split bf16
    tgemm<EPI_W1><<<dim3(16, 10, 8), 512, GSMEM>>>(
        (const __nv_bfloat16*)p_bufcat, (const __nv_bfloat16*)p_w1c, b1, nullptr,
        nullptr, (__nv_bfloat16*)p_hhcat, KC1, 0, HID,
        (size_t)CAP * KC1, (size_t)HID * KC1, (size_t)HID, (size_t)CAP * KC2);
    // oute = hh@w2 + b2
    tgemm<EPI_PLAIN><<<dim3(4, 10, 8), 512, GSMEM>>>(
        (const __nv_bfloat16*)p_hhcat, (const __nv_bfloat16*)p_w2c, b2, nullptr,
        (float*)p_oute, nullptr, KC2, 1024, 0,
        (size_t)CAP * KC2, (size_t)DIM * KC2, (size_t)DIM, (size_t)CAP * DIM);
    final_kernel<<<TKN, 256>>>(out);
}

// round 7
// speedup vs baseline: 2.9059x; 1.2157x over previous
#include <cuda_runtime.h>
#include <cuda_bf16.h>
#include <math.h>
#include <stdint.h>

#define TKN 4096
#define SEQ 2048
#define DIM 1024
#define NH 16
#define NE 8
#define HID 4096
#define CAP 1280
#define NA 8192

// ---------------- scratch ----------------
__device__ float g_qkv[TKN * 3 * DIM];
__device__ float g_x2[TKN * DIM];
__device__ float g_h2[TKN * DIM];
__device__ float g_probs[TKN * NE];
__device__ int   g_eid[NA];
__device__ float g_wflat[NA];
__device__ int   g_pos[NA];
__device__ int   g_cnt[NE];
__device__ float g_oute[NE * CAP * DIM];

// [hi|lo] compact split buffers (row stride = 2*K)
__device__ __nv_bfloat16 g_acat[(size_t)TKN * 2048];
__device__ __nv_bfloat16 g_ocat[(size_t)TKN * 2048];
__device__ __nv_bfloat16 g_bufcat[(size_t)NE * CAP * 2048];
__device__ __nv_bfloat16 g_hhcat[(size_t)NE * CAP * 8192];
__device__ __nv_bfloat16 g_wqkvcat[(size_t)3072 * 2048];
__device__ __nv_bfloat16 g_wocat[(size_t)1024 * 2048];
__device__ __nv_bfloat16 g_w1cat[(size_t)NE * HID * 2048];
__device__ __nv_bfloat16 g_w2cat[(size_t)NE * DIM * 8192];
// pre-split attention operands: [b*NH+h][seq][128] = hi(64) | lo(64)
__device__ __nv_bfloat16 g_qs[(size_t)2 * NH * SEQ * 128];
__device__ __nv_bfloat16 g_ks[(size_t)2 * NH * SEQ * 128];
__device__ __nv_bfloat16 g_vs[(size_t)2 * NH * SEQ * 128];

// ---------------- helpers ----------------
__device__ __forceinline__ uint32_t smem_u32(const void* p) {
    uint32_t a;
    asm("{ .reg .u64 t; cvta.to.shared.u64 t, %1; cvt.u32.u64 %0, t; }" : "=r"(a) : "l"(p));
    return a;
}
__device__ __forceinline__ void ldsm4(uint32_t* r, uint32_t a) {
    asm volatile("ldmatrix.sync.aligned.m8n8.x4.shared.b16 {%0,%1,%2,%3}, [%4];"
                 : "=r"(r[0]), "=r"(r[1]), "=r"(r[2]), "=r"(r[3]) : "r"(a));
}
__device__ __forceinline__ void ldsm4t(uint32_t* r, uint32_t a) {
    asm volatile("ldmatrix.sync.aligned.m8n8.x4.trans.shared.b16 {%0,%1,%2,%3}, [%4];"
                 : "=r"(r[0]), "=r"(r[1]), "=r"(r[2]), "=r"(r[3]) : "r"(a));
}
__device__ __forceinline__ void mma2(float* c, const uint32_t* a, uint32_t b0, uint32_t b1) {
    asm volatile(
        "mma.sync.aligned.m16n8k16.row.col.f32.bf16.bf16.f32 "
        "{%0,%1,%2,%3}, {%4,%5,%6,%7}, {%8,%9}, {%0,%1,%2,%3};"
        : "+f"(c[0]), "+f"(c[1]), "+f"(c[2]), "+f"(c[3])
        : "r"(a[0]), "r"(a[1]), "r"(a[2]), "r"(a[3]), "r"(b0), "r"(b1));
}
__device__ __forceinline__ void cpa16(uint32_t dst, const void* src) {
    asm volatile("cp.async.cg.shared.global [%0], [%1], 16;" :: "r"(dst), "l"(src));
}
#define CPA_COMMIT() asm volatile("cp.async.commit_group;")
#define CPA_WAIT2()  asm volatile("cp.async.wait_group 2;")
#define CPA_WAIT1()  asm volatile("cp.async.wait_group 1;")

__device__ __forceinline__ float gelu_f(float x) {
    float x3 = x * x * x;
    float t = tanhf(0.7978845608028654f * (x + 0.044715f * x3));
    return 0.5f * x * (1.0f + t);
}
__device__ __forceinline__ void split1(float v, __nv_bfloat16& hi, __nv_bfloat16& lo) {
    hi = __float2bfloat16(v);
    lo = __float2bfloat16(v - __bfloat162float(hi));
}
// write split pair into [hi | lo] layout, slabs of `stride`
__device__ __forceinline__ void put_cat2(__nv_bfloat16* p, int stride, float a, float b) {
    __nv_bfloat16 ah, al, bh, bl;
    split1(a, ah, al);
    split1(b, bh, bl);
    __nv_bfloat162 hi; hi.x = ah; hi.y = bh;
    __nv_bfloat162 lo; lo.x = al; lo.y = bl;
    *(__nv_bfloat162*)(p) = hi;
    *(__nv_bfloat162*)(p + stride) = lo;
}

// ---------------- weight transpose + split: W[K][N] fp32 -> Wt[N][2K] = [hi|lo] ----------------
__global__ __launch_bounds__(256) void wconv_kernel(const float* __restrict__ W,
                                                    __nv_bfloat16* __restrict__ Wt,
                                                    int K, int N, size_t wOff, size_t oOff) {
    int z = blockIdx.z;
    W += wOff * z; Wt += oOff * z;
    __shared__ float t[32][33];
    int n0 = blockIdx.x * 32, k0 = blockIdx.y * 32;
    int tx = threadIdx.x, ty = threadIdx.y;
    #pragma unroll
    for (int j = 0; j < 4; j++)
        t[ty + 8 * j][tx] = W[(size_t)(k0 + ty + 8 * j) * N + n0 + tx];
    __syncthreads();
    #pragma unroll
    for (int j = 0; j < 4; j++) {
        int n = n0 + ty + 8 * j;
        int k = k0 + tx;
        float v = t[tx][ty + 8 * j];
        __nv_bfloat16 hi, lo;
        split1(v, hi, lo);
        __nv_bfloat16* p = Wt + (size_t)n * 2 * K;
        p[k] = hi;
        p[K + k] = lo;
    }
}

// ---------------- layernorm ----------------
template <bool CAT>
__global__ __launch_bounds__(256) void ln_kernel(const float* __restrict__ x,
                                                 const float* __restrict__ g,
                                                 const float* __restrict__ b,
                                                 float* __restrict__ outf,
                                                 __nv_bfloat16* __restrict__ outc) {
    int row = blockIdx.x, tid = threadIdx.x;
    const float4* xr = (const float4*)(x + (size_t)row * DIM);
    float4 v = xr[tid];
    float s = v.x + v.y + v.z + v.w;
    float q = v.x * v.x + v.y * v.y + v.z * v.z + v.w * v.w;
    __shared__ float ss[8], sq[8];
    #pragma unroll
    for (int o = 16; o; o >>= 1) {
        s += __shfl_xor_sync(0xffffffffu, s, o);
        q += __shfl_xor_sync(0xffffffffu, q, o);
    }
    int w = tid >> 5;
    if ((tid & 31) == 0) { ss[w] = s; sq[w] = q; }
    __syncthreads();
    __shared__ float mu_s, rs_s;
    if (tid == 0) {
        float S = 0.f, Q = 0.f;
        #pragma unroll
        for (int i = 0; i < 8; i++) { S += ss[i]; Q += sq[i]; }
        float mu = S / DIM;
        mu_s = mu;
        rs_s = rsqrtf(Q / DIM - mu * mu + 1e-6f);
    }
    __syncthreads();
    float mu = mu_s, rs = rs_s;
    float4 gg = ((const float4*)g)[tid];
    float4 bb = ((const float4*)b)[tid];
    float4 o4;
    o4.x = (v.x - mu) * rs * gg.x + bb.x;
    o4.y = (v.y - mu) * rs * gg.y + bb.y;
    o4.z = (v.z - mu) * rs * gg.z + bb.z;
    o4.w = (v.w - mu) * rs * gg.w + bb.w;
    if (CAT) {
        __nv_bfloat16* p = outc + (size_t)row * 2048 + tid * 4;
        put_cat2(p, DIM, o4.x, o4.y);
        put_cat2(p + 2, DIM, o4.z, o4.w);
    } else {
        ((float4*)(outf + (size_t)row * DIM))[tid] = o4;
    }
}

// ---------------- HMMA GEMM: logical K' = 3K over physical [hi|lo] (2K) buffers ----------------
#define EPI_PLAIN 0
#define EPI_WO 1
#define EPI_W1 2
#define STAGE_BYTES 49152
#define GSMEM (3 * STAGE_BYTES)

template <int EPI>
__global__ __launch_bounds__(512, 1) void tgemm(
    const __nv_bfloat16* __restrict__ A, const __nv_bfloat16* __restrict__ Bt,
    const float* __restrict__ bias, const float* __restrict__ res,
    float* __restrict__ Cf, __nv_bfloat16* __restrict__ Cb,
    int Klog, int Nstr, int HIDN,
    size_t aOff, size_t bOff, size_t biasOff, size_t cOff,
    const int* __restrict__ cnt) {
    extern __shared__ __align__(1024) char smem[];
    const uint32_t sb = smem_u32(smem);
    const int tid = threadIdx.x;
    const int z = blockIdx.z;
    const int m0 = blockIdx.y * 128;
    if (cnt != nullptr && m0 >= cnt[z]) return;
    A += aOff * z; Bt += bOff * z; bias += biasOff * z;
    if (EPI == EPI_W1) Cb += cOff * z; else Cf += cOff * z;
    const int n0 = blockIdx.x * 256;
    const int nk = (3 * Klog) >> 6;
    const int Ks2 = 2 * Klog;

    auto loadStage = [&](int kt, int ss) {
        uint32_t sbase = sb + ss * STAGE_BYTES;
        int kb = kt << 6;
        int akb = kb < Ks2 ? kb : kb - Ks2;       // A logical [hi|lo|hi]
        int bkb = kb < Klog ? kb : kb - Klog;     // B logical [hi|hi|lo]
        const __nv_bfloat16* Ag = A + (size_t)m0 * Ks2 + akb;
        #pragma unroll
        for (int i = 0; i < 2; i++) {
            int id = tid + i * 512;
            int r = id >> 3, c = id & 7;
            cpa16(sbase + r * 128 + ((c ^ (r & 7)) << 4), Ag + (size_t)r * Ks2 + c * 8);
        }
        const __nv_bfloat16* Bg = Bt + (size_t)n0 * Ks2 + bkb;
        #pragma unroll
        for (int i = 0; i < 4; i++) {
            int id = tid + i * 512;
            int r = id >> 3, c = id & 7;
            cpa16(sbase + 16384 + r * 128 + ((c ^ (r & 7)) << 4), Bg + (size_t)r * Ks2 + c * 8);
        }
        CPA_COMMIT();
    };

    loadStage(0, 0);
    loadStage(1, 1);
    loadStage(2, 2);

    const int lane = tid & 31, wid = tid >> 5;
    const int wm = wid & 1, wn = wid >> 1;
    const int arl = lane & 15, akc = lane >> 4;

    int arow[4];
    #pragma unroll
    for (int mf = 0; mf < 4; mf++) arow[mf] = wm * 64 + mf * 16 + arl;

    float acc[4][4][4];
    #pragma unroll
    for (int mf = 0; mf < 4; mf++)
        #pragma unroll
        for (int nf = 0; nf < 4; nf++)
            #pragma unroll
            for (int i = 0; i < 4; i++) acc[mf][nf][i] = 0.f;

    for (int kt = 0; kt < nk; kt++) {
        CPA_WAIT2();
        __syncthreads();
        int ss = kt % 3;
        uint32_t Au = sb + ss * STAGE_BYTES;
        uint32_t Bu = Au + 16384;
        #pragma unroll
        for (int j = 0; j < 4; j++) {
            uint32_t af[4][4];
            #pragma unroll
            for (int mf = 0; mf < 4; mf++) {
                int r = arow[mf];
                ldsm4(af[mf], Au + r * 128 + (((j * 2 + akc) ^ (r & 7)) << 4));
            }
            uint32_t bf[2][4];
            #pragma unroll
            for (int pr = 0; pr < 2; pr++) {
                int r = wn * 32 + pr * 16 + arl;
                ldsm4(bf[pr], Bu + r * 128 + (((j * 2 + akc) ^ (r & 7)) << 4));
            }
            #pragma unroll
            for (int mf = 0; mf < 4; mf++) {
                mma2(acc[mf][0], af[mf], bf[0][0], bf[0][2]);
                mma2(acc[mf][1], af[mf], bf[0][1], bf[0][3]);
                mma2(acc[mf][2], af[mf], bf[1][0], bf[1][2]);
                mma2(acc[mf][3], af[mf], bf[1][1], bf[1][3]);
            }
        }
        __syncthreads();
        if (kt + 3 < nk) loadStage(kt + 3, ss);
        else CPA_COMMIT();
    }

    const int quad = lane >> 2, tq = lane & 3;
    #pragma unroll
    for (int mf = 0; mf < 4; mf++) {
        #pragma unroll
        for (int nf = 0; nf < 4; nf++) {
            int m = m0 + wm * 64 + mf * 16 + quad;
            int n = n0 + wn * 32 + nf * 8 + tq * 2;
            const float* c = acc[mf][nf];
            float b0 = bias[n], b1 = bias[n + 1];
            if (EPI == EPI_W1) {
                float v0 = gelu_f(c[0] + b0), v1 = gelu_f(c[1] + b1);
                put_cat2(Cb + (size_t)m * (2 * HIDN) + n, HIDN, v0, v1);
                v0 = gelu_f(c[2] + b0); v1 = gelu_f(c[3] + b1);
                put_cat2(Cb + (size_t)(m + 8) * (2 * HIDN) + n, HIDN, v0, v1);
            } else {
                float2 v = make_float2(c[0] + b0, c[1] + b1);
                float2 w = make_float2(c[2] + b0, c[3] + b1);
                if (EPI == EPI_WO) {
                    float2 r1 = *(const float2*)&res[(size_t)m * Nstr + n];
                    float2 r2 = *(const float2*)&res[(size_t)(m + 8) * Nstr + n];
                    v.x += r1.x; v.y += r1.y;
                    w.x += r2.x; w.y += r2.y;
                }
                *(float2*)&Cf[(size_t)m * Nstr + n] = v;
                *(float2*)&Cf[(size_t)(m + 8) * Nstr + n] = w;
            }
        }
    }
}

// ---------------- RoPE + bf16 split of q,k,v into attention layout ----------------
__global__ void rope3_kernel(const float* __restrict__ cosT, const float* __restrict__ sinT) {
    int idx = blockIdx.x * blockDim.x + threadIdx.x;
    if (idx >= 3 * TKN * NH * 32) return;
    int i = idx & 31;
    int h = (idx >> 5) & 15;
    int t = (idx >> 9) & 4095;
    int qk = idx >> 21;
    int s = t & (SEQ - 1);
    int b = t >> 11;
    size_t src = (size_t)t * 3072 + (size_t)qk * 1024 + h * 64;
    float a = g_qkv[src + i];
    float c = g_qkv[src + i + 32];
    if (qk < 2) {
        float c0 = cosT[s * 64 + i], s0 = sinT[s * 64 + i];
        float c1 = cosT[s * 64 + i + 32], s1 = sinT[s * 64 + i + 32];
        float na = a * c0 - c * s0;
        float nc = c * c1 + a * s1;
        a = na; c = nc;
    }
    __nv_bfloat16 ah, al, ch, cl;
    split1(a, ah, al);
    split1(c, ch, cl);
    __nv_bfloat16* D = (qk == 0 ? g_qs : qk == 1 ? g_ks : g_vs)
                       + ((size_t)(b * NH + h) * SEQ + s) * 128;
    D[i] = ah;
    D[32 + i] = ch;
    D[64 + i] = al;
    D[96 + i] = cl;
}

// ---------------- HMMA flash attention, pre-split bf16, cp.async double-buffered K/V ----------------
#define FSMEM 98304
__global__ __launch_bounds__(256, 2) void flash3_kernel() {
    extern __shared__ __align__(1024) char fsm[];
    const uint32_t Qu = smem_u32(fsm);
    const int b = blockIdx.z, h = blockIdx.y, q0 = blockIdx.x * 128;
    const int tid = threadIdx.x, lane = tid & 31, w = tid >> 5;
    const int arl = lane & 15, akc = lane >> 4;
    const int tq = lane & 3, quad = lane >> 2;
    const __nv_bfloat16* qsrc = g_qs + (size_t)(b * NH + h) * SEQ * 128;
    const __nv_bfloat16* ksrc = g_ks + (size_t)(b * NH + h) * SEQ * 128;
    const __nv_bfloat16* vsrc = g_vs + (size_t)(b * NH + h) * SEQ * 128;

    // Q tile (joins cp.async group 0)
    #pragma unroll
    for (int i = 0; i < 8; i++) {
        int id = tid + i * 256;
        int r = id >> 4, ch = id & 15;
        cpa16(Qu + r * 256 + ((ch ^ (r & 7)) << 4), qsrc + (size_t)(q0 + r) * 128 + ch * 8);
    }
    auto loadKV = [&](int kt, int st) {
        uint32_t Ks = Qu + 32768 + st * 32768;
        #pragma unroll
        for (int i = 0; i < 4; i++) {
            int id = tid + i * 256;
            int r = id >> 4, ch = id & 15;
            cpa16(Ks + r * 256 + ((ch ^ (r & 7)) << 4), ksrc + (size_t)(kt * 64 + r) * 128 + ch * 8);
        }
        uint32_t Vs = Ks + 16384;
        #pragma unroll
        for (int i = 0; i < 4; i++) {
            int id = tid + i * 256;
            int r = id >> 4, ch = id & 15;
            cpa16(Vs + r * 256 + ((ch ^ (r & 7)) << 4), vsrc + (size_t)(kt * 64 + r) * 128 + ch * 8);
        }
        CPA_COMMIT();
    };
    loadKV(0, 0);
    loadKV(1, 1);

    float accO[8][4];
    #pragma unroll
    for (int nf = 0; nf < 8; nf++)
        #pragma unroll
        for (int i = 0; i < 4; i++) accO[nf][i] = 0.f;
    float m0 = -1e30f, m1 = -1e30f, l0 = 0.f, l1 = 0.f;
    const int qr = w * 16 + arl;

    for (int kt = 0; kt < SEQ / 64; kt++) {
        int st = kt & 1;
        CPA_WAIT1();
        __syncthreads();
        uint32_t Ku = Qu + 32768 + st * 32768;
        uint32_t Vu = Ku + 16384;

        float accS[8][4];
        #pragma unroll
        for (int nf = 0; nf < 8; nf++)
            #pragma unroll
            for (int i = 0; i < 4; i++) accS[nf][i] = 0.f;
        #pragma unroll
        for (int j = 0; j < 4; j++) {
            uint32_t ah[4], al[4];
            ldsm4(ah, Qu + qr * 256 + (((j * 2 + akc) ^ (qr & 7)) << 4));
            ldsm4(al, Qu + qr * 256 + (((8 + j * 2 + akc) ^ (qr & 7)) << 4));
            #pragma unroll
            for (int pr = 0; pr < 4; pr++) {
                int kr = pr * 16 + arl;
                uint32_t bh[4], bl[4];
                ldsm4(bh, Ku + kr * 256 + (((j * 2 + akc) ^ (kr & 7)) << 4));
                ldsm4(bl, Ku + kr * 256 + (((8 + j * 2 + akc) ^ (kr & 7)) << 4));
                mma2(accS[2 * pr], ah, bh[0], bh[2]);
                mma2(accS[2 * pr], al, bh[0], bh[2]);
                mma2(accS[2 * pr], ah, bl[0], bl[2]);
                mma2(accS[2 * pr + 1], ah, bh[1], bh[3]);
                mma2(accS[2 * pr + 1], al, bh[1], bh[3]);
                mma2(accS[2 * pr + 1], ah, bl[1], bl[3]);
            }
        }
        float mt0 = m0, mt1 = m1;
        #pragma unroll
        for (int nf = 0; nf < 8; nf++) {
            #pragma unroll
            for (int i = 0; i < 4; i++) accS[nf][i] *= 0.125f;
            mt0 = fmaxf(mt0, fmaxf(accS[nf][0], accS[nf][1]));
            mt1 = fmaxf(mt1, fmaxf(accS[nf][2], accS[nf][3]));
        }
        #pragma unroll
        for (int o = 1; o <= 2; o <<= 1) {
            mt0 = fmaxf(mt0, __shfl_xor_sync(0xffffffffu, mt0, o));
            mt1 = fmaxf(mt1, __shfl_xor_sync(0xffffffffu, mt1, o));
        }
        float c0 = __expf(m0 - mt0), c1 = __expf(m1 - mt1);
        m0 = mt0; m1 = mt1;
        l0 *= c0; l1 *= c1;
        #pragma unroll
        for (int nf = 0; nf < 8; nf++) {
            accO[nf][0] *= c0; accO[nf][1] *= c0;
            accO[nf][2] *= c1; accO[nf][3] *= c1;
        }
        uint32_t ph[8][2], pl[8][2];
        #pragma unroll
        for (int nf = 0; nf < 8; nf++) {
            float p0 = __expf(accS[nf][0] - mt0);
            float p1 = __expf(accS[nf][1] - mt0);
            float p2 = __expf(accS[nf][2] - mt1);
            float p3 = __expf(accS[nf][3] - mt1);
            l0 += p0 + p1; l1 += p2 + p3;
            __nv_bfloat16 h0, e0, h1, e1, h2, e2, h3, e3;
            split1(p0, h0, e0); split1(p1, h1, e1);
            split1(p2, h2, e2); split1(p3, h3, e3);
            ph[nf][0] = ((uint32_t)__bfloat16_as_ushort(h1) << 16) | __bfloat16_as_ushort(h0);
            ph[nf][1] = ((uint32_t)__bfloat16_as_ushort(h3) << 16) | __bfloat16_as_ushort(h2);
            pl[nf][0] = ((uint32_t)__bfloat16_as_ushort(e1) << 16) | __bfloat16_as_ushort(e0);
            pl[nf][1] = ((uint32_t)__bfloat16_as_ushort(e3) << 16) | __bfloat16_as_ushort(e2);
        }
        #pragma unroll
        for (int kf = 0; kf < 4; kf++) {
            uint32_t pah[4] = {ph[2 * kf][0], ph[2 * kf][1], ph[2 * kf + 1][0], ph[2 * kf + 1][1]};
            uint32_t pal[4] = {pl[2 * kf][0], pl[2 * kf][1], pl[2 * kf + 1][0], pl[2 * kf + 1][1]};
            int vr = kf * 16 + arl;
            #pragma unroll
            for (int dp = 0; dp < 4; dp++) {
                uint32_t vh[4], vl[4];
                ldsm4t(vh, Vu + vr * 256 + (((dp * 2 + akc) ^ (vr & 7)) << 4));
                ldsm4t(vl, Vu + vr * 256 + (((8 + dp * 2 + akc) ^ (vr & 7)) << 4));
                mma2(accO[2 * dp], pah, vh[0], vh[1]);
                mma2(accO[2 * dp], pal, vh[0], vh[1]);
                mma2(accO[2 * dp], pah, vl[0], vl[1]);
                mma2(accO[2 * dp + 1], pah, vh[2], vh[3]);
                mma2(accO[2 * dp + 1], pal, vh[2], vh[3]);
                mma2(accO[2 * dp + 1], pah, vl[2], vl[3]);
            }
        }
        __syncthreads();
        if (kt + 2 < SEQ / 64) loadKV(kt + 2, st);
        else CPA_COMMIT();
    }
    #pragma unroll
    for (int o = 1; o <= 2; o <<= 1) {
        l0 += __shfl_xor_sync(0xffffffffu, l0, o);
        l1 += __shfl_xor_sync(0xffffffffu, l1, o);
    }
    float i0 = 1.f / l0, i1 = 1.f / l1;
    int r0 = q0 + w * 16 + quad;
    #pragma unroll
    for (int nf = 0; nf < 8; nf++) {
        int col = h * 64 + nf * 8 + tq * 2;
        put_cat2(g_ocat + (size_t)(b * SEQ + r0) * 2048 + col, DIM,
                 accO[nf][0] * i0, accO[nf][1] * i0);
        put_cat2(g_ocat + (size_t)(b * SEQ + r0 + 8) * 2048 + col, DIM,
                 accO[nf][2] * i1, accO[nf][3] * i1);
    }
}

// ---------------- gating ----------------
__global__ __launch_bounds__(128) void gate_kernel(const float* __restrict__ gate_w) {
    int t = blockIdx.x * 4 + (threadIdx.x >> 5);
    int lane = threadIdx.x & 31;
    const float* xr = g_h2 + (size_t)t * DIM;
    float p[8];
    #pragma unroll
    for (int e = 0; e < 8; e++) p[e] = 0.f;
    for (int it = 0; it < 32; it++) {
        int d = it * 32 + lane;
        float xv = xr[d];
        const float4* gw = (const float4*)(gate_w + d * 8);
        float4 g0 = gw[0], g1 = gw[1];
        p[0] += xv * g0.x; p[1] += xv * g0.y; p[2] += xv * g0.z; p[3] += xv * g0.w;
        p[4] += xv * g1.x; p[5] += xv * g1.y; p[6] += xv * g1.z; p[7] += xv * g1.w;
    }
    #pragma unroll
    for (int e = 0; e < 8; e++)
        #pragma unroll
        for (int o = 16; o; o >>= 1) p[e] += __shfl_xor_sync(0xffffffffu, p[e], o);
    if (lane == 0) {
        float mx = p[0];
        #pragma unroll
        for (int e = 1; e < 8; e++) mx = fmaxf(mx, p[e]);
        float ex[8], sum = 0.f;
        #pragma unroll
        for (int e = 0; e < 8; e++) { ex[e] = __expf(p[e] - mx); sum += ex[e]; }
        float inv = 1.f / sum;
        float pr[8];
        #pragma unroll
        for (int e = 0; e < 8; e++) { pr[e] = ex[e] * inv; g_probs[t * 8 + e] = pr[e]; }
        int i1 = 0;
        float v1 = pr[0];
        #pragma unroll
        for (int e = 1; e < 8; e++) if (pr[e] > v1) { v1 = pr[e]; i1 = e; }
        int i2 = -1;
        float v2 = -1.f;
        #pragma unroll
        for (int e = 0; e < 8; e++) if (e != i1 && pr[e] > v2) { v2 = pr[e]; i2 = e; }
        float dn = 1.f / (v1 + v2);
        g_eid[t] = i1;
        g_eid[TKN + t] = i2;
        g_wflat[t] = v1 * dn;
        g_wflat[TKN + t] = v2 * dn;
    }
}

// ---------------- per-expert positions + counts ----------------
__global__ void pos_kernel() {
    int e = threadIdx.x >> 5;
    int lane = threadIdx.x & 31;
    int base = 0;
    for (int a0 = 0; a0 < NA; a0 += 32) {
        int ea = g_eid[a0 + lane];
        unsigned mask = __ballot_sync(0xffffffffu, ea == e);
        if (ea == e) g_pos[a0 + lane] = base + __popc(mask & ((1u << lane) - 1));
        base += __popc(mask);
    }
    if (lane == 0) g_cnt[e] = base;
}

// ---------------- scatter tokens (split bf16) into capacity buffer ----------------
__global__ __launch_bounds__(256) void scatter_kernel() {
    int a = blockIdx.x;
    int p = g_pos[a];
    if (p >= CAP) return;
    int e = g_eid[a];
    int tok = a & (TKN - 1);
    float4 v = ((const float4*)(g_h2 + (size_t)tok * DIM))[threadIdx.x];
    __nv_bfloat16* dst = g_bufcat + ((size_t)e * CAP + p) * 2048 + threadIdx.x * 4;
    put_cat2(dst, DIM, v.x, v.y);
    put_cat2(dst + 2, DIM, v.z, v.w);
}

// ---------------- aux loss ----------------
__global__ __launch_bounds__(256) void aux_kernel(float* __restrict__ out, int out_size) {
    __shared__ float red[256];
    int tid = threadIdx.x;
    float me[8], cnt[8];
    #pragma unroll
    for (int e = 0; e < 8; e++) { me[e] = 0.f; cnt[e] = 0.f; }
    for (int t = tid; t < TKN; t += 256) {
        #pragma unroll
        for (int e = 0; e < 8; e++) me[e] += g_probs[t * 8 + e];
    }
    for (int a = tid; a < NA; a += 256) cnt[g_eid[a]] += 1.f;
    float auxv = 0.f;
    for (int e = 0; e < 8; e++) {
        red[tid] = me[e];
        __syncthreads();
        for (int st = 128; st; st >>= 1) { if (tid < st) red[tid] += red[tid + st]; __syncthreads(); }
        float meS = red[0];
        __syncthreads();
        red[tid] = cnt[e];
        __syncthreads();
        for (int st = 128; st; st >>= 1) { if (tid < st) red[tid] += red[tid + st]; __syncthreads(); }
        float cS = red[0];
        __syncthreads();
        auxv += (meS / (float)TKN) * (cS / (float)NA);
    }
    if (tid == 0 && out_size > TKN * DIM) out[TKN * DIM] = 8.f * auxv;
}

// ---------------- combine ----------------
__global__ __launch_bounds__(256) void final_kernel(float* __restrict__ out) {
    int t = blockIdx.x;
    int tid = threadIdx.x;
    int p1 = g_pos[t], p2 = g_pos[TKN + t];
    int e1 = g_eid[t], e2 = g_eid[TKN + t];
    float w1 = (p1 < CAP) ? g_wflat[t] : 0.f;
    float w2 = (p2 < CAP) ? g_wflat[TKN + t] : 0.f;
    p1 = min(p1, CAP - 1);
    p2 = min(p2, CAP - 1);
    const float4* a = (const float4*)(g_oute + ((size_t)e1 * CAP + p1) * DIM);
    const float4* b = (const float4*)(g_oute + ((size_t)e2 * CAP + p2) * DIM);
    const float4* xr = (const float4*)(g_x2 + (size_t)t * DIM);
    float4 av = a[tid], bv = b[tid], xv = xr[tid];
    float4 r;
    r.x = xv.x + w1 * av.x + w2 * bv.x;
    r.y = xv.y + w1 * av.y + w2 * bv.y;
    r.z = xv.z + w1 * av.z + w2 * bv.z;
    r.w = xv.w + w1 * av.w + w2 * bv.w;
    ((float4*)(out + (size_t)t * DIM))[tid] = r;
}

// ---------------- host ----------------
extern "C" void kernel_launch(void* const* d_in, const int* in_sizes, int n_in,
                              void* d_out, int out_size) {
    const float* x     = (const float*)d_in[0];
    const float* cosT  = (const float*)d_in[1];
    const float* sinT  = (const float*)d_in[2];
    const float* ln1g  = (const float*)d_in[3];
    const float* ln1b  = (const float*)d_in[4];
    const float* ln2g  = (const float*)d_in[5];
    const float* ln2b  = (const float*)d_in[6];
    const float* wqkv  = (const float*)d_in[7];
    const float* bqkv  = (const float*)d_in[8];
    const float* wo    = (const float*)d_in[9];
    const float* bo    = (const float*)d_in[10];
    const float* gatew = (const float*)d_in[11];
    const float* w1    = (const float*)d_in[12];
    const float* b1    = (const float*)d_in[13];
    const float* w2    = (const float*)d_in[14];
    const float* b2    = (const float*)d_in[15];
    float* out = (float*)d_out;

    void *p_qkv, *p_x2, *p_h2, *p_oute, *p_cnt;
    void *p_acat, *p_ocat, *p_bufcat, *p_hhcat, *p_wqkvc, *p_woc, *p_w1c, *p_w2c;
    cudaGetSymbolAddress(&p_qkv, g_qkv);
    cudaGetSymbolAddress(&p_x2, g_x2);
    cudaGetSymbolAddress(&p_h2, g_h2);
    cudaGetSymbolAddress(&p_oute, g_oute);
    cudaGetSymbolAddress(&p_cnt, g_cnt);
    cudaGetSymbolAddress(&p_acat, g_acat);
    cudaGetSymbolAddress(&p_ocat, g_ocat);
    cudaGetSymbolAddress(&p_bufcat, g_bufcat);
    cudaGetSymbolAddress(&p_hhcat, g_hhcat);
    cudaGetSymbolAddress(&p_wqkvc, g_wqkvcat);
    cudaGetSymbolAddress(&p_woc, g_wocat);
    cudaGetSymbolAddress(&p_w1c, g_w1cat);
    cudaGetSymbolAddress(&p_w2c, g_w2cat);

    static int attr_done = 0;
    if (!attr_done) {
        cudaFuncSetAttribute(tgemm<EPI_PLAIN>, cudaFuncAttributeMaxDynamicSharedMemorySize, GSMEM);
        cudaFuncSetAttribute(tgemm<EPI_WO>, cudaFuncAttributeMaxDynamicSharedMemorySize, GSMEM);
        cudaFuncSetAttribute(tgemm<EPI_W1>, cudaFuncAttributeMaxDynamicSharedMemorySize, GSMEM);
        cudaFuncSetAttribute(flash3_kernel, cudaFuncAttributeMaxDynamicSharedMemorySize, FSMEM);
        attr_done = 1;
    }

    dim3 wb(32, 8);
    wconv_kernel<<<dim3(96, 32, 1), wb>>>(wqkv, (__nv_bfloat16*)p_wqkvc, 1024, 3072, 0, 0);
    wconv_kernel<<<dim3(32, 32, 1), wb>>>(wo, (__nv_bfloat16*)p_woc, 1024, 1024, 0, 0);
    wconv_kernel<<<dim3(128, 32, 8), wb>>>(w1, (__nv_bfloat16*)p_w1c, 1024, 4096,
                                           (size_t)DIM * HID, (size_t)HID * 2048);
    wconv_kernel<<<dim3(32, 128, 8), wb>>>(w2, (__nv_bfloat16*)p_w2c, 4096, 1024,
                                           (size_t)HID * DIM, (size_t)DIM * 8192);

    // ln1 -> split bf16
    ln_kernel<true><<<TKN, 256>>>(x, ln1g, ln1b, nullptr, (__nv_bfloat16*)p_acat);
    // qkv = h @ wqkv + bqkv
    tgemm<EPI_PLAIN><<<dim3(12, 32, 1), 512, GSMEM>>>(
        (const __nv_bfloat16*)p_acat, (const __nv_bfloat16*)p_wqkvc, bqkv, nullptr,
        (float*)p_qkv, nullptr, 1024, 3072, 0, 0, 0, 0, 0, nullptr);
    // rope + split q,k,v
    rope3_kernel<<<(3 * TKN * NH * 32) / 256, 256>>>(cosT, sinT);
    flash3_kernel<<<dim3(SEQ / 128, NH, 2), 256, FSMEM>>>();
    // x2 = o@wo + bo + x
    tgemm<EPI_WO><<<dim3(4, 32, 1), 512, GSMEM>>>(
        (const __nv_bfloat16*)p_ocat, (const __nv_bfloat16*)p_woc, bo, x,
        (float*)p_x2, nullptr, 1024, 1024, 0, 0, 0, 0, 0, nullptr);
    // ln2 -> fp32
    ln_kernel<false><<<TKN, 256>>>((const float*)p_x2, ln2g, ln2b, (float*)p_h2, nullptr);
    gate_kernel<<<TKN / 4, 128>>>(gatew);
    pos_kernel<<<1, 256>>>();
    scatter_kernel<<<NA, 256>>>();
    aux_kernel<<<1, 256>>>(out, out_size);
    // hh = gelu(buf@w1 + b1) -> split bf16 (skips tiles beyond expert count)
    tgemm<EPI_W1><<<dim3(16, 10, 8), 512, GSMEM>>>(
        (const __nv_bfloat16*)p_bufcat, (const __nv_bfloat16*)p_w1c, b1, nullptr,
        nullptr, (__nv_bfloat16*)p_hhcat, 1024, 0, HID,
        (size_t)CAP * 2048, (size_t)HID * 2048, (size_t)HID, (size_t)CAP * 8192,
        (const int*)p_cnt);
    // oute = hh@w2 + b2 (skips tiles beyond expert count)
    tgemm<EPI_PLAIN><<<dim3(4, 10, 8), 512, GSMEM>>>(
        (const __nv_bfloat16*)p_hhcat, (const __nv_bfloat16*)p_w2c, b2, nullptr,
        (float*)p_oute, nullptr, 4096, 1024, 0,
        (size_t)CAP * 8192, (size_t)DIM * 8192, (size_t)DIM, (size_t)CAP * DIM,
        (const int*)p_cnt);
    final_kernel<<<TKN, 256>>>(out);
}

// round 9
// speedup vs baseline: 3.0971x; 1.0658x over previous
#include <cuda_runtime.h>
#include <cuda_bf16.h>
#include <math.h>
#include <stdint.h>

#define TKN 4096
#define SEQ 2048
#define DIM 1024
#define NH 16
#define NE 8
#define HID 4096
#define CAP 1280
#define NA 8192

// ---------------- scratch ----------------
__device__ float g_qkv[TKN * 3 * DIM];
__device__ float g_x2[TKN * DIM];
__device__ float g_h2[TKN * DIM];
__device__ float g_probs[TKN * NE];
__device__ int   g_eid[NA];
__device__ float g_wflat[NA];
__device__ int   g_pos[NA];
__device__ int   g_cnt[NE];
__device__ float g_oute[NE * CAP * DIM];

// [hi|lo] compact split buffers (row stride = 2*K)
__device__ __nv_bfloat16 g_acat[(size_t)TKN * 2048];
__device__ __nv_bfloat16 g_ocat[(size_t)TKN * 2048];
__device__ __nv_bfloat16 g_bufcat[(size_t)NE * CAP * 2048];
__device__ __nv_bfloat16 g_hhcat[(size_t)NE * CAP * 8192];
__device__ __nv_bfloat16 g_wqkvcat[(size_t)3072 * 2048];
__device__ __nv_bfloat16 g_wocat[(size_t)1024 * 2048];
__device__ __nv_bfloat16 g_w1cat[(size_t)NE * HID * 2048];
__device__ __nv_bfloat16 g_w2cat[(size_t)NE * DIM * 8192];
// pre-split attention operands: [b*NH+h][seq][128] = hi(64) | lo(64)
__device__ __nv_bfloat16 g_qs[(size_t)2 * NH * SEQ * 128];
__device__ __nv_bfloat16 g_ks[(size_t)2 * NH * SEQ * 128];
__device__ __nv_bfloat16 g_vs[(size_t)2 * NH * SEQ * 128];

// ---------------- helpers ----------------
__device__ __forceinline__ uint32_t smem_u32(const void* p) {
    uint32_t a;
    asm("{ .reg .u64 t; cvta.to.shared.u64 t, %1; cvt.u32.u64 %0, t; }" : "=r"(a) : "l"(p));
    return a;
}
__device__ __forceinline__ void ldsm4(uint32_t* r, uint32_t a) {
    asm volatile("ldmatrix.sync.aligned.m8n8.x4.shared.b16 {%0,%1,%2,%3}, [%4];"
                 : "=r"(r[0]), "=r"(r[1]), "=r"(r[2]), "=r"(r[3]) : "r"(a));
}
__device__ __forceinline__ void ldsm4t(uint32_t* r, uint32_t a) {
    asm volatile("ldmatrix.sync.aligned.m8n8.x4.trans.shared.b16 {%0,%1,%2,%3}, [%4];"
                 : "=r"(r[0]), "=r"(r[1]), "=r"(r[2]), "=r"(r[3]) : "r"(a));
}
__device__ __forceinline__ void mma2(float* c, const uint32_t* a, uint32_t b0, uint32_t b1) {
    asm volatile(
        "mma.sync.aligned.m16n8k16.row.col.f32.bf16.bf16.f32 "
        "{%0,%1,%2,%3}, {%4,%5,%6,%7}, {%8,%9}, {%0,%1,%2,%3};"
        : "+f"(c[0]), "+f"(c[1]), "+f"(c[2]), "+f"(c[3])
        : "r"(a[0]), "r"(a[1]), "r"(a[2]), "r"(a[3]), "r"(b0), "r"(b1));
}
__device__ __forceinline__ void cpa16(uint32_t dst, const void* src) {
    asm volatile("cp.async.cg.shared.global [%0], [%1], 16;" :: "r"(dst), "l"(src));
}
#define CPA_COMMIT() asm volatile("cp.async.commit_group;")
#define CPA_WAIT2()  asm volatile("cp.async.wait_group 2;")
#define CPA_WAIT1()  asm volatile("cp.async.wait_group 1;")

__device__ __forceinline__ float gelu_f(float x) {
    float x3 = x * x * x;
    float t = tanhf(0.7978845608028654f * (x + 0.044715f * x3));
    return 0.5f * x * (1.0f + t);
}
__device__ __forceinline__ void split1(float v, __nv_bfloat16& hi, __nv_bfloat16& lo) {
    hi = __float2bfloat16(v);
    lo = __float2bfloat16(v - __bfloat162float(hi));
}
__device__ __forceinline__ uint32_t packbf(__nv_bfloat16 a, __nv_bfloat16 b) {
    return ((uint32_t)__bfloat16_as_ushort(b) << 16) | __bfloat16_as_ushort(a);
}
// write split pair into [hi | lo] layout, slabs of `stride`
__device__ __forceinline__ void put_cat2(__nv_bfloat16* p, int stride, float a, float b) {
    __nv_bfloat16 ah, al, bh, bl;
    split1(a, ah, al);
    split1(b, bh, bl);
    __nv_bfloat162 hi; hi.x = ah; hi.y = bh;
    __nv_bfloat162 lo; lo.x = al; lo.y = bl;
    *(__nv_bfloat162*)(p) = hi;
    *(__nv_bfloat162*)(p + stride) = lo;
}

// ---------------- weight transpose + split (vectorized): W[K][N] -> Wt[N][2K] = [hi|lo] ----------------
__global__ __launch_bounds__(256) void wconv_kernel(const float* __restrict__ W,
                                                    __nv_bfloat16* __restrict__ Wt,
                                                    int K, int N, size_t wOff, size_t oOff) {
    int z = blockIdx.z;
    W += wOff * z; Wt += oOff * z;
    __shared__ float t[64][33];
    int n0 = blockIdx.x * 32, k0 = blockIdx.y * 64;
    int tid = threadIdx.x;
    #pragma unroll
    for (int i = 0; i < 8; i++) {
        int id = tid + i * 256;
        int k = id >> 5, n = id & 31;
        t[k][n] = W[(size_t)(k0 + k) * N + n0 + n];
    }
    __syncthreads();
    int n = tid >> 3, kq = tid & 7;
    uint32_t hw[4], lw[4];
    #pragma unroll
    for (int j = 0; j < 4; j++) {
        float a = t[kq * 8 + 2 * j][n], b = t[kq * 8 + 2 * j + 1][n];
        __nv_bfloat16 ah, al, bh, bl;
        split1(a, ah, al);
        split1(b, bh, bl);
        hw[j] = packbf(ah, bh);
        lw[j] = packbf(al, bl);
    }
    __nv_bfloat16* p = Wt + (size_t)(n0 + n) * 2 * K + k0 + kq * 8;
    *(uint4*)p = make_uint4(hw[0], hw[1], hw[2], hw[3]);
    *(uint4*)(p + K) = make_uint4(lw[0], lw[1], lw[2], lw[3]);
}

// ---------------- layernorm ----------------
template <bool CAT>
__global__ __launch_bounds__(256) void ln_kernel(const float* __restrict__ x,
                                                 const float* __restrict__ g,
                                                 const float* __restrict__ b,
                                                 float* __restrict__ outf,
                                                 __nv_bfloat16* __restrict__ outc) {
    int row = blockIdx.x, tid = threadIdx.x;
    const float4* xr = (const float4*)(x + (size_t)row * DIM);
    float4 v = xr[tid];
    float s = v.x + v.y + v.z + v.w;
    float q = v.x * v.x + v.y * v.y + v.z * v.z + v.w * v.w;
    __shared__ float ss[8], sq[8];
    #pragma unroll
    for (int o = 16; o; o >>= 1) {
        s += __shfl_xor_sync(0xffffffffu, s, o);
        q += __shfl_xor_sync(0xffffffffu, q, o);
    }
    int w = tid >> 5;
    if ((tid & 31) == 0) { ss[w] = s; sq[w] = q; }
    __syncthreads();
    __shared__ float mu_s, rs_s;
    if (tid == 0) {
        float S = 0.f, Q = 0.f;
        #pragma unroll
        for (int i = 0; i < 8; i++) { S += ss[i]; Q += sq[i]; }
        float mu = S / DIM;
        mu_s = mu;
        rs_s = rsqrtf(Q / DIM - mu * mu + 1e-6f);
    }
    __syncthreads();
    float mu = mu_s, rs = rs_s;
    float4 gg = ((const float4*)g)[tid];
    float4 bb = ((const float4*)b)[tid];
    float4 o4;
    o4.x = (v.x - mu) * rs * gg.x + bb.x;
    o4.y = (v.y - mu) * rs * gg.y + bb.y;
    o4.z = (v.z - mu) * rs * gg.z + bb.z;
    o4.w = (v.w - mu) * rs * gg.w + bb.w;
    if (CAT) {
        __nv_bfloat16* p = outc + (size_t)row * 2048 + tid * 4;
        put_cat2(p, DIM, o4.x, o4.y);
        put_cat2(p + 2, DIM, o4.z, o4.w);
    } else {
        ((float4*)(outf + (size_t)row * DIM))[tid] = o4;
    }
}

// ---------------- HMMA GEMM: logical K' = 3K over physical [hi|lo] (2K) buffers ----------------
// 4-stage cp.async ring, single __syncthreads per K-tile.
#define EPI_PLAIN 0
#define EPI_WO 1
#define EPI_W1 2
#define EPI_QKV 3
#define STAGE_BYTES 49152
#define GSMEM (4 * STAGE_BYTES)

template <int EPI>
__global__ __launch_bounds__(512, 1) void tgemm(
    const __nv_bfloat16* __restrict__ A, const __nv_bfloat16* __restrict__ Bt,
    const float* __restrict__ bias, const float* __restrict__ res,
    float* __restrict__ Cf, __nv_bfloat16* __restrict__ Cb,
    int Klog, int Nstr, int HIDN,
    size_t aOff, size_t bOff, size_t biasOff, size_t cOff,
    const int* __restrict__ cnt) {
    extern __shared__ __align__(1024) char smem[];
    const uint32_t sb = smem_u32(smem);
    const int tid = threadIdx.x;
    const int z = blockIdx.z;
    const int m0 = blockIdx.y * 128;
    if (cnt != nullptr && m0 >= cnt[z]) return;
    A += aOff * z; Bt += bOff * z; bias += biasOff * z;
    if (EPI == EPI_W1) Cb += cOff * z; else Cf += cOff * z;
    const int n0 = blockIdx.x * 256;
    const int nk = (3 * Klog) >> 6;
    const int Ks2 = 2 * Klog;

    auto loadStage = [&](int kt, int ss) {
        uint32_t sbase = sb + ss * STAGE_BYTES;
        int kb = kt << 6;
        int akb = kb < Ks2 ? kb : kb - Ks2;       // A logical [hi|lo|hi]
        int bkb = kb < Klog ? kb : kb - Klog;     // B logical [hi|hi|lo]
        const __nv_bfloat16* Ag = A + (size_t)m0 * Ks2 + akb;
        #pragma unroll
        for (int i = 0; i < 2; i++) {
            int id = tid + i * 512;
            int r = id >> 3, c = id & 7;
            cpa16(sbase + r * 128 + ((c ^ (r & 7)) << 4), Ag + (size_t)r * Ks2 + c * 8);
        }
        const __nv_bfloat16* Bg = Bt + (size_t)n0 * Ks2 + bkb;
        #pragma unroll
        for (int i = 0; i < 4; i++) {
            int id = tid + i * 512;
            int r = id >> 3, c = id & 7;
            cpa16(sbase + 16384 + r * 128 + ((c ^ (r & 7)) << 4), Bg + (size_t)r * Ks2 + c * 8);
        }
        CPA_COMMIT();
    };

    loadStage(0, 0);
    loadStage(1, 1);
    loadStage(2, 2);

    const int lane = tid & 31, wid = tid >> 5;
    const int wm = wid & 1, wn = wid >> 1;
    const int arl = lane & 15, akc = lane >> 4;

    int arow[4];
    #pragma unroll
    for (int mf = 0; mf < 4; mf++) arow[mf] = wm * 64 + mf * 16 + arl;

    float acc[4][4][4];
    #pragma unroll
    for (int mf = 0; mf < 4; mf++)
        #pragma unroll
        for (int nf = 0; nf < 4; nf++)
            #pragma unroll
            for (int i = 0; i < 4; i++) acc[mf][nf][i] = 0.f;

    for (int kt = 0; kt < nk; kt++) {
        CPA_WAIT2();
        __syncthreads();
        // prefetch 3 ahead into stage (kt+3)&3 == (kt-1)&3 — safe: all threads
        // finished reading that stage before this barrier.
        if (kt + 3 < nk) loadStage(kt + 3, (kt + 3) & 3);
        else CPA_COMMIT();
        int ss = kt & 3;
        uint32_t Au = sb + ss * STAGE_BYTES;
        uint32_t Bu = Au + 16384;
        #pragma unroll
        for (int j = 0; j < 4; j++) {
            uint32_t af[4][4];
            #pragma unroll
            for (int mf = 0; mf < 4; mf++) {
                int r = arow[mf];
                ldsm4(af[mf], Au + r * 128 + (((j * 2 + akc) ^ (r & 7)) << 4));
            }
            uint32_t bf[2][4];
            #pragma unroll
            for (int pr = 0; pr < 2; pr++) {
                int r = wn * 32 + pr * 16 + arl;
                ldsm4(bf[pr], Bu + r * 128 + (((j * 2 + akc) ^ (r & 7)) << 4));
            }
            #pragma unroll
            for (int mf = 0; mf < 4; mf++) {
                mma2(acc[mf][0], af[mf], bf[0][0], bf[0][2]);
                mma2(acc[mf][1], af[mf], bf[0][1], bf[0][3]);
                mma2(acc[mf][2], af[mf], bf[1][0], bf[1][2]);
                mma2(acc[mf][3], af[mf], bf[1][1], bf[1][3]);
            }
        }
    }

    const int quad = lane >> 2, tq = lane & 3;
    #pragma unroll
    for (int mf = 0; mf < 4; mf++) {
        #pragma unroll
        for (int nf = 0; nf < 4; nf++) {
            int m = m0 + wm * 64 + mf * 16 + quad;
            int n = n0 + wn * 32 + nf * 8 + tq * 2;
            const float* c = acc[mf][nf];
            float b0 = bias[n], b1 = bias[n + 1];
            if (EPI == EPI_W1) {
                float v0 = gelu_f(c[0] + b0), v1 = gelu_f(c[1] + b1);
                put_cat2(Cb + (size_t)m * (2 * HIDN) + n, HIDN, v0, v1);
                v0 = gelu_f(c[2] + b0); v1 = gelu_f(c[3] + b1);
                put_cat2(Cb + (size_t)(m + 8) * (2 * HIDN) + n, HIDN, v0, v1);
            } else {
                float2 v = make_float2(c[0] + b0, c[1] + b1);
                float2 w = make_float2(c[2] + b0, c[3] + b1);
                if (EPI == EPI_WO) {
                    float2 r1 = *(const float2*)&res[(size_t)m * Nstr + n];
                    float2 r2 = *(const float2*)&res[(size_t)(m + 8) * Nstr + n];
                    v.x += r1.x; v.y += r1.y;
                    w.x += r2.x; w.y += r2.y;
                }
                if (EPI == EPI_QKV && n >= 2048) {
                    // V columns: write split bf16 directly to attention layout
                    int h = (n - 2048) >> 6, cc = (n - 2048) & 63;
                    int b_ = m >> 11, s = m & (SEQ - 1);
                    __nv_bfloat16* D = g_vs + ((size_t)(b_ * NH + h) * SEQ + s) * 128;
                    put_cat2(D + cc, 64, v.x, v.y);
                    int b2_ = (m + 8) >> 11, s2 = (m + 8) & (SEQ - 1);
                    __nv_bfloat16* D2 = g_vs + ((size_t)(b2_ * NH + h) * SEQ + s2) * 128;
                    put_cat2(D2 + cc, 64, w.x, w.y);
                } else {
                    *(float2*)&Cf[(size_t)m * Nstr + n] = v;
                    *(float2*)&Cf[(size_t)(m + 8) * Nstr + n] = w;
                }
            }
        }
    }
}

// ---------------- RoPE + bf16 split of q,k into attention layout ----------------
__global__ void rope3_kernel(const float* __restrict__ cosT, const float* __restrict__ sinT) {
    int idx = blockIdx.x * blockDim.x + threadIdx.x;
    if (idx >= 2 * TKN * NH * 32) return;
    int i = idx & 31;
    int h = (idx >> 5) & 15;
    int t = (idx >> 9) & 4095;
    int qk = idx >> 21;   // 0=q, 1=k
    int s = t & (SEQ - 1);
    int b = t >> 11;
    size_t src = (size_t)t * 3072 + (size_t)qk * 1024 + h * 64;
    float a = g_qkv[src + i];
    float c = g_qkv[src + i + 32];
    float c0 = cosT[s * 64 + i], s0 = sinT[s * 64 + i];
    float c1 = cosT[s * 64 + i + 32], s1 = sinT[s * 64 + i + 32];
    float na = a * c0 - c * s0;
    float nc = c * c1 + a * s1;
    __nv_bfloat16 ah, al, ch, cl;
    split1(na, ah, al);
    split1(nc, ch, cl);
    __nv_bfloat16* D = (qk == 0 ? g_qs : g_ks) + ((size_t)(b * NH + h) * SEQ + s) * 128;
    D[i] = ah;
    D[32 + i] = ch;
    D[64 + i] = al;
    D[96 + i] = cl;
}

// ---------------- HMMA flash attention, pre-split bf16, cp.async double-buffered K/V ----------------
#define FSMEM 98304
__global__ __launch_bounds__(256, 2) void flash3_kernel() {
    extern __shared__ __align__(1024) char fsm[];
    const uint32_t Qu = smem_u32(fsm);
    const int b = blockIdx.z, h = blockIdx.y, q0 = blockIdx.x * 128;
    const int tid = threadIdx.x, lane = tid & 31, w = tid >> 5;
    const int arl = lane & 15, akc = lane >> 4;
    const int tq = lane & 3, quad = lane >> 2;
    const __nv_bfloat16* qsrc = g_qs + (size_t)(b * NH + h) * SEQ * 128;
    const __nv_bfloat16* ksrc = g_ks + (size_t)(b * NH + h) * SEQ * 128;
    const __nv_bfloat16* vsrc = g_vs + (size_t)(b * NH + h) * SEQ * 128;

    #pragma unroll
    for (int i = 0; i < 8; i++) {
        int id = tid + i * 256;
        int r = id >> 4, ch = id & 15;
        cpa16(Qu + r * 256 + ((ch ^ (r & 7)) << 4), qsrc + (size_t)(q0 + r) * 128 + ch * 8);
    }
    auto loadKV = [&](int kt, int st) {
        uint32_t Ks = Qu + 32768 + st * 32768;
        #pragma unroll
        for (int i = 0; i < 4; i++) {
            int id = tid + i * 256;
            int r = id >> 4, ch = id & 15;
            cpa16(Ks + r * 256 + ((ch ^ (r & 7)) << 4), ksrc + (size_t)(kt * 64 + r) * 128 + ch * 8);
        }
        uint32_t Vs = Ks + 16384;
        #pragma unroll
        for (int i = 0; i < 4; i++) {
            int id = tid + i * 256;
            int r = id >> 4, ch = id & 15;
            cpa16(Vs + r * 256 + ((ch ^ (r & 7)) << 4), vsrc + (size_t)(kt * 64 + r) * 128 + ch * 8);
        }
        CPA_COMMIT();
    };
    loadKV(0, 0);
    loadKV(1, 1);

    float accO[8][4];
    #pragma unroll
    for (int nf = 0; nf < 8; nf++)
        #pragma unroll
        for (int i = 0; i < 4; i++) accO[nf][i] = 0.f;
    float m0 = -1e30f, m1 = -1e30f, l0 = 0.f, l1 = 0.f;
    const int qr = w * 16 + arl;

    for (int kt = 0; kt < SEQ / 64; kt++) {
        int st = kt & 1;
        CPA_WAIT1();
        __syncthreads();
        uint32_t Ku = Qu + 32768 + st * 32768;
        uint32_t Vu = Ku + 16384;

        float accS[8][4];
        #pragma unroll
        for (int nf = 0; nf < 8; nf++)
            #pragma unroll
            for (int i = 0; i < 4; i++) accS[nf][i] = 0.f;
        #pragma unroll
        for (int j = 0; j < 4; j++) {
            uint32_t ah[4], al[4];
            ldsm4(ah, Qu + qr * 256 + (((j * 2 + akc) ^ (qr & 7)) << 4));
            ldsm4(al, Qu + qr * 256 + (((8 + j * 2 + akc) ^ (qr & 7)) << 4));
            #pragma unroll
            for (int pr = 0; pr < 4; pr++) {
                int kr = pr * 16 + arl;
                uint32_t bh[4], bl[4];
                ldsm4(bh, Ku + kr * 256 + (((j * 2 + akc) ^ (kr & 7)) << 4));
                ldsm4(bl, Ku + kr * 256 + (((8 + j * 2 + akc) ^ (kr & 7)) << 4));
                mma2(accS[2 * pr], ah, bh[0], bh[2]);
                mma2(accS[2 * pr], al, bh[0], bh[2]);
                mma2(accS[2 * pr], ah, bl[0], bl[2]);
                mma2(accS[2 * pr + 1], ah, bh[1], bh[3]);
                mma2(accS[2 * pr + 1], al, bh[1], bh[3]);
                mma2(accS[2 * pr + 1], ah, bl[1], bl[3]);
            }
        }
        float mt0 = m0, mt1 = m1;
        #pragma unroll
        for (int nf = 0; nf < 8; nf++) {
            #pragma unroll
            for (int i = 0; i < 4; i++) accS[nf][i] *= 0.125f;
            mt0 = fmaxf(mt0, fmaxf(accS[nf][0], accS[nf][1]));
            mt1 = fmaxf(mt1, fmaxf(accS[nf][2], accS[nf][3]));
        }
        #pragma unroll
        for (int o = 1; o <= 2; o <<= 1) {
            mt0 = fmaxf(mt0, __shfl_xor_sync(0xffffffffu, mt0, o));
            mt1 = fmaxf(mt1, __shfl_xor_sync(0xffffffffu, mt1, o));
        }
        float c0 = __expf(m0 - mt0), c1 = __expf(m1 - mt1);
        m0 = mt0; m1 = mt1;
        l0 *= c0; l1 *= c1;
        #pragma unroll
        for (int nf = 0; nf < 8; nf++) {
            accO[nf][0] *= c0; accO[nf][1] *= c0;
            accO[nf][2] *= c1; accO[nf][3] *= c1;
        }
        uint32_t ph[8][2], pl[8][2];
        #pragma unroll
        for (int nf = 0; nf < 8; nf++) {
            float p0 = __expf(accS[nf][0] - mt0);
            float p1 = __expf(accS[nf][1] - mt0);
            float p2 = __expf(accS[nf][2] - mt1);
            float p3 = __expf(accS[nf][3] - mt1);
            l0 += p0 + p1; l1 += p2 + p3;
            __nv_bfloat16 h0, e0, h1, e1, h2, e2, h3, e3;
            split1(p0, h0, e0); split1(p1, h1, e1);
            split1(p2, h2, e2); split1(p3, h3, e3);
            ph[nf][0] = packbf(h0, h1);
            ph[nf][1] = packbf(h2, h3);
            pl[nf][0] = packbf(e0, e1);
            pl[nf][1] = packbf(e2, e3);
        }
        #pragma unroll
        for (int kf = 0; kf < 4; kf++) {
            uint32_t pah[4] = {ph[2 * kf][0], ph[2 * kf][1], ph[2 * kf + 1][0], ph[2 * kf + 1][1]};
            uint32_t pal[4] = {pl[2 * kf][0], pl[2 * kf][1], pl[2 * kf + 1][0], pl[2 * kf + 1][1]};
            int vr = kf * 16 + arl;
            #pragma unroll
            for (int dp = 0; dp < 4; dp++) {
                uint32_t vh[4], vl[4];
                ldsm4t(vh, Vu + vr * 256 + (((dp * 2 + akc) ^ (vr & 7)) << 4));
                ldsm4t(vl, Vu + vr * 256 + (((8 + dp * 2 + akc) ^ (vr & 7)) << 4));
                mma2(accO[2 * dp], pah, vh[0], vh[1]);
                mma2(accO[2 * dp], pal, vh[0], vh[1]);
                mma2(accO[2 * dp], pah, vl[0], vl[1]);
                mma2(accO[2 * dp + 1], pah, vh[2], vh[3]);
                mma2(accO[2 * dp + 1], pal, vh[2], vh[3]);
                mma2(accO[2 * dp + 1], pah, vl[2], vl[3]);
            }
        }
        __syncthreads();
        if (kt + 2 < SEQ / 64) loadKV(kt + 2, st);
        else CPA_COMMIT();
    }
    #pragma unroll
    for (int o = 1; o <= 2; o <<= 1) {
        l0 += __shfl_xor_sync(0xffffffffu, l0, o);
        l1 += __shfl_xor_sync(0xffffffffu, l1, o);
    }
    float i0 = 1.f / l0, i1 = 1.f / l1;
    int r0 = q0 + w * 16 + quad;
    #pragma unroll
    for (int nf = 0; nf < 8; nf++) {
        int col = h * 64 + nf * 8 + tq * 2;
        put_cat2(g_ocat + (size_t)(b * SEQ + r0) * 2048 + col, DIM,
                 accO[nf][0] * i0, accO[nf][1] * i0);
        put_cat2(g_ocat + (size_t)(b * SEQ + r0 + 8) * 2048 + col, DIM,
                 accO[nf][2] * i1, accO[nf][3] * i1);
    }
}

// ---------------- gating ----------------
__global__ __launch_bounds__(128) void gate_kernel(const float* __restrict__ gate_w) {
    int t = blockIdx.x * 4 + (threadIdx.x >> 5);
    int lane = threadIdx.x & 31;
    const float* xr = g_h2 + (size_t)t * DIM;
    float p[8];
    #pragma unroll
    for (int e = 0; e < 8; e++) p[e] = 0.f;
    for (int it = 0; it < 32; it++) {
        int d = it * 32 + lane;
        float xv = xr[d];
        const float4* gw = (const float4*)(gate_w + d * 8);
        float4 g0 = gw[0], g1 = gw[1];
        p[0] += xv * g0.x; p[1] += xv * g0.y; p[2] += xv * g0.z; p[3] += xv * g0.w;
        p[4] += xv * g1.x; p[5] += xv * g1.y; p[6] += xv * g1.z; p[7] += xv * g1.w;
    }
    #pragma unroll
    for (int e = 0; e < 8; e++)
        #pragma unroll
        for (int o = 16; o; o >>= 1) p[e] += __shfl_xor_sync(0xffffffffu, p[e], o);
    if (lane == 0) {
        float mx = p[0];
        #pragma unroll
        for (int e = 1; e < 8; e++) mx = fmaxf(mx, p[e]);
        float ex[8], sum = 0.f;
        #pragma unroll
        for (int e = 0; e < 8; e++) { ex[e] = __expf(p[e] - mx); sum += ex[e]; }
        float inv = 1.f / sum;
        float pr[8];
        #pragma unroll
        for (int e = 0; e < 8; e++) { pr[e] = ex[e] * inv; g_probs[t * 8 + e] = pr[e]; }
        int i1 = 0;
        float v1 = pr[0];
        #pragma unroll
        for (int e = 1; e < 8; e++) if (pr[e] > v1) { v1 = pr[e]; i1 = e; }
        int i2 = -1;
        float v2 = -1.f;
        #pragma unroll
        for (int e = 0; e < 8; e++) if (e != i1 && pr[e] > v2) { v2 = pr[e]; i2 = e; }
        float dn = 1.f / (v1 + v2);
        g_eid[t] = i1;
        g_eid[TKN + t] = i2;
        g_wflat[t] = v1 * dn;
        g_wflat[TKN + t] = v2 * dn;
    }
}

// ---------------- per-expert positions + counts ----------------
__global__ void pos_kernel() {
    int e = threadIdx.x >> 5;
    int lane = threadIdx.x & 31;
    int base = 0;
    for (int a0 = 0; a0 < NA; a0 += 32) {
        int ea = g_eid[a0 + lane];
        unsigned mask = __ballot_sync(0xffffffffu, ea == e);
        if (ea == e) g_pos[a0 + lane] = base + __popc(mask & ((1u << lane) - 1));
        base += __popc(mask);
    }
    if (lane == 0) g_cnt[e] = base;
}

// ---------------- scatter tokens (split bf16) into capacity buffer ----------------
__global__ __launch_bounds__(256) void scatter_kernel() {
    int a = blockIdx.x;
    int p = g_pos[a];
    if (p >= CAP) return;
    int e = g_eid[a];
    int tok = a & (TKN - 1);
    float4 v = ((const float4*)(g_h2 + (size_t)tok * DIM))[threadIdx.x];
    __nv_bfloat16* dst = g_bufcat + ((size_t)e * CAP + p) * 2048 + threadIdx.x * 4;
    put_cat2(dst, DIM, v.x, v.y);
    put_cat2(dst + 2, DIM, v.z, v.w);
}

// ---------------- aux loss ----------------
__global__ __launch_bounds__(256) void aux_kernel(float* __restrict__ out, int out_size) {
    __shared__ float red[256];
    int tid = threadIdx.x;
    float me[8], cnt[8];
    #pragma unroll
    for (int e = 0; e < 8; e++) { me[e] = 0.f; cnt[e] = 0.f; }
    for (int t = tid; t < TKN; t += 256) {
        #pragma unroll
        for (int e = 0; e < 8; e++) me[e] += g_probs[t * 8 + e];
    }
    for (int a = tid; a < NA; a += 256) cnt[g_eid[a]] += 1.f;
    float auxv = 0.f;
    for (int e = 0; e < 8; e++) {
        red[tid] = me[e];
        __syncthreads();
        for (int st = 128; st; st >>= 1) { if (tid < st) red[tid] += red[tid + st]; __syncthreads(); }
        float meS = red[0];
        __syncthreads();
        red[tid] = cnt[e];
        __syncthreads();
        for (int st = 128; st; st >>= 1) { if (tid < st) red[tid] += red[tid + st]; __syncthreads(); }
        float cS = red[0];
        __syncthreads();
        auxv += (meS / (float)TKN) * (cS / (float)NA);
    }
    if (tid == 0 && out_size > TKN * DIM) out[TKN * DIM] = 8.f * auxv;
}

// ---------------- combine ----------------
__global__ __launch_bounds__(256) void final_kernel(float* __restrict__ out) {
    int t = blockIdx.x;
    int tid = threadIdx.x;
    int p1 = g_pos[t], p2 = g_pos[TKN + t];
    int e1 = g_eid[t], e2 = g_eid[TKN + t];
    float w1 = (p1 < CAP) ? g_wflat[t] : 0.f;
    float w2 = (p2 < CAP) ? g_wflat[TKN + t] : 0.f;
    p1 = min(p1, CAP - 1);
    p2 = min(p2, CAP - 1);
    const float4* a = (const float4*)(g_oute + ((size_t)e1 * CAP + p1) * DIM);
    const float4* b = (const float4*)(g_oute + ((size_t)e2 * CAP + p2) * DIM);
    const float4* xr = (const float4*)(g_x2 + (size_t)t * DIM);
    float4 av = a[tid], bv = b[tid], xv = xr[tid];
    float4 r;
    r.x = xv.x + w1 * av.x + w2 * bv.x;
    r.y = xv.y + w1 * av.y + w2 * bv.y;
    r.z = xv.z + w1 * av.z + w2 * bv.z;
    r.w = xv.w + w1 * av.w + w2 * bv.w;
    ((float4*)(out + (size_t)t * DIM))[tid] = r;
}

// ---------------- host ----------------
extern "C" void kernel_launch(void* const* d_in, const int* in_sizes, int n_in,
                              void* d_out, int out_size) {
    const float* x     = (const float*)d_in[0];
    const float* cosT  = (const float*)d_in[1];
    const float* sinT  = (const float*)d_in[2];
    const float* ln1g  = (const float*)d_in[3];
    const float* ln1b  = (const float*)d_in[4];
    const float* ln2g  = (const float*)d_in[5];
    const float* ln2b  = (const float*)d_in[6];
    const float* wqkv  = (const float*)d_in[7];
    const float* bqkv  = (const float*)d_in[8];
    const float* wo    = (const float*)d_in[9];
    const float* bo    = (const float*)d_in[10];
    const float* gatew = (const float*)d_in[11];
    const float* w1    = (const float*)d_in[12];
    const float* b1    = (const float*)d_in[13];
    const float* w2    = (const float*)d_in[14];
    const float* b2    = (const float*)d_in[15];
    float* out = (float*)d_out;

    void *p_qkv, *p_x2, *p_h2, *p_oute, *p_cnt;
    void *p_acat, *p_ocat, *p_bufcat, *p_hhcat, *p_wqkvc, *p_woc, *p_w1c, *p_w2c;
    cudaGetSymbolAddress(&p_qkv, g_qkv);
    cudaGetSymbolAddress(&p_x2, g_x2);
    cudaGetSymbolAddress(&p_h2, g_h2);
    cudaGetSymbolAddress(&p_oute, g_oute);
    cudaGetSymbolAddress(&p_cnt, g_cnt);
    cudaGetSymbolAddress(&p_acat, g_acat);
    cudaGetSymbolAddress(&p_ocat, g_ocat);
    cudaGetSymbolAddress(&p_bufcat, g_bufcat);
    cudaGetSymbolAddress(&p_hhcat, g_hhcat);
    cudaGetSymbolAddress(&p_wqkvc, g_wqkvcat);
    cudaGetSymbolAddress(&p_woc, g_wocat);
    cudaGetSymbolAddress(&p_w1c, g_w1cat);
    cudaGetSymbolAddress(&p_w2c, g_w2cat);

    static int attr_done = 0;
    if (!attr_done) {
        cudaFuncSetAttribute(tgemm<EPI_PLAIN>, cudaFuncAttributeMaxDynamicSharedMemorySize, GSMEM);
        cudaFuncSetAttribute(tgemm<EPI_WO>, cudaFuncAttributeMaxDynamicSharedMemorySize, GSMEM);
        cudaFuncSetAttribute(tgemm<EPI_W1>, cudaFuncAttributeMaxDynamicSharedMemorySize, GSMEM);
        cudaFuncSetAttribute(tgemm<EPI_QKV>, cudaFuncAttributeMaxDynamicSharedMemorySize, GSMEM);
        cudaFuncSetAttribute(flash3_kernel, cudaFuncAttributeMaxDynamicSharedMemorySize, FSMEM);
        attr_done = 1;
    }

    wconv_kernel<<<dim3(96, 16, 1), 256>>>(wqkv, (__nv_bfloat16*)p_wqkvc, 1024, 3072, 0, 0);
    wconv_kernel<<<dim3(32, 16, 1), 256>>>(wo, (__nv_bfloat16*)p_woc, 1024, 1024, 0, 0);
    wconv_kernel<<<dim3(128, 16, 8), 256>>>(w1, (__nv_bfloat16*)p_w1c, 1024, 4096,
                                            (size_t)DIM * HID, (size_t)HID * 2048);
    wconv_kernel<<<dim3(32, 64, 8), 256>>>(w2, (__nv_bfloat16*)p_w2c, 4096, 1024,
                                           (size_t)HID * DIM, (size_t)DIM * 8192);

    // ln1 -> split bf16
    ln_kernel<true><<<TKN, 256>>>(x, ln1g, ln1b, nullptr, (__nv_bfloat16*)p_acat);
    // qkv = h @ wqkv + bqkv (V columns split directly to g_vs)
    tgemm<EPI_QKV><<<dim3(12, 32, 1), 512, GSMEM>>>(
        (const __nv_bfloat16*)p_acat, (const __nv_bfloat16*)p_wqkvc, bqkv, nullptr,
        (float*)p_qkv, nullptr, 1024, 3072, 0, 0, 0, 0, 0, nullptr);
    // rope + split q,k
    rope3_kernel<<<(2 * TKN * NH * 32) / 256, 256>>>(cosT, sinT);
    flash3_kernel<<<dim3(SEQ / 128, NH, 2), 256, FSMEM>>>();
    // x2 = o@wo + bo + x
    tgemm<EPI_WO><<<dim3(4, 32, 1), 512, GSMEM>>>(
        (const __nv_bfloat16*)p_ocat, (const __nv_bfloat16*)p_woc, bo, x,
        (float*)p_x2, nullptr, 1024, 1024, 0, 0, 0, 0, 0, nullptr);
    // ln2 -> fp32
    ln_kernel<false><<<TKN, 256>>>((const float*)p_x2, ln2g, ln2b, (float*)p_h2, nullptr);
    gate_kernel<<<TKN / 4, 128>>>(gatew);
    pos_kernel<<<1, 256>>>();
    scatter_kernel<<<NA, 256>>>();
    aux_kernel<<<1, 256>>>(out, out_size);
    // hh = gelu(buf@w1 + b1) -> split bf16 (skips tiles beyond expert count)
    tgemm<EPI_W1><<<dim3(16, 10, 8), 512, GSMEM>>>(
        (const __nv_bfloat16*)p_bufcat, (const __nv_bfloat16*)p_w1c, b1, nullptr,
        nullptr, (__nv_bfloat16*)p_hhcat, 1024, 0, HID,
        (size_t)CAP * 2048, (size_t)HID * 2048, (size_t)HID, (size_t)CAP * 8192,
        (const int*)p_cnt);
    // oute = hh@w2 + b2 (skips tiles beyond expert count)
    tgemm<EPI_PLAIN><<<dim3(4, 10, 8), 512, GSMEM>>>(
        (const __nv_bfloat16*)p_hhcat, (const __nv_bfloat16*)p_w2c, b2, nullptr,
        (float*)p_oute, nullptr, 4096, 1024, 0,
        (size_t)CAP * 8192, (size_t)DIM * 8192, (size_t)DIM, (size_t)CAP * DIM,
        (const int*)p_cnt);
    final_kernel<<<TKN, 256>>>(out);
}

// round 10
// speedup vs baseline: 3.0980x; 1.0003x over previous
#include <cuda_runtime.h>
#include <cuda_bf16.h>
#include <math.h>
#include <stdint.h>

#define TKN 4096
#define SEQ 2048
#define DIM 1024
#define NH 16
#define NE 8
#define HID 4096
#define CAP 1280
#define NA 8192

// ---------------- scratch ----------------
__device__ float g_qkv[TKN * 3 * DIM];
__device__ float g_x2[TKN * DIM];
__device__ float g_h2[TKN * DIM];
__device__ float g_probs[TKN * NE];
__device__ int   g_eid[NA];
__device__ float g_wflat[NA];
__device__ int   g_pos[NA];
__device__ int   g_cnt[NE];
__device__ float g_oute[NE * CAP * DIM];

// [hi|lo] compact split buffers (row stride = 2*K)
__device__ __nv_bfloat16 g_acat[(size_t)TKN * 2048];
__device__ __nv_bfloat16 g_ocat[(size_t)TKN * 2048];
__device__ __nv_bfloat16 g_bufcat[(size_t)NE * CAP * 2048];
__device__ __nv_bfloat16 g_hhcat[(size_t)NE * CAP * 8192];
__device__ __nv_bfloat16 g_wqkvcat[(size_t)3072 * 2048];
__device__ __nv_bfloat16 g_wocat[(size_t)1024 * 2048];
__device__ __nv_bfloat16 g_w1cat[(size_t)NE * HID * 2048];
__device__ __nv_bfloat16 g_w2cat[(size_t)NE * DIM * 8192];
// pre-split attention operands: [b*NH+h][seq][128] = hi(64) | lo(64)
__device__ __nv_bfloat16 g_qs[(size_t)2 * NH * SEQ * 128];
__device__ __nv_bfloat16 g_ks[(size_t)2 * NH * SEQ * 128];
__device__ __nv_bfloat16 g_vs[(size_t)2 * NH * SEQ * 128];

// ---------------- helpers ----------------
__device__ __forceinline__ uint32_t smem_u32(const void* p) {
    uint32_t a;
    asm("{ .reg .u64 t; cvta.to.shared.u64 t, %1; cvt.u32.u64 %0, t; }" : "=r"(a) : "l"(p));
    return a;
}
__device__ __forceinline__ void ldsm4(uint32_t* r, uint32_t a) {
    asm volatile("ldmatrix.sync.aligned.m8n8.x4.shared.b16 {%0,%1,%2,%3}, [%4];"
                 : "=r"(r[0]), "=r"(r[1]), "=r"(r[2]), "=r"(r[3]) : "r"(a));
}
__device__ __forceinline__ void ldsm4t(uint32_t* r, uint32_t a) {
    asm volatile("ldmatrix.sync.aligned.m8n8.x4.trans.shared.b16 {%0,%1,%2,%3}, [%4];"
                 : "=r"(r[0]), "=r"(r[1]), "=r"(r[2]), "=r"(r[3]) : "r"(a));
}
__device__ __forceinline__ void mma2(float* c, const uint32_t* a, uint32_t b0, uint32_t b1) {
    asm volatile(
        "mma.sync.aligned.m16n8k16.row.col.f32.bf16.bf16.f32 "
        "{%0,%1,%2,%3}, {%4,%5,%6,%7}, {%8,%9}, {%0,%1,%2,%3};"
        : "+f"(c[0]), "+f"(c[1]), "+f"(c[2]), "+f"(c[3])
        : "r"(a[0]), "r"(a[1]), "r"(a[2]), "r"(a[3]), "r"(b0), "r"(b1));
}
__device__ __forceinline__ void cpa16(uint32_t dst, const void* src) {
    asm volatile("cp.async.cg.shared.global [%0], [%1], 16;" :: "r"(dst), "l"(src));
}
#define CPA_COMMIT() asm volatile("cp.async.commit_group;")
#define CPA_WAIT2()  asm volatile("cp.async.wait_group 2;")
#define CPA_WAIT1()  asm volatile("cp.async.wait_group 1;")

__device__ __forceinline__ float gelu_f(float x) {
    float x3 = x * x * x;
    float t = tanhf(0.7978845608028654f * (x + 0.044715f * x3));
    return 0.5f * x * (1.0f + t);
}
__device__ __forceinline__ void split1(float v, __nv_bfloat16& hi, __nv_bfloat16& lo) {
    hi = __float2bfloat16(v);
    lo = __float2bfloat16(v - __bfloat162float(hi));
}
__device__ __forceinline__ uint32_t packbf(__nv_bfloat16 a, __nv_bfloat16 b) {
    return ((uint32_t)__bfloat16_as_ushort(b) << 16) | __bfloat16_as_ushort(a);
}
// write split pair into [hi | lo] layout, slabs of `stride`
__device__ __forceinline__ void put_cat2(__nv_bfloat16* p, int stride, float a, float b) {
    __nv_bfloat16 ah, al, bh, bl;
    split1(a, ah, al);
    split1(b, bh, bl);
    __nv_bfloat162 hi; hi.x = ah; hi.y = bh;
    __nv_bfloat162 lo; lo.x = al; lo.y = bl;
    *(__nv_bfloat162*)(p) = hi;
    *(__nv_bfloat162*)(p + stride) = lo;
}

// ---------------- weight transpose + split (vectorized): W[K][N] -> Wt[N][2K] = [hi|lo] ----------------
__global__ __launch_bounds__(256) void wconv_kernel(const float* __restrict__ W,
                                                    __nv_bfloat16* __restrict__ Wt,
                                                    int K, int N, size_t wOff, size_t oOff) {
    int z = blockIdx.z;
    W += wOff * z; Wt += oOff * z;
    __shared__ float t[64][33];
    int n0 = blockIdx.x * 32, k0 = blockIdx.y * 64;
    int tid = threadIdx.x;
    #pragma unroll
    for (int i = 0; i < 8; i++) {
        int id = tid + i * 256;
        int k = id >> 5, n = id & 31;
        t[k][n] = W[(size_t)(k0 + k) * N + n0 + n];
    }
    __syncthreads();
    int n = tid >> 3, kq = tid & 7;
    uint32_t hw[4], lw[4];
    #pragma unroll
    for (int j = 0; j < 4; j++) {
        float a = t[kq * 8 + 2 * j][n], b = t[kq * 8 + 2 * j + 1][n];
        __nv_bfloat16 ah, al, bh, bl;
        split1(a, ah, al);
        split1(b, bh, bl);
        hw[j] = packbf(ah, bh);
        lw[j] = packbf(al, bl);
    }
    __nv_bfloat16* p = Wt + (size_t)(n0 + n) * 2 * K + k0 + kq * 8;
    *(uint4*)p = make_uint4(hw[0], hw[1], hw[2], hw[3]);
    *(uint4*)(p + K) = make_uint4(lw[0], lw[1], lw[2], lw[3]);
}

// ---------------- layernorm ----------------
template <bool CAT>
__global__ __launch_bounds__(256) void ln_kernel(const float* __restrict__ x,
                                                 const float* __restrict__ g,
                                                 const float* __restrict__ b,
                                                 float* __restrict__ outf,
                                                 __nv_bfloat16* __restrict__ outc) {
    int row = blockIdx.x, tid = threadIdx.x;
    const float4* xr = (const float4*)(x + (size_t)row * DIM);
    float4 v = xr[tid];
    float s = v.x + v.y + v.z + v.w;
    float q = v.x * v.x + v.y * v.y + v.z * v.z + v.w * v.w;
    __shared__ float ss[8], sq[8];
    #pragma unroll
    for (int o = 16; o; o >>= 1) {
        s += __shfl_xor_sync(0xffffffffu, s, o);
        q += __shfl_xor_sync(0xffffffffu, q, o);
    }
    int w = tid >> 5;
    if ((tid & 31) == 0) { ss[w] = s; sq[w] = q; }
    __syncthreads();
    __shared__ float mu_s, rs_s;
    if (tid == 0) {
        float S = 0.f, Q = 0.f;
        #pragma unroll
        for (int i = 0; i < 8; i++) { S += ss[i]; Q += sq[i]; }
        float mu = S / DIM;
        mu_s = mu;
        rs_s = rsqrtf(Q / DIM - mu * mu + 1e-6f);
    }
    __syncthreads();
    float mu = mu_s, rs = rs_s;
    float4 gg = ((const float4*)g)[tid];
    float4 bb = ((const float4*)b)[tid];
    float4 o4;
    o4.x = (v.x - mu) * rs * gg.x + bb.x;
    o4.y = (v.y - mu) * rs * gg.y + bb.y;
    o4.z = (v.z - mu) * rs * gg.z + bb.z;
    o4.w = (v.w - mu) * rs * gg.w + bb.w;
    if (CAT) {
        __nv_bfloat16* p = outc + (size_t)row * 2048 + tid * 4;
        put_cat2(p, DIM, o4.x, o4.y);
        put_cat2(p + 2, DIM, o4.z, o4.w);
    } else {
        ((float4*)(outf + (size_t)row * DIM))[tid] = o4;
    }
}

// ---------------- HMMA GEMM: logical K' = 3K over physical [hi|lo] (2K) buffers ----------------
// 8 warps, warp tile 64x64 (2x4 warp grid), 4-stage cp.async ring, single sync per K-tile.
#define EPI_PLAIN 0
#define EPI_WO 1
#define EPI_W1 2
#define EPI_QKV 3
#define STAGE_BYTES 49152
#define GSMEM (4 * STAGE_BYTES)

template <int EPI>
__global__ __launch_bounds__(256, 1) void tgemm(
    const __nv_bfloat16* __restrict__ A, const __nv_bfloat16* __restrict__ Bt,
    const float* __restrict__ bias, const float* __restrict__ res,
    float* __restrict__ Cf, __nv_bfloat16* __restrict__ Cb,
    int Klog, int Nstr, int HIDN,
    size_t aOff, size_t bOff, size_t biasOff, size_t cOff,
    const int* __restrict__ cnt) {
    extern __shared__ __align__(1024) char smem[];
    const uint32_t sb = smem_u32(smem);
    const int tid = threadIdx.x;
    const int z = blockIdx.z;
    const int m0 = blockIdx.y * 128;
    if (cnt != nullptr && m0 >= cnt[z]) return;
    A += aOff * z; Bt += bOff * z; bias += biasOff * z;
    if (EPI == EPI_W1) Cb += cOff * z; else Cf += cOff * z;
    const int n0 = blockIdx.x * 256;
    const int nk = (3 * Klog) >> 6;
    const int Ks2 = 2 * Klog;

    auto loadStage = [&](int kt, int ss) {
        uint32_t sbase = sb + ss * STAGE_BYTES;
        int kb = kt << 6;
        int akb = kb < Ks2 ? kb : kb - Ks2;       // A logical [hi|lo|hi]
        int bkb = kb < Klog ? kb : kb - Klog;     // B logical [hi|hi|lo]
        const __nv_bfloat16* Ag = A + (size_t)m0 * Ks2 + akb;
        #pragma unroll
        for (int i = 0; i < 4; i++) {
            int id = tid + i * 256;
            int r = id >> 3, c = id & 7;
            cpa16(sbase + r * 128 + ((c ^ (r & 7)) << 4), Ag + (size_t)r * Ks2 + c * 8);
        }
        const __nv_bfloat16* Bg = Bt + (size_t)n0 * Ks2 + bkb;
        #pragma unroll
        for (int i = 0; i < 8; i++) {
            int id = tid + i * 256;
            int r = id >> 3, c = id & 7;
            cpa16(sbase + 16384 + r * 128 + ((c ^ (r & 7)) << 4), Bg + (size_t)r * Ks2 + c * 8);
        }
        CPA_COMMIT();
    };

    loadStage(0, 0);
    loadStage(1, 1);
    loadStage(2, 2);

    const int lane = tid & 31, wid = tid >> 5;
    const int wm = wid >> 2, wn = wid & 3;     // 2 x 4 warps, 64x64 tile each
    const int arl = lane & 15, akc = lane >> 4;

    int arow[4];
    #pragma unroll
    for (int mf = 0; mf < 4; mf++) arow[mf] = wm * 64 + mf * 16 + arl;

    float acc[4][8][4];
    #pragma unroll
    for (int mf = 0; mf < 4; mf++)
        #pragma unroll
        for (int nf = 0; nf < 8; nf++)
            #pragma unroll
            for (int i = 0; i < 4; i++) acc[mf][nf][i] = 0.f;

    for (int kt = 0; kt < nk; kt++) {
        CPA_WAIT2();
        __syncthreads();
        // prefetch 3 ahead into stage (kt+3)&3 == (kt-1)&3 — all threads finished
        // reading that stage before this barrier.
        if (kt + 3 < nk) loadStage(kt + 3, (kt + 3) & 3);
        else CPA_COMMIT();
        int ss = kt & 3;
        uint32_t Au = sb + ss * STAGE_BYTES;
        uint32_t Bu = Au + 16384;
        #pragma unroll
        for (int j = 0; j < 4; j++) {
            uint32_t af[4][4];
            #pragma unroll
            for (int mf = 0; mf < 4; mf++) {
                int r = arow[mf];
                ldsm4(af[mf], Au + r * 128 + (((j * 2 + akc) ^ (r & 7)) << 4));
            }
            uint32_t bf[4][4];
            #pragma unroll
            for (int pr = 0; pr < 4; pr++) {
                int r = wn * 64 + pr * 16 + arl;
                ldsm4(bf[pr], Bu + r * 128 + (((j * 2 + akc) ^ (r & 7)) << 4));
            }
            #pragma unroll
            for (int mf = 0; mf < 4; mf++)
                #pragma unroll
                for (int pr = 0; pr < 4; pr++) {
                    mma2(acc[mf][2 * pr], af[mf], bf[pr][0], bf[pr][2]);
                    mma2(acc[mf][2 * pr + 1], af[mf], bf[pr][1], bf[pr][3]);
                }
        }
    }

    const int quad = lane >> 2, tq = lane & 3;
    #pragma unroll
    for (int mf = 0; mf < 4; mf++) {
        #pragma unroll
        for (int nf = 0; nf < 8; nf++) {
            int m = m0 + wm * 64 + mf * 16 + quad;
            int n = n0 + wn * 64 + nf * 8 + tq * 2;
            const float* c = acc[mf][nf];
            float b0 = bias[n], b1 = bias[n + 1];
            if (EPI == EPI_W1) {
                float v0 = gelu_f(c[0] + b0), v1 = gelu_f(c[1] + b1);
                put_cat2(Cb + (size_t)m * (2 * HIDN) + n, HIDN, v0, v1);
                v0 = gelu_f(c[2] + b0); v1 = gelu_f(c[3] + b1);
                put_cat2(Cb + (size_t)(m + 8) * (2 * HIDN) + n, HIDN, v0, v1);
            } else {
                float2 v = make_float2(c[0] + b0, c[1] + b1);
                float2 w = make_float2(c[2] + b0, c[3] + b1);
                if (EPI == EPI_WO) {
                    float2 r1 = *(const float2*)&res[(size_t)m * Nstr + n];
                    float2 r2 = *(const float2*)&res[(size_t)(m + 8) * Nstr + n];
                    v.x += r1.x; v.y += r1.y;
                    w.x += r2.x; w.y += r2.y;
                }
                if (EPI == EPI_QKV && n >= 2048) {
                    // V columns: write split bf16 directly to attention layout
                    int h = (n - 2048) >> 6, cc = (n - 2048) & 63;
                    int b_ = m >> 11, s = m & (SEQ - 1);
                    __nv_bfloat16* D = g_vs + ((size_t)(b_ * NH + h) * SEQ + s) * 128;
                    put_cat2(D + cc, 64, v.x, v.y);
                    int b2_ = (m + 8) >> 11, s2 = (m + 8) & (SEQ - 1);
                    __nv_bfloat16* D2 = g_vs + ((size_t)(b2_ * NH + h) * SEQ + s2) * 128;
                    put_cat2(D2 + cc, 64, w.x, w.y);
                } else {
                    *(float2*)&Cf[(size_t)m * Nstr + n] = v;
                    *(float2*)&Cf[(size_t)(m + 8) * Nstr + n] = w;
                }
            }
        }
    }
}

// ---------------- RoPE + bf16 split of q,k into attention layout ----------------
__global__ void rope3_kernel(const float* __restrict__ cosT, const float* __restrict__ sinT) {
    int idx = blockIdx.x * blockDim.x + threadIdx.x;
    if (idx >= 2 * TKN * NH * 32) return;
    int i = idx & 31;
    int h = (idx >> 5) & 15;
    int t = (idx >> 9) & 4095;
    int qk = idx >> 21;   // 0=q, 1=k
    int s = t & (SEQ - 1);
    int b = t >> 11;
    size_t src = (size_t)t * 3072 + (size_t)qk * 1024 + h * 64;
    float a = g_qkv[src + i];
    float c = g_qkv[src + i + 32];
    float c0 = cosT[s * 64 + i], s0 = sinT[s * 64 + i];
    float c1 = cosT[s * 64 + i + 32], s1 = sinT[s * 64 + i + 32];
    float na = a * c0 - c * s0;
    float nc = c * c1 + a * s1;
    __nv_bfloat16 ah, al, ch, cl;
    split1(na, ah, al);
    split1(nc, ch, cl);
    __nv_bfloat16* D = (qk == 0 ? g_qs : g_ks) + ((size_t)(b * NH + h) * SEQ + s) * 128;
    D[i] = ah;
    D[32 + i] = ch;
    D[64 + i] = al;
    D[96 + i] = cl;
}

// ---------------- HMMA flash attention, pre-split bf16, cp.async double-buffered K/V ----------------
#define FSMEM 98304
__global__ __launch_bounds__(256, 2) void flash3_kernel() {
    extern __shared__ __align__(1024) char fsm[];
    const uint32_t Qu = smem_u32(fsm);
    const int b = blockIdx.z, h = blockIdx.y, q0 = blockIdx.x * 128;
    const int tid = threadIdx.x, lane = tid & 31, w = tid >> 5;
    const int arl = lane & 15, akc = lane >> 4;
    const int tq = lane & 3, quad = lane >> 2;
    const __nv_bfloat16* qsrc = g_qs + (size_t)(b * NH + h) * SEQ * 128;
    const __nv_bfloat16* ksrc = g_ks + (size_t)(b * NH + h) * SEQ * 128;
    const __nv_bfloat16* vsrc = g_vs + (size_t)(b * NH + h) * SEQ * 128;

    #pragma unroll
    for (int i = 0; i < 8; i++) {
        int id = tid + i * 256;
        int r = id >> 4, ch = id & 15;
        cpa16(Qu + r * 256 + ((ch ^ (r & 7)) << 4), qsrc + (size_t)(q0 + r) * 128 + ch * 8);
    }
    auto loadKV = [&](int kt, int st) {
        uint32_t Ks = Qu + 32768 + st * 32768;
        #pragma unroll
        for (int i = 0; i < 4; i++) {
            int id = tid + i * 256;
            int r = id >> 4, ch = id & 15;
            cpa16(Ks + r * 256 + ((ch ^ (r & 7)) << 4), ksrc + (size_t)(kt * 64 + r) * 128 + ch * 8);
        }
        uint32_t Vs = Ks + 16384;
        #pragma unroll
        for (int i = 0; i < 4; i++) {
            int id = tid + i * 256;
            int r = id >> 4, ch = id & 15;
            cpa16(Vs + r * 256 + ((ch ^ (r & 7)) << 4), vsrc + (size_t)(kt * 64 + r) * 128 + ch * 8);
        }
        CPA_COMMIT();
    };
    loadKV(0, 0);
    loadKV(1, 1);

    float accO[8][4];
    #pragma unroll
    for (int nf = 0; nf < 8; nf++)
        #pragma unroll
        for (int i = 0; i < 4; i++) accO[nf][i] = 0.f;
    float m0 = -1e30f, m1 = -1e30f, l0 = 0.f, l1 = 0.f;
    const int qr = w * 16 + arl;

    for (int kt = 0; kt < SEQ / 64; kt++) {
        int st = kt & 1;
        CPA_WAIT1();
        __syncthreads();
        uint32_t Ku = Qu + 32768 + st * 32768;
        uint32_t Vu = Ku + 16384;

        float accS[8][4];
        #pragma unroll
        for (int nf = 0; nf < 8; nf++)
            #pragma unroll
            for (int i = 0; i < 4; i++) accS[nf][i] = 0.f;
        #pragma unroll
        for (int j = 0; j < 4; j++) {
            uint32_t ah[4], al[4];
            ldsm4(ah, Qu + qr * 256 + (((j * 2 + akc) ^ (qr & 7)) << 4));
            ldsm4(al, Qu + qr * 256 + (((8 + j * 2 + akc) ^ (qr & 7)) << 4));
            #pragma unroll
            for (int pr = 0; pr < 4; pr++) {
                int kr = pr * 16 + arl;
                uint32_t bh[4], bl[4];
                ldsm4(bh, Ku + kr * 256 + (((j * 2 + akc) ^ (kr & 7)) << 4));
                ldsm4(bl, Ku + kr * 256 + (((8 + j * 2 + akc) ^ (kr & 7)) << 4));
                mma2(accS[2 * pr], ah, bh[0], bh[2]);
                mma2(accS[2 * pr], al, bh[0], bh[2]);
                mma2(accS[2 * pr], ah, bl[0], bl[2]);
                mma2(accS[2 * pr + 1], ah, bh[1], bh[3]);
                mma2(accS[2 * pr + 1], al, bh[1], bh[3]);
                mma2(accS[2 * pr + 1], ah, bl[1], bl[3]);
            }
        }
        float mt0 = m0, mt1 = m1;
        #pragma unroll
        for (int nf = 0; nf < 8; nf++) {
            #pragma unroll
            for (int i = 0; i < 4; i++) accS[nf][i] *= 0.125f;
            mt0 = fmaxf(mt0, fmaxf(accS[nf][0], accS[nf][1]));
            mt1 = fmaxf(mt1, fmaxf(accS[nf][2], accS[nf][3]));
        }
        #pragma unroll
        for (int o = 1; o <= 2; o <<= 1) {
            mt0 = fmaxf(mt0, __shfl_xor_sync(0xffffffffu, mt0, o));
            mt1 = fmaxf(mt1, __shfl_xor_sync(0xffffffffu, mt1, o));
        }
        float c0 = __expf(m0 - mt0), c1 = __expf(m1 - mt1);
        m0 = mt0; m1 = mt1;
        l0 *= c0; l1 *= c1;
        #pragma unroll
        for (int nf = 0; nf < 8; nf++) {
            accO[nf][0] *= c0; accO[nf][1] *= c0;
            accO[nf][2] *= c1; accO[nf][3] *= c1;
        }
        uint32_t ph[8][2], pl[8][2];
        #pragma unroll
        for (int nf = 0; nf < 8; nf++) {
            float p0 = __expf(accS[nf][0] - mt0);
            float p1 = __expf(accS[nf][1] - mt0);
            float p2 = __expf(accS[nf][2] - mt1);
            float p3 = __expf(accS[nf][3] - mt1);
            l0 += p0 + p1; l1 += p2 + p3;
            __nv_bfloat16 h0, e0, h1, e1, h2, e2, h3, e3;
            split1(p0, h0, e0); split1(p1, h1, e1);
            split1(p2, h2, e2); split1(p3, h3, e3);
            ph[nf][0] = packbf(h0, h1);
            ph[nf][1] = packbf(h2, h3);
            pl[nf][0] = packbf(e0, e1);
            pl[nf][1] = packbf(e2, e3);
        }
        #pragma unroll
        for (int kf = 0; kf < 4; kf++) {
            uint32_t pah[4] = {ph[2 * kf][0], ph[2 * kf][1], ph[2 * kf + 1][0], ph[2 * kf + 1][1]};
            uint32_t pal[4] = {pl[2 * kf][0], pl[2 * kf][1], pl[2 * kf + 1][0], pl[2 * kf + 1][1]};
            int vr = kf * 16 + arl;
            #pragma unroll
            for (int dp = 0; dp < 4; dp++) {
                uint32_t vh[4], vl[4];
                ldsm4t(vh, Vu + vr * 256 + (((dp * 2 + akc) ^ (vr & 7)) << 4));
                ldsm4t(vl, Vu + vr * 256 + (((8 + dp * 2 + akc) ^ (vr & 7)) << 4));
                mma2(accO[2 * dp], pah, vh[0], vh[1]);
                mma2(accO[2 * dp], pal, vh[0], vh[1]);
                mma2(accO[2 * dp], pah, vl[0], vl[1]);
                mma2(accO[2 * dp + 1], pah, vh[2], vh[3]);
                mma2(accO[2 * dp + 1], pal, vh[2], vh[3]);
                mma2(accO[2 * dp + 1], pah, vl[2], vl[3]);
            }
        }
        __syncthreads();
        if (kt + 2 < SEQ / 64) loadKV(kt + 2, st);
        else CPA_COMMIT();
    }
    #pragma unroll
    for (int o = 1; o <= 2; o <<= 1) {
        l0 += __shfl_xor_sync(0xffffffffu, l0, o);
        l1 += __shfl_xor_sync(0xffffffffu, l1, o);
    }
    float i0 = 1.f / l0, i1 = 1.f / l1;
    int r0 = q0 + w * 16 + quad;
    #pragma unroll
    for (int nf = 0; nf < 8; nf++) {
        int col = h * 64 + nf * 8 + tq * 2;
        put_cat2(g_ocat + (size_t)(b * SEQ + r0) * 2048 + col, DIM,
                 accO[nf][0] * i0, accO[nf][1] * i0);
        put_cat2(g_ocat + (size_t)(b * SEQ + r0 + 8) * 2048 + col, DIM,
                 accO[nf][2] * i1, accO[nf][3] * i1);
    }
}

// ---------------- gating ----------------
__global__ __launch_bounds__(128) void gate_kernel(const float* __restrict__ gate_w) {
    int t = blockIdx.x * 4 + (threadIdx.x >> 5);
    int lane = threadIdx.x & 31;
    const float* xr = g_h2 + (size_t)t * DIM;
    float p[8];
    #pragma unroll
    for (int e = 0; e < 8; e++) p[e] = 0.f;
    for (int it = 0; it < 32; it++) {
        int d = it * 32 + lane;
        float xv = xr[d];
        const float4* gw = (const float4*)(gate_w + d * 8);
        float4 g0 = gw[0], g1 = gw[1];
        p[0] += xv * g0.x; p[1] += xv * g0.y; p[2] += xv * g0.z; p[3] += xv * g0.w;
        p[4] += xv * g1.x; p[5] += xv * g1.y; p[6] += xv * g1.z; p[7] += xv * g1.w;
    }
    #pragma unroll
    for (int e = 0; e < 8; e++)
        #pragma unroll
        for (int o = 16; o; o >>= 1) p[e] += __shfl_xor_sync(0xffffffffu, p[e], o);
    if (lane == 0) {
        float mx = p[0];
        #pragma unroll
        for (int e = 1; e < 8; e++) mx = fmaxf(mx, p[e]);
        float ex[8], sum = 0.f;
        #pragma unroll
        for (int e = 0; e < 8; e++) { ex[e] = __expf(p[e] - mx); sum += ex[e]; }
        float inv = 1.f / sum;
        float pr[8];
        #pragma unroll
        for (int e = 0; e < 8; e++) { pr[e] = ex[e] * inv; g_probs[t * 8 + e] = pr[e]; }
        int i1 = 0;
        float v1 = pr[0];
        #pragma unroll
        for (int e = 1; e < 8; e++) if (pr[e] > v1) { v1 = pr[e]; i1 = e; }
        int i2 = -1;
        float v2 = -1.f;
        #pragma unroll
        for (int e = 0; e < 8; e++) if (e != i1 && pr[e] > v2) { v2 = pr[e]; i2 = e; }
        float dn = 1.f / (v1 + v2);
        g_eid[t] = i1;
        g_eid[TKN + t] = i2;
        g_wflat[t] = v1 * dn;
        g_wflat[TKN + t] = v2 * dn;
    }
}

// ---------------- per-expert positions + counts ----------------
__global__ void pos_kernel() {
    int e = threadIdx.x >> 5;
    int lane = threadIdx.x & 31;
    int base = 0;
    for (int a0 = 0; a0 < NA; a0 += 32) {
        int ea = g_eid[a0 + lane];
        unsigned mask = __ballot_sync(0xffffffffu, ea == e);
        if (ea == e) g_pos[a0 + lane] = base + __popc(mask & ((1u << lane) - 1));
        base += __popc(mask);
    }
    if (lane == 0) g_cnt[e] = base;
}

// ---------------- scatter tokens (split bf16) into capacity buffer ----------------
__global__ __launch_bounds__(256) void scatter_kernel() {
    int a = blockIdx.x;
    int p = g_pos[a];
    if (p >= CAP) return;
    int e = g_eid[a];
    int tok = a & (TKN - 1);
    float4 v = ((const float4*)(g_h2 + (size_t)tok * DIM))[threadIdx.x];
    __nv_bfloat16* dst = g_bufcat + ((size_t)e * CAP + p) * 2048 + threadIdx.x * 4;
    put_cat2(dst, DIM, v.x, v.y);
    put_cat2(dst + 2, DIM, v.z, v.w);
}

// ---------------- aux loss ----------------
__global__ __launch_bounds__(256) void aux_kernel(float* __restrict__ out, int out_size) {
    __shared__ float red[256];
    int tid = threadIdx.x;
    float me[8], cnt[8];
    #pragma unroll
    for (int e = 0; e < 8; e++) { me[e] = 0.f; cnt[e] = 0.f; }
    for (int t = tid; t < TKN; t += 256) {
        #pragma unroll
        for (int e = 0; e < 8; e++) me[e] += g_probs[t * 8 + e];
    }
    for (int a = tid; a < NA; a += 256) cnt[g_eid[a]] += 1.f;
    float auxv = 0.f;
    for (int e = 0; e < 8; e++) {
        red[tid] = me[e];
        __syncthreads();
        for (int st = 128; st; st >>= 1) { if (tid < st) red[tid] += red[tid + st]; __syncthreads(); }
        float meS = red[0];
        __syncthreads();
        red[tid] = cnt[e];
        __syncthreads();
        for (int st = 128; st; st >>= 1) { if (tid < st) red[tid] += red[tid + st]; __syncthreads(); }
        float cS = red[0];
        __syncthreads();
        auxv += (meS / (float)TKN) * (cS / (float)NA);
    }
    if (tid == 0 && out_size > TKN * DIM) out[TKN * DIM] = 8.f * auxv;
}

// ---------------- combine ----------------
__global__ __launch_bounds__(256) void final_kernel(float* __restrict__ out) {
    int t = blockIdx.x;
    int tid = threadIdx.x;
    int p1 = g_pos[t], p2 = g_pos[TKN + t];
    int e1 = g_eid[t], e2 = g_eid[TKN + t];
    float w1 = (p1 < CAP) ? g_wflat[t] : 0.f;
    float w2 = (p2 < CAP) ? g_wflat[TKN + t] : 0.f;
    p1 = min(p1, CAP - 1);
    p2 = min(p2, CAP - 1);
    const float4* a = (const float4*)(g_oute + ((size_t)e1 * CAP + p1) * DIM);
    const float4* b = (const float4*)(g_oute + ((size_t)e2 * CAP + p2) * DIM);
    const float4* xr = (const float4*)(g_x2 + (size_t)t * DIM);
    float4 av = a[tid], bv = b[tid], xv = xr[tid];
    float4 r;
    r.x = xv.x + w1 * av.x + w2 * bv.x;
    r.y = xv.y + w1 * av.y + w2 * bv.y;
    r.z = xv.z + w1 * av.z + w2 * bv.z;
    r.w = xv.w + w1 * av.w + w2 * bv.w;
    ((float4*)(out + (size_t)t * DIM))[tid] = r;
}

// ---------------- host ----------------
extern "C" void kernel_launch(void* const* d_in, const int* in_sizes, int n_in,
                              void* d_out, int out_size) {
    const float* x     = (const float*)d_in[0];
    const float* cosT  = (const float*)d_in[1];
    const float* sinT  = (const float*)d_in[2];
    const float* ln1g  = (const float*)d_in[3];
    const float* ln1b  = (const float*)d_in[4];
    const float* ln2g  = (const float*)d_in[5];
    const float* ln2b  = (const float*)d_in[6];
    const float* wqkv  = (const float*)d_in[7];
    const float* bqkv  = (const float*)d_in[8];
    const float* wo    = (const float*)d_in[9];
    const float* bo    = (const float*)d_in[10];
    const float* gatew = (const float*)d_in[11];
    const float* w1    = (const float*)d_in[12];
    const float* b1    = (const float*)d_in[13];
    const float* w2    = (const float*)d_in[14];
    const float* b2    = (const float*)d_in[15];
    float* out = (float*)d_out;

    void *p_qkv, *p_x2, *p_h2, *p_oute, *p_cnt;
    void *p_acat, *p_ocat, *p_bufcat, *p_hhcat, *p_wqkvc, *p_woc, *p_w1c, *p_w2c;
    cudaGetSymbolAddress(&p_qkv, g_qkv);
    cudaGetSymbolAddress(&p_x2, g_x2);
    cudaGetSymbolAddress(&p_h2, g_h2);
    cudaGetSymbolAddress(&p_oute, g_oute);
    cudaGetSymbolAddress(&p_cnt, g_cnt);
    cudaGetSymbolAddress(&p_acat, g_acat);
    cudaGetSymbolAddress(&p_ocat, g_ocat);
    cudaGetSymbolAddress(&p_bufcat, g_bufcat);
    cudaGetSymbolAddress(&p_hhcat, g_hhcat);
    cudaGetSymbolAddress(&p_wqkvc, g_wqkvcat);
    cudaGetSymbolAddress(&p_woc, g_wocat);
    cudaGetSymbolAddress(&p_w1c, g_w1cat);
    cudaGetSymbolAddress(&p_w2c, g_w2cat);

    static int attr_done = 0;
    if (!attr_done) {
        cudaFuncSetAttribute(tgemm<EPI_PLAIN>, cudaFuncAttributeMaxDynamicSharedMemorySize, GSMEM);
        cudaFuncSetAttribute(tgemm<EPI_WO>, cudaFuncAttributeMaxDynamicSharedMemorySize, GSMEM);
        cudaFuncSetAttribute(tgemm<EPI_W1>, cudaFuncAttributeMaxDynamicSharedMemorySize, GSMEM);
        cudaFuncSetAttribute(tgemm<EPI_QKV>, cudaFuncAttributeMaxDynamicSharedMemorySize, GSMEM);
        cudaFuncSetAttribute(flash3_kernel, cudaFuncAttributeMaxDynamicSharedMemorySize, FSMEM);
        attr_done = 1;
    }

    wconv_kernel<<<dim3(96, 16, 1), 256>>>(wqkv, (__nv_bfloat16*)p_wqkvc, 1024, 3072, 0, 0);
    wconv_kernel<<<dim3(32, 16, 1), 256>>>(wo, (__nv_bfloat16*)p_woc, 1024, 1024, 0, 0);
    wconv_kernel<<<dim3(128, 16, 8), 256>>>(w1, (__nv_bfloat16*)p_w1c, 1024, 4096,
                                            (size_t)DIM * HID, (size_t)HID * 2048);
    wconv_kernel<<<dim3(32, 64, 8), 256>>>(w2, (__nv_bfloat16*)p_w2c, 4096, 1024,
                                           (size_t)HID * DIM, (size_t)DIM * 8192);

    // ln1 -> split bf16
    ln_kernel<true><<<TKN, 256>>>(x, ln1g, ln1b, nullptr, (__nv_bfloat16*)p_acat);
    // qkv = h @ wqkv + bqkv (V columns split directly to g_vs)
    tgemm<EPI_QKV><<<dim3(12, 32, 1), 256, GSMEM>>>(
        (const __nv_bfloat16*)p_acat, (const __nv_bfloat16*)p_wqkvc, bqkv, nullptr,
        (float*)p_qkv, nullptr, 1024, 3072, 0, 0, 0, 0, 0, nullptr);
    // rope + split q,k
    rope3_kernel<<<(2 * TKN * NH * 32) / 256, 256>>>(cosT, sinT);
    flash3_kernel<<<dim3(SEQ / 128, NH, 2), 256, FSMEM>>>();
    // x2 = o@wo + bo + x
    tgemm<EPI_WO><<<dim3(4, 32, 1), 256, GSMEM>>>(
        (const __nv_bfloat16*)p_ocat, (const __nv_bfloat16*)p_woc, bo, x,
        (float*)p_x2, nullptr, 1024, 1024, 0, 0, 0, 0, 0, nullptr);
    // ln2 -> fp32
    ln_kernel<false><<<TKN, 256>>>((const float*)p_x2, ln2g, ln2b, (float*)p_h2, nullptr);
    gate_kernel<<<TKN / 4, 128>>>(gatew);
    pos_kernel<<<1, 256>>>();
    scatter_kernel<<<NA, 256>>>();
    aux_kernel<<<1, 256>>>(out, out_size);
    // hh = gelu(buf@w1 + b1) -> split bf16 (skips tiles beyond expert count)
    tgemm<EPI_W1><<<dim3(16, 10, 8), 256, GSMEM>>>(
        (const __nv_bfloat16*)p_bufcat, (const __nv_bfloat16*)p_w1c, b1, nullptr,
        nullptr, (__nv_bfloat16*)p_hhcat, 1024, 0, HID,
        (size_t)CAP * 2048, (size_t)HID * 2048, (size_t)HID, (size_t)CAP * 8192,
        (const int*)p_cnt);
    // oute = hh@w2 + b2 (skips tiles beyond expert count)
    tgemm<EPI_PLAIN><<<dim3(4, 10, 8), 256, GSMEM>>>(
        (const __nv_bfloat16*)p_hhcat, (const __nv_bfloat16*)p_w2c, b2, nullptr,
        (float*)p_oute, nullptr, 4096, 1024, 0,
        (size_t)CAP * 8192, (size_t)DIM * 8192, (size_t)DIM, (size_t)CAP * DIM,
        (const int*)p_cnt);
    final_kernel<<<TKN, 256>>>(out);
}

// round 12
// speedup vs baseline: 3.1213x; 1.0075x over previous
#include <cuda_runtime.h>
#include <cuda_bf16.h>
#include <math.h>
#include <stdint.h>

#define TKN 4096
#define SEQ 2048
#define DIM 1024
#define NH 16
#define NE 8
#define HID 4096
#define CAP 1280
#define NA 8192

// ---------------- scratch ----------------
__device__ float g_qkv[TKN * 3 * DIM];
__device__ float g_x2[TKN * DIM];
__device__ float g_h2[TKN * DIM];
__device__ float g_probs[TKN * NE];
__device__ int   g_eid[NA];
__device__ float g_wflat[NA];
__device__ int   g_pos[NA];
__device__ int   g_cnt[NE];
__device__ float g_oute[NE * CAP * DIM];

// [hi|lo] compact split buffers (row stride = 2*K)
__device__ __nv_bfloat16 g_acat[(size_t)TKN * 2048];
__device__ __nv_bfloat16 g_ocat[(size_t)TKN * 2048];
__device__ __nv_bfloat16 g_bufcat[(size_t)NE * CAP * 2048];
__device__ __nv_bfloat16 g_hhcat[(size_t)NE * CAP * 8192];
__device__ __nv_bfloat16 g_wqkvcat[(size_t)3072 * 2048];
__device__ __nv_bfloat16 g_wocat[(size_t)1024 * 2048];
__device__ __nv_bfloat16 g_w1cat[(size_t)NE * HID * 2048];
__device__ __nv_bfloat16 g_w2cat[(size_t)NE * DIM * 8192];
// pre-split attention operands: [b*NH+h][seq][128] = hi(64) | lo(64)
__device__ __nv_bfloat16 g_qs[(size_t)2 * NH * SEQ * 128];
__device__ __nv_bfloat16 g_ks[(size_t)2 * NH * SEQ * 128];
__device__ __nv_bfloat16 g_vs[(size_t)2 * NH * SEQ * 128];

// ---------------- helpers ----------------
__device__ __forceinline__ uint32_t smem_u32(const void* p) {
    uint32_t a;
    asm("{ .reg .u64 t; cvta.to.shared.u64 t, %1; cvt.u32.u64 %0, t; }" : "=r"(a) : "l"(p));
    return a;
}
__device__ __forceinline__ void ldsm4(uint32_t* r, uint32_t a) {
    asm volatile("ldmatrix.sync.aligned.m8n8.x4.shared.b16 {%0,%1,%2,%3}, [%4];"
                 : "=r"(r[0]), "=r"(r[1]), "=r"(r[2]), "=r"(r[3]) : "r"(a));
}
__device__ __forceinline__ void ldsm4t(uint32_t* r, uint32_t a) {
    asm volatile("ldmatrix.sync.aligned.m8n8.x4.trans.shared.b16 {%0,%1,%2,%3}, [%4];"
                 : "=r"(r[0]), "=r"(r[1]), "=r"(r[2]), "=r"(r[3]) : "r"(a));
}
__device__ __forceinline__ void mma2(float* c, const uint32_t* a, uint32_t b0, uint32_t b1) {
    asm volatile(
        "mma.sync.aligned.m16n8k16.row.col.f32.bf16.bf16.f32 "
        "{%0,%1,%2,%3}, {%4,%5,%6,%7}, {%8,%9}, {%0,%1,%2,%3};"
        : "+f"(c[0]), "+f"(c[1]), "+f"(c[2]), "+f"(c[3])
        : "r"(a[0]), "r"(a[1]), "r"(a[2]), "r"(a[3]), "r"(b0), "r"(b1));
}
__device__ __forceinline__ void cpa16(uint32_t dst, const void* src) {
    asm volatile("cp.async.cg.shared.global [%0], [%1], 16;" :: "r"(dst), "l"(src));
}
#define CPA_COMMIT() asm volatile("cp.async.commit_group;")
#define CPA_WAIT2()  asm volatile("cp.async.wait_group 2;")
#define CPA_WAIT1()  asm volatile("cp.async.wait_group 1;")

__device__ __forceinline__ float gelu_f(float x) {
    float x3 = x * x * x;
    float t = tanhf(0.7978845608028654f * (x + 0.044715f * x3));
    return 0.5f * x * (1.0f + t);
}
__device__ __forceinline__ void split1(float v, __nv_bfloat16& hi, __nv_bfloat16& lo) {
    hi = __float2bfloat16(v);
    lo = __float2bfloat16(v - __bfloat162float(hi));
}
__device__ __forceinline__ uint32_t packbf(__nv_bfloat16 a, __nv_bfloat16 b) {
    return ((uint32_t)__bfloat16_as_ushort(b) << 16) | __bfloat16_as_ushort(a);
}
// write split pair into [hi | lo] layout, slabs of `stride`
__device__ __forceinline__ void put_cat2(__nv_bfloat16* p, int stride, float a, float b) {
    __nv_bfloat16 ah, al, bh, bl;
    split1(a, ah, al);
    split1(b, bh, bl);
    __nv_bfloat162 hi; hi.x = ah; hi.y = bh;
    __nv_bfloat162 lo; lo.x = al; lo.y = bl;
    *(__nv_bfloat162*)(p) = hi;
    *(__nv_bfloat162*)(p + stride) = lo;
}

// ---------------- weight transpose + split (vectorized): W[K][N] -> Wt[N][2K] = [hi|lo] ----------------
__global__ __launch_bounds__(256) void wconv_kernel(const float* __restrict__ W,
                                                    __nv_bfloat16* __restrict__ Wt,
                                                    int K, int N, size_t wOff, size_t oOff) {
    int z = blockIdx.z;
    W += wOff * z; Wt += oOff * z;
    __shared__ float t[64][33];
    int n0 = blockIdx.x * 32, k0 = blockIdx.y * 64;
    int tid = threadIdx.x;
    #pragma unroll
    for (int i = 0; i < 8; i++) {
        int id = tid + i * 256;
        int k = id >> 5, n = id & 31;
        t[k][n] = W[(size_t)(k0 + k) * N + n0 + n];
    }
    __syncthreads();
    int n = tid >> 3, kq = tid & 7;
    uint32_t hw[4], lw[4];
    #pragma unroll
    for (int j = 0; j < 4; j++) {
        float a = t[kq * 8 + 2 * j][n], b = t[kq * 8 + 2 * j + 1][n];
        __nv_bfloat16 ah, al, bh, bl;
        split1(a, ah, al);
        split1(b, bh, bl);
        hw[j] = packbf(ah, bh);
        lw[j] = packbf(al, bl);
    }
    __nv_bfloat16* p = Wt + (size_t)(n0 + n) * 2 * K + k0 + kq * 8;
    *(uint4*)p = make_uint4(hw[0], hw[1], hw[2], hw[3]);
    *(uint4*)(p + K) = make_uint4(lw[0], lw[1], lw[2], lw[3]);
}

// ---------------- layernorm ----------------
template <bool CAT>
__global__ __launch_bounds__(256) void ln_kernel(const float* __restrict__ x,
                                                 const float* __restrict__ g,
                                                 const float* __restrict__ b,
                                                 float* __restrict__ outf,
                                                 __nv_bfloat16* __restrict__ outc) {
    int row = blockIdx.x, tid = threadIdx.x;
    const float4* xr = (const float4*)(x + (size_t)row * DIM);
    float4 v = xr[tid];
    float s = v.x + v.y + v.z + v.w;
    float q = v.x * v.x + v.y * v.y + v.z * v.z + v.w * v.w;
    __shared__ float ss[8], sq[8];
    #pragma unroll
    for (int o = 16; o; o >>= 1) {
        s += __shfl_xor_sync(0xffffffffu, s, o);
        q += __shfl_xor_sync(0xffffffffu, q, o);
    }
    int w = tid >> 5;
    if ((tid & 31) == 0) { ss[w] = s; sq[w] = q; }
    __syncthreads();
    __shared__ float mu_s, rs_s;
    if (tid == 0) {
        float S = 0.f, Q = 0.f;
        #pragma unroll
        for (int i = 0; i < 8; i++) { S += ss[i]; Q += sq[i]; }
        float mu = S / DIM;
        mu_s = mu;
        rs_s = rsqrtf(Q / DIM - mu * mu + 1e-6f);
    }
    __syncthreads();
    float mu = mu_s, rs = rs_s;
    float4 gg = ((const float4*)g)[tid];
    float4 bb = ((const float4*)b)[tid];
    float4 o4;
    o4.x = (v.x - mu) * rs * gg.x + bb.x;
    o4.y = (v.y - mu) * rs * gg.y + bb.y;
    o4.z = (v.z - mu) * rs * gg.z + bb.z;
    o4.w = (v.w - mu) * rs * gg.w + bb.w;
    if (CAT) {
        __nv_bfloat16* p = outc + (size_t)row * 2048 + tid * 4;
        put_cat2(p, DIM, o4.x, o4.y);
        put_cat2(p + 2, DIM, o4.z, o4.w);
    } else {
        ((float4*)(outf + (size_t)row * DIM))[tid] = o4;
    }
}

// ---------------- HMMA GEMM: logical K' = 3K over physical [hi|lo] (2K) buffers ----------------
// 8 warps, warp tile 64x64 (2x4 warp grid), 4-stage cp.async ring, single sync per K-tile.
#define EPI_PLAIN 0
#define EPI_WO 1
#define EPI_W1 2
#define EPI_QKV 3
#define STAGE_BYTES 49152
#define GSMEM (4 * STAGE_BYTES)

template <int EPI>
__global__ __launch_bounds__(256, 1) void tgemm(
    const __nv_bfloat16* __restrict__ A, const __nv_bfloat16* __restrict__ Bt,
    const float* __restrict__ bias, const float* __restrict__ res,
    float* __restrict__ Cf, __nv_bfloat16* __restrict__ Cb,
    int Klog, int Nstr, int HIDN,
    size_t aOff, size_t bOff, size_t biasOff, size_t cOff,
    const int* __restrict__ cnt) {
    extern __shared__ __align__(1024) char smem[];
    const uint32_t sb = smem_u32(smem);
    const int tid = threadIdx.x;
    const int z = blockIdx.z;
    const int m0 = blockIdx.y * 128;
    if (cnt != nullptr && m0 >= cnt[z]) return;
    A += aOff * z; Bt += bOff * z; bias += biasOff * z;
    if (EPI == EPI_W1) Cb += cOff * z; else Cf += cOff * z;
    const int n0 = blockIdx.x * 256;
    const int nk = (3 * Klog) >> 6;
    const int Ks2 = 2 * Klog;

    auto loadStage = [&](int kt, int ss) {
        uint32_t sbase = sb + ss * STAGE_BYTES;
        int kb = kt << 6;
        int akb = kb < Ks2 ? kb : kb - Ks2;       // A logical [hi|lo|hi]
        int bkb = kb < Klog ? kb : kb - Klog;     // B logical [hi|hi|lo]
        const __nv_bfloat16* Ag = A + (size_t)m0 * Ks2 + akb;
        #pragma unroll
        for (int i = 0; i < 4; i++) {
            int id = tid + i * 256;
            int r = id >> 3, c = id & 7;
            cpa16(sbase + r * 128 + ((c ^ (r & 7)) << 4), Ag + (size_t)r * Ks2 + c * 8);
        }
        const __nv_bfloat16* Bg = Bt + (size_t)n0 * Ks2 + bkb;
        #pragma unroll
        for (int i = 0; i < 8; i++) {
            int id = tid + i * 256;
            int r = id >> 3, c = id & 7;
            cpa16(sbase + 16384 + r * 128 + ((c ^ (r & 7)) << 4), Bg + (size_t)r * Ks2 + c * 8);
        }
        CPA_COMMIT();
    };

    loadStage(0, 0);
    loadStage(1, 1);
    loadStage(2, 2);

    const int lane = tid & 31, wid = tid >> 5;
    const int wm = wid >> 2, wn = wid & 3;     // 2 x 4 warps, 64x64 tile each
    const int arl = lane & 15, akc = lane >> 4;

    int arow[4];
    #pragma unroll
    for (int mf = 0; mf < 4; mf++) arow[mf] = wm * 64 + mf * 16 + arl;

    float acc[4][8][4];
    #pragma unroll
    for (int mf = 0; mf < 4; mf++)
        #pragma unroll
        for (int nf = 0; nf < 8; nf++)
            #pragma unroll
            for (int i = 0; i < 4; i++) acc[mf][nf][i] = 0.f;

    for (int kt = 0; kt < nk; kt++) {
        CPA_WAIT2();
        __syncthreads();
        // prefetch 3 ahead into stage (kt+3)&3 == (kt-1)&3 — all threads finished
        // reading that stage before this barrier.
        if (kt + 3 < nk) loadStage(kt + 3, (kt + 3) & 3);
        else CPA_COMMIT();
        int ss = kt & 3;
        uint32_t Au = sb + ss * STAGE_BYTES;
        uint32_t Bu = Au + 16384;
        #pragma unroll
        for (int j = 0; j < 4; j++) {
            uint32_t af[4][4];
            #pragma unroll
            for (int mf = 0; mf < 4; mf++) {
                int r = arow[mf];
                ldsm4(af[mf], Au + r * 128 + (((j * 2 + akc) ^ (r & 7)) << 4));
            }
            uint32_t bf[4][4];
            #pragma unroll
            for (int pr = 0; pr < 4; pr++) {
                int r = wn * 64 + pr * 16 + arl;
                ldsm4(bf[pr], Bu + r * 128 + (((j * 2 + akc) ^ (r & 7)) << 4));
            }
            #pragma unroll
            for (int mf = 0; mf < 4; mf++)
                #pragma unroll
                for (int pr = 0; pr < 4; pr++) {
                    mma2(acc[mf][2 * pr], af[mf], bf[pr][0], bf[pr][2]);
                    mma2(acc[mf][2 * pr + 1], af[mf], bf[pr][1], bf[pr][3]);
                }
        }
    }

    const int quad = lane >> 2, tq = lane & 3;
    #pragma unroll
    for (int mf = 0; mf < 4; mf++) {
        #pragma unroll
        for (int nf = 0; nf < 8; nf++) {
            int m = m0 + wm * 64 + mf * 16 + quad;
            int n = n0 + wn * 64 + nf * 8 + tq * 2;
            const float* c = acc[mf][nf];
            float b0 = bias[n], b1 = bias[n + 1];
            if (EPI == EPI_W1) {
                float v0 = gelu_f(c[0] + b0), v1 = gelu_f(c[1] + b1);
                put_cat2(Cb + (size_t)m * (2 * HIDN) + n, HIDN, v0, v1);
                v0 = gelu_f(c[2] + b0); v1 = gelu_f(c[3] + b1);
                put_cat2(Cb + (size_t)(m + 8) * (2 * HIDN) + n, HIDN, v0, v1);
            } else {
                float2 v = make_float2(c[0] + b0, c[1] + b1);
                float2 w = make_float2(c[2] + b0, c[3] + b1);
                if (EPI == EPI_WO) {
                    float2 r1 = *(const float2*)&res[(size_t)m * Nstr + n];
                    float2 r2 = *(const float2*)&res[(size_t)(m + 8) * Nstr + n];
                    v.x += r1.x; v.y += r1.y;
                    w.x += r2.x; w.y += r2.y;
                }
                if (EPI == EPI_QKV && n >= 2048) {
                    // V columns: write split bf16 directly to attention layout
                    int h = (n - 2048) >> 6, cc = (n - 2048) & 63;
                    int b_ = m >> 11, s = m & (SEQ - 1);
                    __nv_bfloat16* D = g_vs + ((size_t)(b_ * NH + h) * SEQ + s) * 128;
                    put_cat2(D + cc, 64, v.x, v.y);
                    int b2_ = (m + 8) >> 11, s2 = (m + 8) & (SEQ - 1);
                    __nv_bfloat16* D2 = g_vs + ((size_t)(b2_ * NH + h) * SEQ + s2) * 128;
                    put_cat2(D2 + cc, 64, w.x, w.y);
                } else {
                    *(float2*)&Cf[(size_t)m * Nstr + n] = v;
                    *(float2*)&Cf[(size_t)(m + 8) * Nstr + n] = w;
                }
            }
        }
    }
}

// ---------------- RoPE + bf16 split of q,k into attention layout ----------------
__global__ void rope3_kernel(const float* __restrict__ cosT, const float* __restrict__ sinT) {
    int idx = blockIdx.x * blockDim.x + threadIdx.x;
    if (idx >= 2 * TKN * NH * 32) return;
    int i = idx & 31;
    int h = (idx >> 5) & 15;
    int t = (idx >> 9) & 4095;
    int qk = idx >> 21;   // 0=q, 1=k
    int s = t & (SEQ - 1);
    int b = t >> 11;
    size_t src = (size_t)t * 3072 + (size_t)qk * 1024 + h * 64;
    float a = g_qkv[src + i];
    float c = g_qkv[src + i + 32];
    float c0 = cosT[s * 64 + i], s0 = sinT[s * 64 + i];
    float c1 = cosT[s * 64 + i + 32], s1 = sinT[s * 64 + i + 32];
    float na = a * c0 - c * s0;
    float nc = c * c1 + a * s1;
    __nv_bfloat16 ah, al, ch, cl;
    split1(na, ah, al);
    split1(nc, ch, cl);
    __nv_bfloat16* D = (qk == 0 ? g_qs : g_ks) + ((size_t)(b * NH + h) * SEQ + s) * 128;
    D[i] = ah;
    D[32 + i] = ch;
    D[64 + i] = al;
    D[96 + i] = cl;
}

// ---------------- HMMA flash attention, pre-split bf16, cp.async double-buffered K/V ----------------
#define FSMEM 98304
__global__ __launch_bounds__(256, 2) void flash3_kernel() {
    extern __shared__ __align__(1024) char fsm[];
    const uint32_t Qu = smem_u32(fsm);
    const int b = blockIdx.z, h = blockIdx.y, q0 = blockIdx.x * 128;
    const int tid = threadIdx.x, lane = tid & 31, w = tid >> 5;
    const int arl = lane & 15, akc = lane >> 4;
    const int tq = lane & 3, quad = lane >> 2;
    const __nv_bfloat16* qsrc = g_qs + (size_t)(b * NH + h) * SEQ * 128;
    const __nv_bfloat16* ksrc = g_ks + (size_t)(b * NH + h) * SEQ * 128;
    const __nv_bfloat16* vsrc = g_vs + (size_t)(b * NH + h) * SEQ * 128;

    #pragma unroll
    for (int i = 0; i < 8; i++) {
        int id = tid + i * 256;
        int r = id >> 4, ch = id & 15;
        cpa16(Qu + r * 256 + ((ch ^ (r & 7)) << 4), qsrc + (size_t)(q0 + r) * 128 + ch * 8);
    }
    auto loadKV = [&](int kt, int st) {
        uint32_t Ks = Qu + 32768 + st * 32768;
        #pragma unroll
        for (int i = 0; i < 4; i++) {
            int id = tid + i * 256;
            int r = id >> 4, ch = id & 15;
            cpa16(Ks + r * 256 + ((ch ^ (r & 7)) << 4), ksrc + (size_t)(kt * 64 + r) * 128 + ch * 8);
        }
        uint32_t Vs = Ks + 16384;
        #pragma unroll
        for (int i = 0; i < 4; i++) {
            int id = tid + i * 256;
            int r = id >> 4, ch = id & 15;
            cpa16(Vs + r * 256 + ((ch ^ (r & 7)) << 4), vsrc + (size_t)(kt * 64 + r) * 128 + ch * 8);
        }
        CPA_COMMIT();
    };
    loadKV(0, 0);
    loadKV(1, 1);

    float accO[8][4];
    #pragma unroll
    for (int nf = 0; nf < 8; nf++)
        #pragma unroll
        for (int i = 0; i < 4; i++) accO[nf][i] = 0.f;
    float m0 = -1e30f, m1 = -1e30f, l0 = 0.f, l1 = 0.f;
    const int qr = w * 16 + arl;

    for (int kt = 0; kt < SEQ / 64; kt++) {
        int st = kt & 1;
        CPA_WAIT1();
        __syncthreads();
        uint32_t Ku = Qu + 32768 + st * 32768;
        uint32_t Vu = Ku + 16384;

        float accS[8][4];
        #pragma unroll
        for (int nf = 0; nf < 8; nf++)
            #pragma unroll
            for (int i = 0; i < 4; i++) accS[nf][i] = 0.f;
        #pragma unroll
        for (int j = 0; j < 4; j++) {
            uint32_t ah[4], al[4];
            ldsm4(ah, Qu + qr * 256 + (((j * 2 + akc) ^ (qr & 7)) << 4));
            ldsm4(al, Qu + qr * 256 + (((8 + j * 2 + akc) ^ (qr & 7)) << 4));
            #pragma unroll
            for (int pr = 0; pr < 4; pr++) {
                int kr = pr * 16 + arl;
                uint32_t bh[4], bl[4];
                ldsm4(bh, Ku + kr * 256 + (((j * 2 + akc) ^ (kr & 7)) << 4));
                ldsm4(bl, Ku + kr * 256 + (((8 + j * 2 + akc) ^ (kr & 7)) << 4));
                mma2(accS[2 * pr], ah, bh[0], bh[2]);
                mma2(accS[2 * pr], al, bh[0], bh[2]);
                mma2(accS[2 * pr], ah, bl[0], bl[2]);
                mma2(accS[2 * pr + 1], ah, bh[1], bh[3]);
                mma2(accS[2 * pr + 1], al, bh[1], bh[3]);
                mma2(accS[2 * pr + 1], ah, bl[1], bl[3]);
            }
        }
        float mt0 = m0, mt1 = m1;
        #pragma unroll
        for (int nf = 0; nf < 8; nf++) {
            #pragma unroll
            for (int i = 0; i < 4; i++) accS[nf][i] *= 0.125f;
            mt0 = fmaxf(mt0, fmaxf(accS[nf][0], accS[nf][1]));
            mt1 = fmaxf(mt1, fmaxf(accS[nf][2], accS[nf][3]));
        }
        #pragma unroll
        for (int o = 1; o <= 2; o <<= 1) {
            mt0 = fmaxf(mt0, __shfl_xor_sync(0xffffffffu, mt0, o));
            mt1 = fmaxf(mt1, __shfl_xor_sync(0xffffffffu, mt1, o));
        }
        float c0 = __expf(m0 - mt0), c1 = __expf(m1 - mt1);
        m0 = mt0; m1 = mt1;
        l0 *= c0; l1 *= c1;
        #pragma unroll
        for (int nf = 0; nf < 8; nf++) {
            accO[nf][0] *= c0; accO[nf][1] *= c0;
            accO[nf][2] *= c1; accO[nf][3] *= c1;
        }
        uint32_t ph[8][2], pl[8][2];
        #pragma unroll
        for (int nf = 0; nf < 8; nf++) {
            float p0 = __expf(accS[nf][0] - mt0);
            float p1 = __expf(accS[nf][1] - mt0);
            float p2 = __expf(accS[nf][2] - mt1);
            float p3 = __expf(accS[nf][3] - mt1);
            l0 += p0 + p1; l1 += p2 + p3;
            __nv_bfloat16 h0, e0, h1, e1, h2, e2, h3, e3;
            split1(p0, h0, e0); split1(p1, h1, e1);
            split1(p2, h2, e2); split1(p3, h3, e3);
            ph[nf][0] = packbf(h0, h1);
            ph[nf][1] = packbf(h2, h3);
            pl[nf][0] = packbf(e0, e1);
            pl[nf][1] = packbf(e2, e3);
        }
        #pragma unroll
        for (int kf = 0; kf < 4; kf++) {
            uint32_t pah[4] = {ph[2 * kf][0], ph[2 * kf][1], ph[2 * kf + 1][0], ph[2 * kf + 1][1]};
            uint32_t pal[4] = {pl[2 * kf][0], pl[2 * kf][1], pl[2 * kf + 1][0], pl[2 * kf + 1][1]};
            int vr = kf * 16 + arl;
            #pragma unroll
            for (int dp = 0; dp < 4; dp++) {
                uint32_t vh[4], vl[4];
                ldsm4t(vh, Vu + vr * 256 + (((dp * 2 + akc) ^ (vr & 7)) << 4));
                ldsm4t(vl, Vu + vr * 256 + (((8 + dp * 2 + akc) ^ (vr & 7)) << 4));
                mma2(accO[2 * dp], pah, vh[0], vh[1]);
                mma2(accO[2 * dp], pal, vh[0], vh[1]);
                mma2(accO[2 * dp], pah, vl[0], vl[1]);
                mma2(accO[2 * dp + 1], pah, vh[2], vh[3]);
                mma2(accO[2 * dp + 1], pal, vh[2], vh[3]);
                mma2(accO[2 * dp + 1], pah, vl[2], vl[3]);
            }
        }
        __syncthreads();
        if (kt + 2 < SEQ / 64) loadKV(kt + 2, st);
        else CPA_COMMIT();
    }
    #pragma unroll
    for (int o = 1; o <= 2; o <<= 1) {
        l0 += __shfl_xor_sync(0xffffffffu, l0, o);
        l1 += __shfl_xor_sync(0xffffffffu, l1, o);
    }
    float i0 = 1.f / l0, i1 = 1.f / l1;
    int r0 = q0 + w * 16 + quad;
    #pragma unroll
    for (int nf = 0; nf < 8; nf++) {
        int col = h * 64 + nf * 8 + tq * 2;
        put_cat2(g_ocat + (size_t)(b * SEQ + r0) * 2048 + col, DIM,
                 accO[nf][0] * i0, accO[nf][1] * i0);
        put_cat2(g_ocat + (size_t)(b * SEQ + r0 + 8) * 2048 + col, DIM,
                 accO[nf][2] * i1, accO[nf][3] * i1);
    }
}

// ---------------- gating ----------------
__global__ __launch_bounds__(128) void gate_kernel(const float* __restrict__ gate_w) {
    int t = blockIdx.x * 4 + (threadIdx.x >> 5);
    int lane = threadIdx.x & 31;
    const float* xr = g_h2 + (size_t)t * DIM;
    float p[8];
    #pragma unroll
    for (int e = 0; e < 8; e++) p[e] = 0.f;
    for (int it = 0; it < 32; it++) {
        int d = it * 32 + lane;
        float xv = xr[d];
        const float4* gw = (const float4*)(gate_w + d * 8);
        float4 g0 = gw[0], g1 = gw[1];
        p[0] += xv * g0.x; p[1] += xv * g0.y; p[2] += xv * g0.z; p[3] += xv * g0.w;
        p[4] += xv * g1.x; p[5] += xv * g1.y; p[6] += xv * g1.z; p[7] += xv * g1.w;
    }
    #pragma unroll
    for (int e = 0; e < 8; e++)
        #pragma unroll
        for (int o = 16; o; o >>= 1) p[e] += __shfl_xor_sync(0xffffffffu, p[e], o);
    if (lane == 0) {
        float mx = p[0];
        #pragma unroll
        for (int e = 1; e < 8; e++) mx = fmaxf(mx, p[e]);
        float ex[8], sum = 0.f;
        #pragma unroll
        for (int e = 0; e < 8; e++) { ex[e] = __expf(p[e] - mx); sum += ex[e]; }
        float inv = 1.f / sum;
        float pr[8];
        #pragma unroll
        for (int e = 0; e < 8; e++) { pr[e] = ex[e] * inv; g_probs[t * 8 + e] = pr[e]; }
        int i1 = 0;
        float v1 = pr[0];
        #pragma unroll
        for (int e = 1; e < 8; e++) if (pr[e] > v1) { v1 = pr[e]; i1 = e; }
        int i2 = -1;
        float v2 = -1.f;
        #pragma unroll
        for (int e = 0; e < 8; e++) if (e != i1 && pr[e] > v2) { v2 = pr[e]; i2 = e; }
        float dn = 1.f / (v1 + v2);
        g_eid[t] = i1;
        g_eid[TKN + t] = i2;
        g_wflat[t] = v1 * dn;
        g_wflat[TKN + t] = v2 * dn;
    }
}

// ---------------- per-expert positions + counts ----------------
__global__ void pos_kernel() {
    int e = threadIdx.x >> 5;
    int lane = threadIdx.x & 31;
    int base = 0;
    for (int a0 = 0; a0 < NA; a0 += 32) {
        int ea = g_eid[a0 + lane];
        unsigned mask = __ballot_sync(0xffffffffu, ea == e);
        if (ea == e) g_pos[a0 + lane] = base + __popc(mask & ((1u << lane) - 1));
        base += __popc(mask);
    }
    if (lane == 0) g_cnt[e] = base;
}

// ---------------- scatter tokens (split bf16) into capacity buffer ----------------
__global__ __launch_bounds__(256) void scatter_kernel() {
    int a = blockIdx.x;
    int p = g_pos[a];
    if (p >= CAP) return;
    int e = g_eid[a];
    int tok = a & (TKN - 1);
    float4 v = ((const float4*)(g_h2 + (size_t)tok * DIM))[threadIdx.x];
    __nv_bfloat16* dst = g_bufcat + ((size_t)e * CAP + p) * 2048 + threadIdx.x * 4;
    put_cat2(dst, DIM, v.x, v.y);
    put_cat2(dst + 2, DIM, v.z, v.w);
}

// ---------------- aux loss ----------------
__global__ __launch_bounds__(256) void aux_kernel(float* __restrict__ out, int out_size) {
    __shared__ float red[256];
    int tid = threadIdx.x;
    float me[8], cnt[8];
    #pragma unroll
    for (int e = 0; e < 8; e++) { me[e] = 0.f; cnt[e] = 0.f; }
    for (int t = tid; t < TKN; t += 256) {
        #pragma unroll
        for (int e = 0; e < 8; e++) me[e] += g_probs[t * 8 + e];
    }
    for (int a = tid; a < NA; a += 256) cnt[g_eid[a]] += 1.f;
    float auxv = 0.f;
    for (int e = 0; e < 8; e++) {
        red[tid] = me[e];
        __syncthreads();
        for (int st = 128; st; st >>= 1) { if (tid < st) red[tid] += red[tid + st]; __syncthreads(); }
        float meS = red[0];
        __syncthreads();
        red[tid] = cnt[e];
        __syncthreads();
        for (int st = 128; st; st >>= 1) { if (tid < st) red[tid] += red[tid + st]; __syncthreads(); }
        float cS = red[0];
        __syncthreads();
        auxv += (meS / (float)TKN) * (cS / (float)NA);
    }
    if (tid == 0 && out_size > TKN * DIM) out[TKN * DIM] = 8.f * auxv;
}

// ---------------- combine ----------------
__global__ __launch_bounds__(256) void final_kernel(float* __restrict__ out) {
    int t = blockIdx.x;
    int tid = threadIdx.x;
    int p1 = g_pos[t], p2 = g_pos[TKN + t];
    int e1 = g_eid[t], e2 = g_eid[TKN + t];
    float w1 = (p1 < CAP) ? g_wflat[t] : 0.f;
    float w2 = (p2 < CAP) ? g_wflat[TKN + t] : 0.f;
    p1 = min(p1, CAP - 1);
    p2 = min(p2, CAP - 1);
    const float4* a = (const float4*)(g_oute + ((size_t)e1 * CAP + p1) * DIM);
    const float4* b = (const float4*)(g_oute + ((size_t)e2 * CAP + p2) * DIM);
    const float4* xr = (const float4*)(g_x2 + (size_t)t * DIM);
    float4 av = a[tid], bv = b[tid], xv = xr[tid];
    float4 r;
    r.x = xv.x + w1 * av.x + w2 * bv.x;
    r.y = xv.y + w1 * av.y + w2 * bv.y;
    r.z = xv.z + w1 * av.z + w2 * bv.z;
    r.w = xv.w + w1 * av.w + w2 * bv.w;
    ((float4*)(out + (size_t)t * DIM))[tid] = r;
}

// ---------------- host ----------------
extern "C" void kernel_launch(void* const* d_in, const int* in_sizes, int n_in,
                              void* d_out, int out_size) {
    const float* x     = (const float*)d_in[0];
    const float* cosT  = (const float*)d_in[1];
    const float* sinT  = (const float*)d_in[2];
    const float* ln1g  = (const float*)d_in[3];
    const float* ln1b  = (const float*)d_in[4];
    const float* ln2g  = (const float*)d_in[5];
    const float* ln2b  = (const float*)d_in[6];
    const float* wqkv  = (const float*)d_in[7];
    const float* bqkv  = (const float*)d_in[8];
    const float* wo    = (const float*)d_in[9];
    const float* bo    = (const float*)d_in[10];
    const float* gatew = (const float*)d_in[11];
    const float* w1    = (const float*)d_in[12];
    const float* b1    = (const float*)d_in[13];
    const float* w2    = (const float*)d_in[14];
    const float* b2    = (const float*)d_in[15];
    float* out = (float*)d_out;

    void *p_qkv, *p_x2, *p_h2, *p_oute, *p_cnt;
    void *p_acat, *p_ocat, *p_bufcat, *p_hhcat, *p_wqkvc, *p_woc, *p_w1c, *p_w2c;
    cudaGetSymbolAddress(&p_qkv, g_qkv);
    cudaGetSymbolAddress(&p_x2, g_x2);
    cudaGetSymbolAddress(&p_h2, g_h2);
    cudaGetSymbolAddress(&p_oute, g_oute);
    cudaGetSymbolAddress(&p_cnt, g_cnt);
    cudaGetSymbolAddress(&p_acat, g_acat);
    cudaGetSymbolAddress(&p_ocat, g_ocat);
    cudaGetSymbolAddress(&p_bufcat, g_bufcat);
    cudaGetSymbolAddress(&p_hhcat, g_hhcat);
    cudaGetSymbolAddress(&p_wqkvc, g_wqkvcat);
    cudaGetSymbolAddress(&p_woc, g_wocat);
    cudaGetSymbolAddress(&p_w1c, g_w1cat);
    cudaGetSymbolAddress(&p_w2c, g_w2cat);

    static int init_done = 0;
    static cudaStream_t s1, s2;
    static cudaEvent_t e0, e1, e2, e3, e4;
    if (!init_done) {
        cudaFuncSetAttribute(tgemm<EPI_PLAIN>, cudaFuncAttributeMaxDynamicSharedMemorySize, GSMEM);
        cudaFuncSetAttribute(tgemm<EPI_WO>, cudaFuncAttributeMaxDynamicSharedMemorySize, GSMEM);
        cudaFuncSetAttribute(tgemm<EPI_W1>, cudaFuncAttributeMaxDynamicSharedMemorySize, GSMEM);
        cudaFuncSetAttribute(tgemm<EPI_QKV>, cudaFuncAttributeMaxDynamicSharedMemorySize, GSMEM);
        cudaFuncSetAttribute(flash3_kernel, cudaFuncAttributeMaxDynamicSharedMemorySize, FSMEM);
        cudaStreamCreateWithFlags(&s1, cudaStreamNonBlocking);
        cudaStreamCreateWithFlags(&s2, cudaStreamNonBlocking);
        cudaEventCreateWithFlags(&e0, cudaEventDisableTiming);
        cudaEventCreateWithFlags(&e1, cudaEventDisableTiming);
        cudaEventCreateWithFlags(&e2, cudaEventDisableTiming);
        cudaEventCreateWithFlags(&e3, cudaEventDisableTiming);
        cudaEventCreateWithFlags(&e4, cudaEventDisableTiming);
        init_done = 1;
    }

    // fork side streams off the main (captured) stream
    cudaEventRecord(e0, 0);
    cudaStreamWaitEvent(s1, e0, 0);
    cudaStreamWaitEvent(s2, e0, 0);

    // s1: heavy weight conversions (DRAM-bound) — overlap with qkv GEMM + flash
    wconv_kernel<<<dim3(32, 16, 1), 256, 0, s1>>>(wo, (__nv_bfloat16*)p_woc, 1024, 1024, 0, 0);
    wconv_kernel<<<dim3(128, 16, 8), 256, 0, s1>>>(w1, (__nv_bfloat16*)p_w1c, 1024, 4096,
                                                   (size_t)DIM * HID, (size_t)HID * 2048);
    wconv_kernel<<<dim3(32, 64, 8), 256, 0, s1>>>(w2, (__nv_bfloat16*)p_w2c, 4096, 1024,
                                                  (size_t)HID * DIM, (size_t)DIM * 8192);
    cudaEventRecord(e1, s1);

    // s2: ln1 (concurrent with wconv_qkv on main stream)
    ln_kernel<true><<<TKN, 256, 0, s2>>>(x, ln1g, ln1b, nullptr, (__nv_bfloat16*)p_acat);
    cudaEventRecord(e2, s2);

    // main: qkv weight conversion, then qkv GEMM
    wconv_kernel<<<dim3(96, 16, 1), 256>>>(wqkv, (__nv_bfloat16*)p_wqkvc, 1024, 3072, 0, 0);
    cudaStreamWaitEvent(0, e2, 0);
    tgemm<EPI_QKV><<<dim3(12, 32, 1), 256, GSMEM>>>(
        (const __nv_bfloat16*)p_acat, (const __nv_bfloat16*)p_wqkvc, bqkv, nullptr,
        (float*)p_qkv, nullptr, 1024, 3072, 0, 0, 0, 0, 0, nullptr);
    rope3_kernel<<<(2 * TKN * NH * 32) / 256, 256>>>(cosT, sinT);
    flash3_kernel<<<dim3(SEQ / 128, NH, 2), 256, FSMEM>>>();
    // wo GEMM needs g_wocat from s1
    cudaStreamWaitEvent(0, e1, 0);
    tgemm<EPI_WO><<<dim3(4, 32, 1), 256, GSMEM>>>(
        (const __nv_bfloat16*)p_ocat, (const __nv_bfloat16*)p_woc, bo, x,
        (float*)p_x2, nullptr, 1024, 1024, 0, 0, 0, 0, 0, nullptr);
    ln_kernel<false><<<TKN, 256>>>((const float*)p_x2, ln2g, ln2b, (float*)p_h2, nullptr);
    gate_kernel<<<TKN / 4, 128>>>(gatew);
    pos_kernel<<<1, 256>>>();
    // aux only needs probs (gate) + eid (gate): run on s2 concurrent with scatter + MoE GEMMs
    cudaEventRecord(e3, 0);
    cudaStreamWaitEvent(s2, e3, 0);
    aux_kernel<<<1, 256, 0, s2>>>(out, out_size);
    cudaEventRecord(e4, s2);
    // main: scatter + expert FFN
    scatter_kernel<<<NA, 256>>>();
    tgemm<EPI_W1><<<dim3(16, 10, 8), 256, GSMEM>>>(
        (const __nv_bfloat16*)p_bufcat, (const __nv_bfloat16*)p_w1c, b1, nullptr,
        nullptr, (__nv_bfloat16*)p_hhcat, 1024, 0, HID,
        (size_t)CAP * 2048, (size_t)HID * 2048, (size_t)HID, (size_t)CAP * 8192,
        (const int*)p_cnt);
    tgemm<EPI_PLAIN><<<dim3(4, 10, 8), 256, GSMEM>>>(
        (const __nv_bfloat16*)p_hhcat, (const __nv_bfloat16*)p_w2c, b2, nullptr,
        (float*)p_oute, nullptr, 4096, 1024, 0,
        (size_t)CAP * 8192, (size_t)DIM * 8192, (size_t)DIM, (size_t)CAP * DIM,
        (const int*)p_cnt);
    final_kernel<<<TKN, 256>>>(out);
    // join aux back into the main stream before capture ends
    cudaStreamWaitEvent(0, e4, 0);
}

// round 15
// speedup vs baseline: 3.1627x; 1.0133x over previous
#include <cuda_runtime.h>
#include <cuda_bf16.h>
#include <math.h>
#include <stdint.h>

#define TKN 4096
#define SEQ 2048
#define DIM 1024
#define NH 16
#define NE 8
#define HID 4096
#define CAP 1280
#define NA 8192

// ---------------- scratch ----------------
__device__ float g_x2[TKN * DIM];
__device__ float g_h2[TKN * DIM];
__device__ float g_probs[TKN * NE];
__device__ int   g_eid[NA];
__device__ float g_wflat[NA];
__device__ int   g_pos[NA];
__device__ int   g_cnt[NE];
__device__ float g_oute[NE * CAP * DIM];

// [hi|lo] compact split buffers (row stride = 2*K)
__device__ __nv_bfloat16 g_acat[(size_t)TKN * 2048];
__device__ __nv_bfloat16 g_ocat[(size_t)TKN * 2048];
__device__ __nv_bfloat16 g_bufcat[(size_t)NE * CAP * 2048];
__device__ __nv_bfloat16 g_hhcat[(size_t)NE * CAP * 8192];
__device__ __nv_bfloat16 g_wqkvcat[(size_t)3072 * 2048];
__device__ __nv_bfloat16 g_wocat[(size_t)1024 * 2048];
__device__ __nv_bfloat16 g_w1cat[(size_t)NE * HID * 2048];
__device__ __nv_bfloat16 g_w2cat[(size_t)NE * DIM * 8192];
// pre-split attention operands: [b*NH+h][seq][128] = hi(64) | lo(64)
__device__ __nv_bfloat16 g_qs[(size_t)2 * NH * SEQ * 128];
__device__ __nv_bfloat16 g_ks[(size_t)2 * NH * SEQ * 128];
__device__ __nv_bfloat16 g_vs[(size_t)2 * NH * SEQ * 128];

// ---------------- helpers ----------------
__device__ __forceinline__ uint32_t smem_u32(const void* p) {
    uint32_t a;
    asm("{ .reg .u64 t; cvta.to.shared.u64 t, %1; cvt.u32.u64 %0, t; }" : "=r"(a) : "l"(p));
    return a;
}
__device__ __forceinline__ void ldsm4(uint32_t* r, uint32_t a) {
    asm volatile("ldmatrix.sync.aligned.m8n8.x4.shared.b16 {%0,%1,%2,%3}, [%4];"
                 : "=r"(r[0]), "=r"(r[1]), "=r"(r[2]), "=r"(r[3]) : "r"(a));
}
__device__ __forceinline__ void ldsm4t(uint32_t* r, uint32_t a) {
    asm volatile("ldmatrix.sync.aligned.m8n8.x4.trans.shared.b16 {%0,%1,%2,%3}, [%4];"
                 : "=r"(r[0]), "=r"(r[1]), "=r"(r[2]), "=r"(r[3]) : "r"(a));
}
__device__ __forceinline__ void mma2(float* c, const uint32_t* a, uint32_t b0, uint32_t b1) {
    asm volatile(
        "mma.sync.aligned.m16n8k16.row.col.f32.bf16.bf16.f32 "
        "{%0,%1,%2,%3}, {%4,%5,%6,%7}, {%8,%9}, {%0,%1,%2,%3};"
        : "+f"(c[0]), "+f"(c[1]), "+f"(c[2]), "+f"(c[3])
        : "r"(a[0]), "r"(a[1]), "r"(a[2]), "r"(a[3]), "r"(b0), "r"(b1));
}
__device__ __forceinline__ void cpa16(uint32_t dst, const void* src) {
    asm volatile("cp.async.cg.shared.global [%0], [%1], 16;" :: "r"(dst), "l"(src));
}
#define CPA_COMMIT() asm volatile("cp.async.commit_group;")
#define CPA_WAIT2()  asm volatile("cp.async.wait_group 2;")
#define CPA_WAIT1()  asm volatile("cp.async.wait_group 1;")

__device__ __forceinline__ float gelu_f(float x) {
    float x3 = x * x * x;
    float t = tanhf(0.7978845608028654f * (x + 0.044715f * x3));
    return 0.5f * x * (1.0f + t);
}
__device__ __forceinline__ void split1(float v, __nv_bfloat16& hi, __nv_bfloat16& lo) {
    hi = __float2bfloat16(v);
    lo = __float2bfloat16(v - __bfloat162float(hi));
}
__device__ __forceinline__ uint32_t packbf(__nv_bfloat16 a, __nv_bfloat16 b) {
    return ((uint32_t)__bfloat16_as_ushort(b) << 16) | __bfloat16_as_ushort(a);
}
// write split pair into [hi | lo] layout, slabs of `stride`
__device__ __forceinline__ void put_cat2(__nv_bfloat16* p, int stride, float a, float b) {
    __nv_bfloat16 ah, al, bh, bl;
    split1(a, ah, al);
    split1(b, bh, bl);
    __nv_bfloat162 hi; hi.x = ah; hi.y = bh;
    __nv_bfloat162 lo; lo.x = al; lo.y = bl;
    *(__nv_bfloat162*)(p) = hi;
    *(__nv_bfloat162*)(p + stride) = lo;
}

// ---------------- weight transpose + split (vectorized): W[K][N] -> Wt[N][2K] = [hi|lo] ----------------
__global__ __launch_bounds__(256) void wconv_kernel(const float* __restrict__ W,
                                                    __nv_bfloat16* __restrict__ Wt,
                                                    int K, int N, size_t wOff, size_t oOff) {
    int z = blockIdx.z;
    W += wOff * z; Wt += oOff * z;
    __shared__ float t[64][33];
    int n0 = blockIdx.x * 32, k0 = blockIdx.y * 64;
    int tid = threadIdx.x;
    #pragma unroll
    for (int i = 0; i < 8; i++) {
        int id = tid + i * 256;
        int k = id >> 5, n = id & 31;
        t[k][n] = W[(size_t)(k0 + k) * N + n0 + n];
    }
    __syncthreads();
    int n = tid >> 3, kq = tid & 7;
    uint32_t hw[4], lw[4];
    #pragma unroll
    for (int j = 0; j < 4; j++) {
        float a = t[kq * 8 + 2 * j][n], b = t[kq * 8 + 2 * j + 1][n];
        __nv_bfloat16 ah, al, bh, bl;
        split1(a, ah, al);
        split1(b, bh, bl);
        hw[j] = packbf(ah, bh);
        lw[j] = packbf(al, bl);
    }
    __nv_bfloat16* p = Wt + (size_t)(n0 + n) * 2 * K + k0 + kq * 8;
    *(uint4*)p = make_uint4(hw[0], hw[1], hw[2], hw[3]);
    *(uint4*)(p + K) = make_uint4(lw[0], lw[1], lw[2], lw[3]);
}

// ---------------- layernorm ----------------
template <bool CAT>
__global__ __launch_bounds__(256) void ln_kernel(const float* __restrict__ x,
                                                 const float* __restrict__ g,
                                                 const float* __restrict__ b,
                                                 float* __restrict__ outf,
                                                 __nv_bfloat16* __restrict__ outc) {
    int row = blockIdx.x, tid = threadIdx.x;
    const float4* xr = (const float4*)(x + (size_t)row * DIM);
    float4 v = xr[tid];
    float s = v.x + v.y + v.z + v.w;
    float q = v.x * v.x + v.y * v.y + v.z * v.z + v.w * v.w;
    __shared__ float ss[8], sq[8];
    #pragma unroll
    for (int o = 16; o; o >>= 1) {
        s += __shfl_xor_sync(0xffffffffu, s, o);
        q += __shfl_xor_sync(0xffffffffu, q, o);
    }
    int w = tid >> 5;
    if ((tid & 31) == 0) { ss[w] = s; sq[w] = q; }
    __syncthreads();
    __shared__ float mu_s, rs_s;
    if (tid == 0) {
        float S = 0.f, Q = 0.f;
        #pragma unroll
        for (int i = 0; i < 8; i++) { S += ss[i]; Q += sq[i]; }
        float mu = S / DIM;
        mu_s = mu;
        rs_s = rsqrtf(Q / DIM - mu * mu + 1e-6f);
    }
    __syncthreads();
    float mu = mu_s, rs = rs_s;
    float4 gg = ((const float4*)g)[tid];
    float4 bb = ((const float4*)b)[tid];
    float4 o4;
    o4.x = (v.x - mu) * rs * gg.x + bb.x;
    o4.y = (v.y - mu) * rs * gg.y + bb.y;
    o4.z = (v.z - mu) * rs * gg.z + bb.z;
    o4.w = (v.w - mu) * rs * gg.w + bb.w;
    if (CAT) {
        __nv_bfloat16* p = outc + (size_t)row * 2048 + tid * 4;
        put_cat2(p, DIM, o4.x, o4.y);
        put_cat2(p + 2, DIM, o4.z, o4.w);
    } else {
        ((float4*)(outf + (size_t)row * DIM))[tid] = o4;
    }
}

// ---------------- HMMA GEMM: logical K' = 3K over physical [hi|lo] (2K) buffers ----------------
// 8 warps, warp tile 64x64 (2x4 warp grid), 4-stage cp.async ring, single sync per K-tile.
#define EPI_PLAIN 0
#define EPI_WO 1
#define EPI_W1 2
#define EPI_QKV 3
#define STAGE_BYTES 49152
#define GSMEM (4 * STAGE_BYTES)

template <int EPI>
__global__ __launch_bounds__(256, 1) void tgemm(
    const __nv_bfloat16* __restrict__ A, const __nv_bfloat16* __restrict__ Bt,
    const float* __restrict__ bias, const float* __restrict__ res,
    float* __restrict__ Cf, __nv_bfloat16* __restrict__ Cb,
    int Klog, int Nstr, int HIDN,
    size_t aOff, size_t bOff, size_t biasOff, size_t cOff,
    const int* __restrict__ cnt,
    const float* __restrict__ cosT, const float* __restrict__ sinT) {
    extern __shared__ __align__(1024) char smem[];
    const uint32_t sb = smem_u32(smem);
    const int tid = threadIdx.x;
    const int z = blockIdx.z;
    const int m0 = blockIdx.y * 128;
    if (cnt != nullptr && m0 >= cnt[z]) return;
    A += aOff * z; Bt += bOff * z; bias += biasOff * z;
    if (EPI == EPI_W1) Cb += cOff * z; else Cf += cOff * z;
    const int n0 = blockIdx.x * 256;
    const int nk = (3 * Klog) >> 6;
    const int Ks2 = 2 * Klog;

    auto loadStage = [&](int kt, int ss) {
        uint32_t sbase = sb + ss * STAGE_BYTES;
        int kb = kt << 6;
        int akb = kb < Ks2 ? kb : kb - Ks2;       // A logical [hi|lo|hi]
        int bkb = kb < Klog ? kb : kb - Klog;     // B logical [hi|hi|lo]
        const __nv_bfloat16* Ag = A + (size_t)m0 * Ks2 + akb;
        #pragma unroll
        for (int i = 0; i < 4; i++) {
            int id = tid + i * 256;
            int r = id >> 3, c = id & 7;
            cpa16(sbase + r * 128 + ((c ^ (r & 7)) << 4), Ag + (size_t)r * Ks2 + c * 8);
        }
        const __nv_bfloat16* Bg = Bt + (size_t)n0 * Ks2 + bkb;
        #pragma unroll
        for (int i = 0; i < 8; i++) {
            int id = tid + i * 256;
            int r = id >> 3, c = id & 7;
            cpa16(sbase + 16384 + r * 128 + ((c ^ (r & 7)) << 4), Bg + (size_t)r * Ks2 + c * 8);
        }
        CPA_COMMIT();
    };

    loadStage(0, 0);
    loadStage(1, 1);
    loadStage(2, 2);

    const int lane = tid & 31, wid = tid >> 5;
    const int wm = wid >> 2, wn = wid & 3;     // 2 x 4 warps, 64x64 tile each
    const int arl = lane & 15, akc = lane >> 4;

    int arow[4];
    #pragma unroll
    for (int mf = 0; mf < 4; mf++) arow[mf] = wm * 64 + mf * 16 + arl;

    float acc[4][8][4];
    #pragma unroll
    for (int mf = 0; mf < 4; mf++)
        #pragma unroll
        for (int nf = 0; nf < 8; nf++)
            #pragma unroll
            for (int i = 0; i < 4; i++) acc[mf][nf][i] = 0.f;

    for (int kt = 0; kt < nk; kt++) {
        CPA_WAIT2();
        __syncthreads();
        // prefetch 3 ahead into stage (kt+3)&3 == (kt-1)&3 — all threads finished
        // reading that stage before this barrier.
        if (kt + 3 < nk) loadStage(kt + 3, (kt + 3) & 3);
        else CPA_COMMIT();
        int ss = kt & 3;
        uint32_t Au = sb + ss * STAGE_BYTES;
        uint32_t Bu = Au + 16384;
        #pragma unroll
        for (int j = 0; j < 4; j++) {
            uint32_t af[4][4];
            #pragma unroll
            for (int mf = 0; mf < 4; mf++) {
                int r = arow[mf];
                ldsm4(af[mf], Au + r * 128 + (((j * 2 + akc) ^ (r & 7)) << 4));
            }
            uint32_t bf[4][4];
            #pragma unroll
            for (int pr = 0; pr < 4; pr++) {
                int r = wn * 64 + pr * 16 + arl;
                ldsm4(bf[pr], Bu + r * 128 + (((j * 2 + akc) ^ (r & 7)) << 4));
            }
            #pragma unroll
            for (int mf = 0; mf < 4; mf++)
                #pragma unroll
                for (int pr = 0; pr < 4; pr++) {
                    mma2(acc[mf][2 * pr], af[mf], bf[pr][0], bf[pr][2]);
                    mma2(acc[mf][2 * pr + 1], af[mf], bf[pr][1], bf[pr][3]);
                }
        }
    }

    const int quad = lane >> 2, tq = lane & 3;
    if (EPI == EPI_QKV && n0 < 2048) {
        // q or k tile: apply RoPE in-register, write split bf16 to attention layout
        __nv_bfloat16* base = (n0 < 1024) ? g_qs : g_ks;
        #pragma unroll
        for (int mf = 0; mf < 4; mf++) {
            int m = m0 + wm * 64 + mf * 16 + quad;
            #pragma unroll
            for (int nf = 0; nf < 4; nf++) {
                int n = n0 + wn * 64 + nf * 8 + tq * 2;
                int h = (n & 1023) >> 6;
                int cc = n & 63;   // in [0,32): pairs with cc+32 in fragment nf+4
                const float* cA = acc[mf][nf];
                const float* cC = acc[mf][nf + 4];
                float b0 = bias[n], b1 = bias[n + 1];
                float b2 = bias[n + 32], b3 = bias[n + 33];
                #pragma unroll
                for (int half = 0; half < 2; half++) {
                    int mr = m + half * 8;
                    int s = mr & (SEQ - 1), bb = mr >> 11;
                    float a0 = cA[2 * half + 0] + b0;
                    float a1 = cA[2 * half + 1] + b1;
                    float g0 = cC[2 * half + 0] + b2;
                    float g1 = cC[2 * half + 1] + b3;
                    const float* cr = cosT + s * 64;
                    const float* sr = sinT + s * 64;
                    float na0 = a0 * cr[cc] - g0 * sr[cc];
                    float na1 = a1 * cr[cc + 1] - g1 * sr[cc + 1];
                    float nc0 = g0 * cr[cc + 32] + a0 * sr[cc + 32];
                    float nc1 = g1 * cr[cc + 33] + a1 * sr[cc + 33];
                    __nv_bfloat16* D = base + ((size_t)(bb * NH + h) * SEQ + s) * 128;
                    put_cat2(D + cc, 64, na0, na1);
                    put_cat2(D + cc + 32, 64, nc0, nc1);
                }
            }
        }
        return;
    }
    #pragma unroll
    for (int mf = 0; mf < 4; mf++) {
        #pragma unroll
        for (int nf = 0; nf < 8; nf++) {
            int m = m0 + wm * 64 + mf * 16 + quad;
            int n = n0 + wn * 64 + nf * 8 + tq * 2;
            const float* c = acc[mf][nf];
            float b0 = bias[n], b1 = bias[n + 1];
            if (EPI == EPI_W1) {
                float v0 = gelu_f(c[0] + b0), v1 = gelu_f(c[1] + b1);
                put_cat2(Cb + (size_t)m * (2 * HIDN) + n, HIDN, v0, v1);
                v0 = gelu_f(c[2] + b0); v1 = gelu_f(c[3] + b1);
                put_cat2(Cb + (size_t)(m + 8) * (2 * HIDN) + n, HIDN, v0, v1);
            } else {
                float2 v = make_float2(c[0] + b0, c[1] + b1);
                float2 w = make_float2(c[2] + b0, c[3] + b1);
                if (EPI == EPI_WO) {
                    float2 r1 = *(const float2*)&res[(size_t)m * Nstr + n];
                    float2 r2 = *(const float2*)&res[(size_t)(m + 8) * Nstr + n];
                    v.x += r1.x; v.y += r1.y;
                    w.x += r2.x; w.y += r2.y;
                }
                if (EPI == EPI_QKV) {
                    // V columns (n >= 2048): write split bf16 directly to attention layout
                    int h = (n - 2048) >> 6, cc = (n - 2048) & 63;
                    int b_ = m >> 11, s = m & (SEQ - 1);
                    __nv_bfloat16* D = g_vs + ((size_t)(b_ * NH + h) * SEQ + s) * 128;
                    put_cat2(D + cc, 64, v.x, v.y);
                    int b2_ = (m + 8) >> 11, s2 = (m + 8) & (SEQ - 1);
                    __nv_bfloat16* D2 = g_vs + ((size_t)(b2_ * NH + h) * SEQ + s2) * 128;
                    put_cat2(D2 + cc, 64, w.x, w.y);
                } else {
                    *(float2*)&Cf[(size_t)m * Nstr + n] = v;
                    *(float2*)&Cf[(size_t)(m + 8) * Nstr + n] = w;
                }
            }
        }
    }
}

// ---------------- HMMA flash attention, pre-split bf16, cp.async double-buffered K/V ----------------
#define FSMEM 98304
__global__ __launch_bounds__(256, 2) void flash3_kernel() {
    extern __shared__ __align__(1024) char fsm[];
    const uint32_t Qu = smem_u32(fsm);
    const int b = blockIdx.z, h = blockIdx.y, q0 = blockIdx.x * 128;
    const int tid = threadIdx.x, lane = tid & 31, w = tid >> 5;
    const int arl = lane & 15, akc = lane >> 4;
    const int tq = lane & 3, quad = lane >> 2;
    const __nv_bfloat16* qsrc = g_qs + (size_t)(b * NH + h) * SEQ * 128;
    const __nv_bfloat16* ksrc = g_ks + (size_t)(b * NH + h) * SEQ * 128;
    const __nv_bfloat16* vsrc = g_vs + (size_t)(b * NH + h) * SEQ * 128;

    #pragma unroll
    for (int i = 0; i < 8; i++) {
        int id = tid + i * 256;
        int r = id >> 4, ch = id & 15;
        cpa16(Qu + r * 256 + ((ch ^ (r & 7)) << 4), qsrc + (size_t)(q0 + r) * 128 + ch * 8);
    }
    auto loadKV = [&](int kt, int st) {
        uint32_t Ks = Qu + 32768 + st * 32768;
        #pragma unroll
        for (int i = 0; i < 4; i++) {
            int id = tid + i * 256;
            int r = id >> 4, ch = id & 15;
            cpa16(Ks + r * 256 + ((ch ^ (r & 7)) << 4), ksrc + (size_t)(kt * 64 + r) * 128 + ch * 8);
        }
        uint32_t Vs = Ks + 16384;
        #pragma unroll
        for (int i = 0; i < 4; i++) {
            int id = tid + i * 256;
            int r = id >> 4, ch = id & 15;
            cpa16(Vs + r * 256 + ((ch ^ (r & 7)) << 4), vsrc + (size_t)(kt * 64 + r) * 128 + ch * 8);
        }
        CPA_COMMIT();
    };
    loadKV(0, 0);
    loadKV(1, 1);

    float accO[8][4];
    #pragma unroll
    for (int nf = 0; nf < 8; nf++)
        #pragma unroll
        for (int i = 0; i < 4; i++) accO[nf][i] = 0.f;
    float m0 = -1e30f, m1 = -1e30f, l0 = 0.f, l1 = 0.f;
    const int qr = w * 16 + arl;

    for (int kt = 0; kt < SEQ / 64; kt++) {
        int st = kt & 1;
        CPA_WAIT1();
        __syncthreads();
        uint32_t Ku = Qu + 32768 + st * 32768;
        uint32_t Vu = Ku + 16384;

        float accS[8][4];
        #pragma unroll
        for (int nf = 0; nf < 8; nf++)
            #pragma unroll
            for (int i = 0; i < 4; i++) accS[nf][i] = 0.f;
        #pragma unroll
        for (int j = 0; j < 4; j++) {
            uint32_t ah[4], al[4];
            ldsm4(ah, Qu + qr * 256 + (((j * 2 + akc) ^ (qr & 7)) << 4));
            ldsm4(al, Qu + qr * 256 + (((8 + j * 2 + akc) ^ (qr & 7)) << 4));
            #pragma unroll
            for (int pr = 0; pr < 4; pr++) {
                int kr = pr * 16 + arl;
                uint32_t bh[4], bl[4];
                ldsm4(bh, Ku + kr * 256 + (((j * 2 + akc) ^ (kr & 7)) << 4));
                ldsm4(bl, Ku + kr * 256 + (((8 + j * 2 + akc) ^ (kr & 7)) << 4));
                mma2(accS[2 * pr], ah, bh[0], bh[2]);
                mma2(accS[2 * pr], al, bh[0], bh[2]);
                mma2(accS[2 * pr], ah, bl[0], bl[2]);
                mma2(accS[2 * pr + 1], ah, bh[1], bh[3]);
                mma2(accS[2 * pr + 1], al, bh[1], bh[3]);
                mma2(accS[2 * pr + 1], ah, bl[1], bl[3]);
            }
        }
        float mt0 = m0, mt1 = m1;
        #pragma unroll
        for (int nf = 0; nf < 8; nf++) {
            #pragma unroll
            for (int i = 0; i < 4; i++) accS[nf][i] *= 0.125f;
            mt0 = fmaxf(mt0, fmaxf(accS[nf][0], accS[nf][1]));
            mt1 = fmaxf(mt1, fmaxf(accS[nf][2], accS[nf][3]));
        }
        #pragma unroll
        for (int o = 1; o <= 2; o <<= 1) {
            mt0 = fmaxf(mt0, __shfl_xor_sync(0xffffffffu, mt0, o));
            mt1 = fmaxf(mt1, __shfl_xor_sync(0xffffffffu, mt1, o));
        }
        float c0 = __expf(m0 - mt0), c1 = __expf(m1 - mt1);
        m0 = mt0; m1 = mt1;
        l0 *= c0; l1 *= c1;
        #pragma unroll
        for (int nf = 0; nf < 8; nf++) {
            accO[nf][0] *= c0; accO[nf][1] *= c0;
            accO[nf][2] *= c1; accO[nf][3] *= c1;
        }
        uint32_t ph[8][2], pl[8][2];
        #pragma unroll
        for (int nf = 0; nf < 8; nf++) {
            float p0 = __expf(accS[nf][0] - mt0);
            float p1 = __expf(accS[nf][1] - mt0);
            float p2 = __expf(accS[nf][2] - mt1);
            float p3 = __expf(accS[nf][3] - mt1);
            l0 += p0 + p1; l1 += p2 + p3;
            __nv_bfloat16 h0, e0, h1, e1, h2, e2, h3, e3;
            split1(p0, h0, e0); split1(p1, h1, e1);
            split1(p2, h2, e2); split1(p3, h3, e3);
            ph[nf][0] = packbf(h0, h1);
            ph[nf][1] = packbf(h2, h3);
            pl[nf][0] = packbf(e0, e1);
            pl[nf][1] = packbf(e2, e3);
        }
        #pragma unroll
        for (int kf = 0; kf < 4; kf++) {
            uint32_t pah[4] = {ph[2 * kf][0], ph[2 * kf][1], ph[2 * kf + 1][0], ph[2 * kf + 1][1]};
            uint32_t pal[4] = {pl[2 * kf][0], pl[2 * kf][1], pl[2 * kf + 1][0], pl[2 * kf + 1][1]};
            int vr = kf * 16 + arl;
            #pragma unroll
            for (int dp = 0; dp < 4; dp++) {
                uint32_t vh[4], vl[4];
                ldsm4t(vh, Vu + vr * 256 + (((dp * 2 + akc) ^ (vr & 7)) << 4));
                ldsm4t(vl, Vu + vr * 256 + (((8 + dp * 2 + akc) ^ (vr & 7)) << 4));
                mma2(accO[2 * dp], pah, vh[0], vh[1]);
                mma2(accO[2 * dp], pal, vh[0], vh[1]);
                mma2(accO[2 * dp], pah, vl[0], vl[1]);
                mma2(accO[2 * dp + 1], pah, vh[2], vh[3]);
                mma2(accO[2 * dp + 1], pal, vh[2], vh[3]);
                mma2(accO[2 * dp + 1], pah, vl[2], vl[3]);
            }
        }
        __syncthreads();
        if (kt + 2 < SEQ / 64) loadKV(kt + 2, st);
        else CPA_COMMIT();
    }
    #pragma unroll
    for (int o = 1; o <= 2; o <<= 1) {
        l0 += __shfl_xor_sync(0xffffffffu, l0, o);
        l1 += __shfl_xor_sync(0xffffffffu, l1, o);
    }
    float i0 = 1.f / l0, i1 = 1.f / l1;
    int r0 = q0 + w * 16 + quad;
    #pragma unroll
    for (int nf = 0; nf < 8; nf++) {
        int col = h * 64 + nf * 8 + tq * 2;
        put_cat2(g_ocat + (size_t)(b * SEQ + r0) * 2048 + col, DIM,
                 accO[nf][0] * i0, accO[nf][1] * i0);
        put_cat2(g_ocat + (size_t)(b * SEQ + r0 + 8) * 2048 + col, DIM,
                 accO[nf][2] * i1, accO[nf][3] * i1);
    }
}

// ---------------- gating ----------------
__global__ __launch_bounds__(128) void gate_kernel(const float* __restrict__ gate_w) {
    int t = blockIdx.x * 4 + (threadIdx.x >> 5);
    int lane = threadIdx.x & 31;
    const float* xr = g_h2 + (size_t)t * DIM;
    float p[8];
    #pragma unroll
    for (int e = 0; e < 8; e++) p[e] = 0.f;
    for (int it = 0; it < 32; it++) {
        int d = it * 32 + lane;
        float xv = xr[d];
        const float4* gw = (const float4*)(gate_w + d * 8);
        float4 g0 = gw[0], g1 = gw[1];
        p[0] += xv * g0.x; p[1] += xv * g0.y; p[2] += xv * g0.z; p[3] += xv * g0.w;
        p[4] += xv * g1.x; p[5] += xv * g1.y; p[6] += xv * g1.z; p[7] += xv * g1.w;
    }
    #pragma unroll
    for (int e = 0; e < 8; e++)
        #pragma unroll
        for (int o = 16; o; o >>= 1) p[e] += __shfl_xor_sync(0xffffffffu, p[e], o);
    if (lane == 0) {
        float mx = p[0];
        #pragma unroll
        for (int e = 1; e < 8; e++) mx = fmaxf(mx, p[e]);
        float ex[8], sum = 0.f;
        #pragma unroll
        for (int e = 0; e < 8; e++) { ex[e] = __expf(p[e] - mx); sum += ex[e]; }
        float inv = 1.f / sum;
        float pr[8];
        #pragma unroll
        for (int e = 0; e < 8; e++) { pr[e] = ex[e] * inv; g_probs[t * 8 + e] = pr[e]; }
        int i1 = 0;
        float v1 = pr[0];
        #pragma unroll
        for (int e = 1; e < 8; e++) if (pr[e] > v1) { v1 = pr[e]; i1 = e; }
        int i2 = -1;
        float v2 = -1.f;
        #pragma unroll
        for (int e = 0; e < 8; e++) if (e != i1 && pr[e] > v2) { v2 = pr[e]; i2 = e; }
        float dn = 1.f / (v1 + v2);
        g_eid[t] = i1;
        g_eid[TKN + t] = i2;
        g_wflat[t] = v1 * dn;
        g_wflat[TKN + t] = v2 * dn;
    }
}

// ---------------- per-expert positions + counts ----------------
__global__ void pos_kernel() {
    int e = threadIdx.x >> 5;
    int lane = threadIdx.x & 31;
    int base = 0;
    for (int a0 = 0; a0 < NA; a0 += 32) {
        int ea = g_eid[a0 + lane];
        unsigned mask = __ballot_sync(0xffffffffu, ea == e);
        if (ea == e) g_pos[a0 + lane] = base + __popc(mask & ((1u << lane) - 1));
        base += __popc(mask);
    }
    if (lane == 0) g_cnt[e] = base;
}

// ---------------- scatter tokens (split bf16) into capacity buffer ----------------
__global__ __launch_bounds__(256) void scatter_kernel() {
    int a = blockIdx.x;
    int p = g_pos[a];
    if (p >= CAP) return;
    int e = g_eid[a];
    int tok = a & (TKN - 1);
    float4 v = ((const float4*)(g_h2 + (size_t)tok * DIM))[threadIdx.x];
    __nv_bfloat16* dst = g_bufcat + ((size_t)e * CAP + p) * 2048 + threadIdx.x * 4;
    put_cat2(dst, DIM, v.x, v.y);
    put_cat2(dst + 2, DIM, v.z, v.w);
}

// ---------------- aux loss ----------------
__global__ __launch_bounds__(256) void aux_kernel(float* __restrict__ out, int out_size) {
    __shared__ float red[256];
    int tid = threadIdx.x;
    float me[8], cnt[8];
    #pragma unroll
    for (int e = 0; e < 8; e++) { me[e] = 0.f; cnt[e] = 0.f; }
    for (int t = tid; t < TKN; t += 256) {
        #pragma unroll
        for (int e = 0; e < 8; e++) me[e] += g_probs[t * 8 + e];
    }
    for (int a = tid; a < NA; a += 256) cnt[g_eid[a]] += 1.f;
    float auxv = 0.f;
    for (int e = 0; e < 8; e++) {
        red[tid] = me[e];
        __syncthreads();
        for (int st = 128; st; st >>= 1) { if (tid < st) red[tid] += red[tid + st]; __syncthreads(); }
        float meS = red[0];
        __syncthreads();
        red[tid] = cnt[e];
        __syncthreads();
        for (int st = 128; st; st >>= 1) { if (tid < st) red[tid] += red[tid + st]; __syncthreads(); }
        float cS = red[0];
        __syncthreads();
        auxv += (meS / (float)TKN) * (cS / (float)NA);
    }
    if (tid == 0 && out_size > TKN * DIM) out[TKN * DIM] = 8.f * auxv;
}

// ---------------- combine ----------------
__global__ __launch_bounds__(256) void final_kernel(float* __restrict__ out) {
    int t = blockIdx.x;
    int tid = threadIdx.x;
    int p1 = g_pos[t], p2 = g_pos[TKN + t];
    int e1 = g_eid[t], e2 = g_eid[TKN + t];
    float w1 = (p1 < CAP) ? g_wflat[t] : 0.f;
    float w2 = (p2 < CAP) ? g_wflat[TKN + t] : 0.f;
    p1 = min(p1, CAP - 1);
    p2 = min(p2, CAP - 1);
    const float4* a = (const float4*)(g_oute + ((size_t)e1 * CAP + p1) * DIM);
    const float4* b = (const float4*)(g_oute + ((size_t)e2 * CAP + p2) * DIM);
    const float4* xr = (const float4*)(g_x2 + (size_t)t * DIM);
    float4 av = a[tid], bv = b[tid], xv = xr[tid];
    float4 r;
    r.x = xv.x + w1 * av.x + w2 * bv.x;
    r.y = xv.y + w1 * av.y + w2 * bv.y;
    r.z = xv.z + w1 * av.z + w2 * bv.z;
    r.w = xv.w + w1 * av.w + w2 * bv.w;
    ((float4*)(out + (size_t)t * DIM))[tid] = r;
}

// ---------------- host ----------------
extern "C" void kernel_launch(void* const* d_in, const int* in_sizes, int n_in,
                              void* d_out, int out_size) {
    const float* x     = (const float*)d_in[0];
    const float* cosT  = (const float*)d_in[1];
    const float* sinT  = (const float*)d_in[2];
    const float* ln1g  = (const float*)d_in[3];
    const float* ln1b  = (const float*)d_in[4];
    const float* ln2g  = (const float*)d_in[5];
    const float* ln2b  = (const float*)d_in[6];
    const float* wqkv  = (const float*)d_in[7];
    const float* bqkv  = (const float*)d_in[8];
    const float* wo    = (const float*)d_in[9];
    const float* bo    = (const float*)d_in[10];
    const float* gatew = (const float*)d_in[11];
    const float* w1    = (const float*)d_in[12];
    const float* b1    = (const float*)d_in[13];
    const float* w2    = (const float*)d_in[14];
    const float* b2    = (const float*)d_in[15];
    float* out = (float*)d_out;

    void *p_x2, *p_h2, *p_oute, *p_cnt;
    void *p_acat, *p_ocat, *p_bufcat, *p_hhcat, *p_wqkvc, *p_woc, *p_w1c, *p_w2c;
    cudaGetSymbolAddress(&p_x2, g_x2);
    cudaGetSymbolAddress(&p_h2, g_h2);
    cudaGetSymbolAddress(&p_oute, g_oute);
    cudaGetSymbolAddress(&p_cnt, g_cnt);
    cudaGetSymbolAddress(&p_acat, g_acat);
    cudaGetSymbolAddress(&p_ocat, g_ocat);
    cudaGetSymbolAddress(&p_bufcat, g_bufcat);
    cudaGetSymbolAddress(&p_hhcat, g_hhcat);
    cudaGetSymbolAddress(&p_wqkvc, g_wqkvcat);
    cudaGetSymbolAddress(&p_woc, g_wocat);
    cudaGetSymbolAddress(&p_w1c, g_w1cat);
    cudaGetSymbolAddress(&p_w2c, g_w2cat);

    static int init_done = 0;
    static cudaStream_t s1, s2;
    static cudaEvent_t e0, e1, e2, e3, e4;
    if (!init_done) {
        cudaFuncSetAttribute(tgemm<EPI_PLAIN>, cudaFuncAttributeMaxDynamicSharedMemorySize, GSMEM);
        cudaFuncSetAttribute(tgemm<EPI_WO>, cudaFuncAttributeMaxDynamicSharedMemorySize, GSMEM);
        cudaFuncSetAttribute(tgemm<EPI_W1>, cudaFuncAttributeMaxDynamicSharedMemorySize, GSMEM);
        cudaFuncSetAttribute(tgemm<EPI_QKV>, cudaFuncAttributeMaxDynamicSharedMemorySize, GSMEM);
        cudaFuncSetAttribute(flash3_kernel, cudaFuncAttributeMaxDynamicSharedMemorySize, FSMEM);
        cudaStreamCreateWithFlags(&s1, cudaStreamNonBlocking);
        cudaStreamCreateWithFlags(&s2, cudaStreamNonBlocking);
        cudaEventCreateWithFlags(&e0, cudaEventDisableTiming);
        cudaEventCreateWithFlags(&e1, cudaEventDisableTiming);
        cudaEventCreateWithFlags(&e2, cudaEventDisableTiming);
        cudaEventCreateWithFlags(&e3, cudaEventDisableTiming);
        cudaEventCreateWithFlags(&e4, cudaEventDisableTiming);
        init_done = 1;
    }

    // fork side streams off the main (captured) stream
    cudaEventRecord(e0, 0);
    cudaStreamWaitEvent(s1, e0, 0);
    cudaStreamWaitEvent(s2, e0, 0);

    // s1: heavy weight conversions (DRAM-bound) — overlap with qkv GEMM + flash
    wconv_kernel<<<dim3(32, 16, 1), 256, 0, s1>>>(wo, (__nv_bfloat16*)p_woc, 1024, 1024, 0, 0);
    wconv_kernel<<<dim3(128, 16, 8), 256, 0, s1>>>(w1, (__nv_bfloat16*)p_w1c, 1024, 4096,
                                                   (size_t)DIM * HID, (size_t)HID * 2048);
    wconv_kernel<<<dim3(32, 64, 8), 256, 0, s1>>>(w2, (__nv_bfloat16*)p_w2c, 4096, 1024,
                                                  (size_t)HID * DIM, (size_t)DIM * 8192);
    cudaEventRecord(e1, s1);

    // s2: ln1 (concurrent with wconv_qkv on main stream)
    ln_kernel<true><<<TKN, 256, 0, s2>>>(x, ln1g, ln1b, nullptr, (__nv_bfloat16*)p_acat);
    cudaEventRecord(e2, s2);

    // main: qkv weight conversion, then qkv GEMM (RoPE + q/k/v split fused into epilogue)
    wconv_kernel<<<dim3(96, 16, 1), 256>>>(wqkv, (__nv_bfloat16*)p_wqkvc, 1024, 3072, 0, 0);
    cudaStreamWaitEvent(0, e2, 0);
    tgemm<EPI_QKV><<<dim3(12, 32, 1), 256, GSMEM>>>(
        (const __nv_bfloat16*)p_acat, (const __nv_bfloat16*)p_wqkvc, bqkv, nullptr,
        nullptr, nullptr, 1024, 3072, 0, 0, 0, 0, 0, nullptr, cosT, sinT);
    flash3_kernel<<<dim3(SEQ / 128, NH, 2), 256, FSMEM>>>();
    // wo GEMM needs g_wocat from s1
    cudaStreamWaitEvent(0, e1, 0);
    tgemm<EPI_WO><<<dim3(4, 32, 1), 256, GSMEM>>>(
        (const __nv_bfloat16*)p_ocat, (const __nv_bfloat16*)p_woc, bo, x,
        (float*)p_x2, nullptr, 1024, 1024, 0, 0, 0, 0, 0, nullptr, nullptr, nullptr);
    ln_kernel<false><<<TKN, 256>>>((const float*)p_x2, ln2g, ln2b, (float*)p_h2, nullptr);
    gate_kernel<<<TKN / 4, 128>>>(gatew);
    pos_kernel<<<1, 256>>>();
    // aux only needs probs + eid: run on s2 concurrent with scatter + MoE GEMMs
    cudaEventRecord(e3, 0);
    cudaStreamWaitEvent(s2, e3, 0);
    aux_kernel<<<1, 256, 0, s2>>>(out, out_size);
    cudaEventRecord(e4, s2);
    // main: scatter + expert FFN
    scatter_kernel<<<NA, 256>>>();
    tgemm<EPI_W1><<<dim3(16, 10, 8), 256, GSMEM>>>(
        (const __nv_bfloat16*)p_bufcat, (const __nv_bfloat16*)p_w1c, b1, nullptr,
        nullptr, (__nv_bfloat16*)p_hhcat, 1024, 0, HID,
        (size_t)CAP * 2048, (size_t)HID * 2048, (size_t)HID, (size_t)CAP * 8192,
        (const int*)p_cnt, nullptr, nullptr);
    tgemm<EPI_PLAIN><<<dim3(4, 10, 8), 256, GSMEM>>>(
        (const __nv_bfloat16*)p_hhcat, (const __nv_bfloat16*)p_w2c, b2, nullptr,
        (float*)p_oute, nullptr, 4096, 1024, 0,
        (size_t)CAP * 8192, (size_t)DIM * 8192, (size_t)DIM, (size_t)CAP * DIM,
        (const int*)p_cnt, nullptr, nullptr);
    final_kernel<<<TKN, 256>>>(out);
    // join aux back into the main stream before capture ends
    cudaStreamWaitEvent(0, e4, 0);
}

// round 16
// speedup vs baseline: 4.0277x; 1.2735x over previous
#include <cuda_runtime.h>
#include <cuda_bf16.h>
#include <cuda_fp16.h>
#include <math.h>
#include <stdint.h>

#define TKN 4096
#define SEQ 2048
#define DIM 1024
#define NH 16
#define NE 8
#define HID 4096
#define CAP 1280
#define NA 8192

// ---------------- scratch ----------------
__device__ float g_x2[TKN * DIM];
__device__ float g_h2[TKN * DIM];
__device__ float g_probs[TKN * NE];
__device__ int   g_eid[NA];
__device__ float g_wflat[NA];
__device__ int   g_pos[NA];
__device__ int   g_cnt[NE];
__device__ float g_oute[NE * CAP * DIM];

// bf16 [hi|lo] split buffers (row stride = 2*K) for attention-side GEMMs
__device__ __nv_bfloat16 g_acat[(size_t)TKN * 2048];
__device__ __nv_bfloat16 g_ocat[(size_t)TKN * 2048];
__device__ __nv_bfloat16 g_wqkvcat[(size_t)3072 * 2048];
__device__ __nv_bfloat16 g_wocat[(size_t)1024 * 2048];
// fp16 MoE buffers: activations hi-only (stride K), weights [hi|lo] (stride 2K)
__device__ __half g_bufh[(size_t)NE * CAP * 1024];
__device__ __half g_hhh[(size_t)NE * CAP * 4096];
__device__ __half g_w1h[(size_t)NE * HID * 2048];
__device__ __half g_w2h[(size_t)NE * DIM * 8192];
// pre-split attention operands: [b*NH+h][seq][128] = hi(64) | lo(64)
__device__ __nv_bfloat16 g_qs[(size_t)2 * NH * SEQ * 128];
__device__ __nv_bfloat16 g_ks[(size_t)2 * NH * SEQ * 128];
__device__ __nv_bfloat16 g_vs[(size_t)2 * NH * SEQ * 128];

// ---------------- helpers ----------------
__device__ __forceinline__ uint32_t smem_u32(const void* p) {
    uint32_t a;
    asm("{ .reg .u64 t; cvta.to.shared.u64 t, %1; cvt.u32.u64 %0, t; }" : "=r"(a) : "l"(p));
    return a;
}
__device__ __forceinline__ void ldsm4(uint32_t* r, uint32_t a) {
    asm volatile("ldmatrix.sync.aligned.m8n8.x4.shared.b16 {%0,%1,%2,%3}, [%4];"
                 : "=r"(r[0]), "=r"(r[1]), "=r"(r[2]), "=r"(r[3]) : "r"(a));
}
__device__ __forceinline__ void ldsm4t(uint32_t* r, uint32_t a) {
    asm volatile("ldmatrix.sync.aligned.m8n8.x4.trans.shared.b16 {%0,%1,%2,%3}, [%4];"
                 : "=r"(r[0]), "=r"(r[1]), "=r"(r[2]), "=r"(r[3]) : "r"(a));
}
__device__ __forceinline__ void mma2(float* c, const uint32_t* a, uint32_t b0, uint32_t b1) {
    asm volatile(
        "mma.sync.aligned.m16n8k16.row.col.f32.bf16.bf16.f32 "
        "{%0,%1,%2,%3}, {%4,%5,%6,%7}, {%8,%9}, {%0,%1,%2,%3};"
        : "+f"(c[0]), "+f"(c[1]), "+f"(c[2]), "+f"(c[3])
        : "r"(a[0]), "r"(a[1]), "r"(a[2]), "r"(a[3]), "r"(b0), "r"(b1));
}
__device__ __forceinline__ void mma2h(float* c, const uint32_t* a, uint32_t b0, uint32_t b1) {
    asm volatile(
        "mma.sync.aligned.m16n8k16.row.col.f32.f16.f16.f32 "
        "{%0,%1,%2,%3}, {%4,%5,%6,%7}, {%8,%9}, {%0,%1,%2,%3};"
        : "+f"(c[0]), "+f"(c[1]), "+f"(c[2]), "+f"(c[3])
        : "r"(a[0]), "r"(a[1]), "r"(a[2]), "r"(a[3]), "r"(b0), "r"(b1));
}
__device__ __forceinline__ void cpa16(uint32_t dst, const void* src) {
    asm volatile("cp.async.cg.shared.global [%0], [%1], 16;" :: "r"(dst), "l"(src));
}
#define CPA_COMMIT() asm volatile("cp.async.commit_group;")
#define CPA_WAIT2()  asm volatile("cp.async.wait_group 2;")
#define CPA_WAIT1()  asm volatile("cp.async.wait_group 1;")

__device__ __forceinline__ float gelu_f(float x) {
    float x3 = x * x * x;
    float t = tanhf(0.7978845608028654f * (x + 0.044715f * x3));
    return 0.5f * x * (1.0f + t);
}
__device__ __forceinline__ void split1(float v, __nv_bfloat16& hi, __nv_bfloat16& lo) {
    hi = __float2bfloat16(v);
    lo = __float2bfloat16(v - __bfloat162float(hi));
}
__device__ __forceinline__ uint32_t packbf(__nv_bfloat16 a, __nv_bfloat16 b) {
    return ((uint32_t)__bfloat16_as_ushort(b) << 16) | __bfloat16_as_ushort(a);
}
__device__ __forceinline__ uint32_t packh(__half a, __half b) {
    return ((uint32_t)__half_as_ushort(b) << 16) | __half_as_ushort(a);
}
// write split pair into bf16 [hi | lo] layout, slabs of `stride`
__device__ __forceinline__ void put_cat2(__nv_bfloat16* p, int stride, float a, float b) {
    __nv_bfloat16 ah, al, bh, bl;
    split1(a, ah, al);
    split1(b, bh, bl);
    __nv_bfloat162 hi; hi.x = ah; hi.y = bh;
    __nv_bfloat162 lo; lo.x = al; lo.y = bl;
    *(__nv_bfloat162*)(p) = hi;
    *(__nv_bfloat162*)(p + stride) = lo;
}

// ---------------- weight transpose + split bf16: W[K][N] -> Wt[N][2K] = [hi|lo] ----------------
__global__ __launch_bounds__(256) void wconv_kernel(const float* __restrict__ W,
                                                    __nv_bfloat16* __restrict__ Wt,
                                                    int K, int N, size_t wOff, size_t oOff) {
    int z = blockIdx.z;
    W += wOff * z; Wt += oOff * z;
    __shared__ float t[64][33];
    int n0 = blockIdx.x * 32, k0 = blockIdx.y * 64;
    int tid = threadIdx.x;
    #pragma unroll
    for (int i = 0; i < 8; i++) {
        int id = tid + i * 256;
        int k = id >> 5, n = id & 31;
        t[k][n] = W[(size_t)(k0 + k) * N + n0 + n];
    }
    __syncthreads();
    int n = tid >> 3, kq = tid & 7;
    uint32_t hw[4], lw[4];
    #pragma unroll
    for (int j = 0; j < 4; j++) {
        float a = t[kq * 8 + 2 * j][n], b = t[kq * 8 + 2 * j + 1][n];
        __nv_bfloat16 ah, al, bh, bl;
        split1(a, ah, al);
        split1(b, bl = __nv_bfloat16(), bl);   // placeholder to silence unused warn
        split1(b, bh, bl);
        hw[j] = packbf(ah, bh);
        lw[j] = packbf(al, bl);
    }
    __nv_bfloat16* p = Wt + (size_t)(n0 + n) * 2 * K + k0 + kq * 8;
    *(uint4*)p = make_uint4(hw[0], hw[1], hw[2], hw[3]);
    *(uint4*)(p + K) = make_uint4(lw[0], lw[1], lw[2], lw[3]);
}

// ---------------- weight transpose + split fp16: W[K][N] -> Wt[N][2K] = [hi|lo] ----------------
__global__ __launch_bounds__(256) void wconvh_kernel(const float* __restrict__ W,
                                                     __half* __restrict__ Wt,
                                                     int K, int N, size_t wOff, size_t oOff) {
    int z = blockIdx.z;
    W += wOff * z; Wt += oOff * z;
    __shared__ float t[64][33];
    int n0 = blockIdx.x * 32, k0 = blockIdx.y * 64;
    int tid = threadIdx.x;
    #pragma unroll
    for (int i = 0; i < 8; i++) {
        int id = tid + i * 256;
        int k = id >> 5, n = id & 31;
        t[k][n] = W[(size_t)(k0 + k) * N + n0 + n];
    }
    __syncthreads();
    int n = tid >> 3, kq = tid & 7;
    uint32_t hw[4], lw[4];
    #pragma unroll
    for (int j = 0; j < 4; j++) {
        float a = t[kq * 8 + 2 * j][n], b = t[kq * 8 + 2 * j + 1][n];
        __half ah = __float2half(a);
        __half bh = __float2half(b);
        __half al = __float2half(a - __half2float(ah));
        __half bl = __float2half(b - __half2float(bh));
        hw[j] = packh(ah, bh);
        lw[j] = packh(al, bl);
    }
    __half* p = Wt + (size_t)(n0 + n) * 2 * K + k0 + kq * 8;
    *(uint4*)p = make_uint4(hw[0], hw[1], hw[2], hw[3]);
    *(uint4*)(p + K) = make_uint4(lw[0], lw[1], lw[2], lw[3]);
}

// ---------------- layernorm ----------------
template <bool CAT>
__global__ __launch_bounds__(256) void ln_kernel(const float* __restrict__ x,
                                                 const float* __restrict__ g,
                                                 const float* __restrict__ b,
                                                 float* __restrict__ outf,
                                                 __nv_bfloat16* __restrict__ outc) {
    int row = blockIdx.x, tid = threadIdx.x;
    const float4* xr = (const float4*)(x + (size_t)row * DIM);
    float4 v = xr[tid];
    float s = v.x + v.y + v.z + v.w;
    float q = v.x * v.x + v.y * v.y + v.z * v.z + v.w * v.w;
    __shared__ float ss[8], sq[8];
    #pragma unroll
    for (int o = 16; o; o >>= 1) {
        s += __shfl_xor_sync(0xffffffffu, s, o);
        q += __shfl_xor_sync(0xffffffffu, q, o);
    }
    int w = tid >> 5;
    if ((tid & 31) == 0) { ss[w] = s; sq[w] = q; }
    __syncthreads();
    __shared__ float mu_s, rs_s;
    if (tid == 0) {
        float S = 0.f, Q = 0.f;
        #pragma unroll
        for (int i = 0; i < 8; i++) { S += ss[i]; Q += sq[i]; }
        float mu = S / DIM;
        mu_s = mu;
        rs_s = rsqrtf(Q / DIM - mu * mu + 1e-6f);
    }
    __syncthreads();
    float mu = mu_s, rs = rs_s;
    float4 gg = ((const float4*)g)[tid];
    float4 bb = ((const float4*)b)[tid];
    float4 o4;
    o4.x = (v.x - mu) * rs * gg.x + bb.x;
    o4.y = (v.y - mu) * rs * gg.y + bb.y;
    o4.z = (v.z - mu) * rs * gg.z + bb.z;
    o4.w = (v.w - mu) * rs * gg.w + bb.w;
    if (CAT) {
        __nv_bfloat16* p = outc + (size_t)row * 2048 + tid * 4;
        put_cat2(p, DIM, o4.x, o4.y);
        put_cat2(p + 2, DIM, o4.z, o4.w);
    } else {
        ((float4*)(outf + (size_t)row * DIM))[tid] = o4;
    }
}

// ---------------- HMMA GEMM ----------------
// H=0: bf16 3-term (A [hi|lo] stride 2K, logical [hi|lo|hi]; B [hi|lo] stride 2K, logical [hi|hi|lo])
// H=1: fp16 2-term (A hi-only stride K, logical [hi|hi]; B [hi|lo] stride 2K, logical = physical)
#define EPI_PLAIN 0
#define EPI_WO 1
#define EPI_W1 2
#define EPI_QKV 3
#define STAGE_BYTES 49152
#define GSMEM (4 * STAGE_BYTES)

template <int EPI, int H>
__global__ __launch_bounds__(256, 1) void tgemm(
    const void* __restrict__ A_, const void* __restrict__ Bt_,
    const float* __restrict__ bias, const float* __restrict__ res,
    float* __restrict__ Cf, void* __restrict__ Cb_,
    int Klog, int Nstr, int HIDN,
    size_t aOff, size_t bOff, size_t biasOff, size_t cOff,
    const int* __restrict__ cnt,
    const float* __restrict__ cosT, const float* __restrict__ sinT) {
    extern __shared__ __align__(1024) char smem[];
    const uint32_t sb = smem_u32(smem);
    const int tid = threadIdx.x;
    const int z = blockIdx.z;
    const int m0 = blockIdx.y * 128;
    if (cnt != nullptr && m0 >= cnt[z]) return;
    const int astr = H ? Klog : 2 * Klog;
    const int bstr = 2 * Klog;
    const char* Ab = (const char*)A_ + aOff * z * 2;
    const char* Bb = (const char*)Bt_ + bOff * z * 2;
    bias += biasOff * z;
    __half* Cbh = (__half*)Cb_ + cOff * z;
    Cf += (EPI == EPI_W1) ? 0 : cOff * z;
    const int n0 = blockIdx.x * 256;
    const int nterm = H ? 2 : 3;
    const int nk = (nterm * Klog) >> 6;

    auto loadStage = [&](int kt, int ss) {
        uint32_t sbase = sb + ss * STAGE_BYTES;
        int kb = kt << 6;
        int akb, bkb;
        if (H) {
            akb = kb < Klog ? kb : kb - Klog;
            bkb = kb;
        } else {
            akb = kb < 2 * Klog ? kb : kb - 2 * Klog;
            bkb = kb < Klog ? kb : kb - Klog;
        }
        const char* Ag = Ab + ((size_t)m0 * astr + akb) * 2;
        #pragma unroll
        for (int i = 0; i < 4; i++) {
            int id = tid + i * 256;
            int r = id >> 3, c = id & 7;
            cpa16(sbase + r * 128 + ((c ^ (r & 7)) << 4), Ag + ((size_t)r * astr + c * 8) * 2);
        }
        const char* Bg = Bb + ((size_t)n0 * bstr + bkb) * 2;
        #pragma unroll
        for (int i = 0; i < 8; i++) {
            int id = tid + i * 256;
            int r = id >> 3, c = id & 7;
            cpa16(sbase + 16384 + r * 128 + ((c ^ (r & 7)) << 4), Bg + ((size_t)r * bstr + c * 8) * 2);
        }
        CPA_COMMIT();
    };

    loadStage(0, 0);
    loadStage(1, 1);
    loadStage(2, 2);

    const int lane = tid & 31, wid = tid >> 5;
    const int wm = wid >> 2, wn = wid & 3;
    const int arl = lane & 15, akc = lane >> 4;

    int arow[4];
    #pragma unroll
    for (int mf = 0; mf < 4; mf++) arow[mf] = wm * 64 + mf * 16 + arl;

    float acc[4][8][4];
    #pragma unroll
    for (int mf = 0; mf < 4; mf++)
        #pragma unroll
        for (int nf = 0; nf < 8; nf++)
            #pragma unroll
            for (int i = 0; i < 4; i++) acc[mf][nf][i] = 0.f;

    for (int kt = 0; kt < nk; kt++) {
        CPA_WAIT2();
        __syncthreads();
        if (kt + 3 < nk) loadStage(kt + 3, (kt + 3) & 3);
        else CPA_COMMIT();
        int ss = kt & 3;
        uint32_t Au = sb + ss * STAGE_BYTES;
        uint32_t Bu = Au + 16384;
        #pragma unroll
        for (int j = 0; j < 4; j++) {
            uint32_t af[4][4];
            #pragma unroll
            for (int mf = 0; mf < 4; mf++) {
                int r = arow[mf];
                ldsm4(af[mf], Au + r * 128 + (((j * 2 + akc) ^ (r & 7)) << 4));
            }
            uint32_t bf[4][4];
            #pragma unroll
            for (int pr = 0; pr < 4; pr++) {
                int r = wn * 64 + pr * 16 + arl;
                ldsm4(bf[pr], Bu + r * 128 + (((j * 2 + akc) ^ (r & 7)) << 4));
            }
            #pragma unroll
            for (int mf = 0; mf < 4; mf++)
                #pragma unroll
                for (int pr = 0; pr < 4; pr++) {
                    if (H) {
                        mma2h(acc[mf][2 * pr], af[mf], bf[pr][0], bf[pr][2]);
                        mma2h(acc[mf][2 * pr + 1], af[mf], bf[pr][1], bf[pr][3]);
                    } else {
                        mma2(acc[mf][2 * pr], af[mf], bf[pr][0], bf[pr][2]);
                        mma2(acc[mf][2 * pr + 1], af[mf], bf[pr][1], bf[pr][3]);
                    }
                }
        }
    }

    const int quad = lane >> 2, tq = lane & 3;
    if (EPI == EPI_QKV && n0 < 2048) {
        __nv_bfloat16* base = (n0 < 1024) ? g_qs : g_ks;
        #pragma unroll
        for (int mf = 0; mf < 4; mf++) {
            int m = m0 + wm * 64 + mf * 16 + quad;
            #pragma unroll
            for (int nf = 0; nf < 4; nf++) {
                int n = n0 + wn * 64 + nf * 8 + tq * 2;
                int h = (n & 1023) >> 6;
                int cc = n & 63;
                const float* cA = acc[mf][nf];
                const float* cC = acc[mf][nf + 4];
                float b0 = bias[n], b1 = bias[n + 1];
                float b2 = bias[n + 32], b3 = bias[n + 33];
                #pragma unroll
                for (int half = 0; half < 2; half++) {
                    int mr = m + half * 8;
                    int s = mr & (SEQ - 1), bb = mr >> 11;
                    float a0 = cA[2 * half + 0] + b0;
                    float a1 = cA[2 * half + 1] + b1;
                    float g0 = cC[2 * half + 0] + b2;
                    float g1 = cC[2 * half + 1] + b3;
                    const float* cr = cosT + s * 64;
                    const float* sr = sinT + s * 64;
                    float na0 = a0 * cr[cc] - g0 * sr[cc];
                    float na1 = a1 * cr[cc + 1] - g1 * sr[cc + 1];
                    float nc0 = g0 * cr[cc + 32] + a0 * sr[cc + 32];
                    float nc1 = g1 * cr[cc + 33] + a1 * sr[cc + 33];
                    __nv_bfloat16* D = base + ((size_t)(bb * NH + h) * SEQ + s) * 128;
                    put_cat2(D + cc, 64, na0, na1);
                    put_cat2(D + cc + 32, 64, nc0, nc1);
                }
            }
        }
        return;
    }
    #pragma unroll
    for (int mf = 0; mf < 4; mf++) {
        #pragma unroll
        for (int nf = 0; nf < 8; nf++) {
            int m = m0 + wm * 64 + mf * 16 + quad;
            int n = n0 + wn * 64 + nf * 8 + tq * 2;
            const float* c = acc[mf][nf];
            float b0 = bias[n], b1 = bias[n + 1];
            if (EPI == EPI_W1) {
                // hi-only fp16 output
                __half2 u = __floats2half2_rn(gelu_f(c[0] + b0), gelu_f(c[1] + b1));
                *(__half2*)(Cbh + (size_t)m * HIDN + n) = u;
                __half2 v = __floats2half2_rn(gelu_f(c[2] + b0), gelu_f(c[3] + b1));
                *(__half2*)(Cbh + (size_t)(m + 8) * HIDN + n) = v;
            } else {
                float2 v = make_float2(c[0] + b0, c[1] + b1);
                float2 w = make_float2(c[2] + b0, c[3] + b1);
                if (EPI == EPI_WO) {
                    float2 r1 = *(const float2*)&res[(size_t)m * Nstr + n];
                    float2 r2 = *(const float2*)&res[(size_t)(m + 8) * Nstr + n];
                    v.x += r1.x; v.y += r1.y;
                    w.x += r2.x; w.y += r2.y;
                }
                if (EPI == EPI_QKV) {
                    int h = (n - 2048) >> 6, cc = (n - 2048) & 63;
                    int b_ = m >> 11, s = m & (SEQ - 1);
                    __nv_bfloat16* D = g_vs + ((size_t)(b_ * NH + h) * SEQ + s) * 128;
                    put_cat2(D + cc, 64, v.x, v.y);
                    int b2_ = (m + 8) >> 11, s2 = (m + 8) & (SEQ - 1);
                    __nv_bfloat16* D2 = g_vs + ((size_t)(b2_ * NH + h) * SEQ + s2) * 128;
                    put_cat2(D2 + cc, 64, w.x, w.y);
                } else {
                    *(float2*)&Cf[(size_t)m * Nstr + n] = v;
                    *(float2*)&Cf[(size_t)(m + 8) * Nstr + n] = w;
                }
            }
        }
    }
}

// ---------------- HMMA flash attention ----------------
#define FSMEM 98304
__global__ __launch_bounds__(256, 2) void flash3_kernel() {
    extern __shared__ __align__(1024) char fsm[];
    const uint32_t Qu = smem_u32(fsm);
    const int b = blockIdx.z, h = blockIdx.y, q0 = blockIdx.x * 128;
    const int tid = threadIdx.x, lane = tid & 31, w = tid >> 5;
    const int arl = lane & 15, akc = lane >> 4;
    const int tq = lane & 3, quad = lane >> 2;
    const __nv_bfloat16* qsrc = g_qs + (size_t)(b * NH + h) * SEQ * 128;
    const __nv_bfloat16* ksrc = g_ks + (size_t)(b * NH + h) * SEQ * 128;
    const __nv_bfloat16* vsrc = g_vs + (size_t)(b * NH + h) * SEQ * 128;

    #pragma unroll
    for (int i = 0; i < 8; i++) {
        int id = tid + i * 256;
        int r = id >> 4, ch = id & 15;
        cpa16(Qu + r * 256 + ((ch ^ (r & 7)) << 4), qsrc + (size_t)(q0 + r) * 128 + ch * 8);
    }
    auto loadKV = [&](int kt, int st) {
        uint32_t Ks = Qu + 32768 + st * 32768;
        #pragma unroll
        for (int i = 0; i < 4; i++) {
            int id = tid + i * 256;
            int r = id >> 4, ch = id & 15;
            cpa16(Ks + r * 256 + ((ch ^ (r & 7)) << 4), ksrc + (size_t)(kt * 64 + r) * 128 + ch * 8);
        }
        uint32_t Vs = Ks + 16384;
        #pragma unroll
        for (int i = 0; i < 4; i++) {
            int id = tid + i * 256;
            int r = id >> 4, ch = id & 15;
            cpa16(Vs + r * 256 + ((ch ^ (r & 7)) << 4), vsrc + (size_t)(kt * 64 + r) * 128 + ch * 8);
        }
        CPA_COMMIT();
    };
    loadKV(0, 0);
    loadKV(1, 1);

    float accO[8][4];
    #pragma unroll
    for (int nf = 0; nf < 8; nf++)
        #pragma unroll
        for (int i = 0; i < 4; i++) accO[nf][i] = 0.f;
    float m0 = -1e30f, m1 = -1e30f, l0 = 0.f, l1 = 0.f;
    const int qr = w * 16 + arl;

    for (int kt = 0; kt < SEQ / 64; kt++) {
        int st = kt & 1;
        CPA_WAIT1();
        __syncthreads();
        uint32_t Ku = Qu + 32768 + st * 32768;
        uint32_t Vu = Ku + 16384;

        float accS[8][4];
        #pragma unroll
        for (int nf = 0; nf < 8; nf++)
            #pragma unroll
            for (int i = 0; i < 4; i++) accS[nf][i] = 0.f;
        #pragma unroll
        for (int j = 0; j < 4; j++) {
            uint32_t ah[4], al[4];
            ldsm4(ah, Qu + qr * 256 + (((j * 2 + akc) ^ (qr & 7)) << 4));
            ldsm4(al, Qu + qr * 256 + (((8 + j * 2 + akc) ^ (qr & 7)) << 4));
            #pragma unroll
            for (int pr = 0; pr < 4; pr++) {
                int kr = pr * 16 + arl;
                uint32_t bh[4], bl[4];
                ldsm4(bh, Ku + kr * 256 + (((j * 2 + akc) ^ (kr & 7)) << 4));
                ldsm4(bl, Ku + kr * 256 + (((8 + j * 2 + akc) ^ (kr & 7)) << 4));
                mma2(accS[2 * pr], ah, bh[0], bh[2]);
                mma2(accS[2 * pr], al, bh[0], bh[2]);
                mma2(accS[2 * pr], ah, bl[0], bl[2]);
                mma2(accS[2 * pr + 1], ah, bh[1], bh[3]);
                mma2(accS[2 * pr + 1], al, bh[1], bh[3]);
                mma2(accS[2 * pr + 1], ah, bl[1], bl[3]);
            }
        }
        float mt0 = m0, mt1 = m1;
        #pragma unroll
        for (int nf = 0; nf < 8; nf++) {
            #pragma unroll
            for (int i = 0; i < 4; i++) accS[nf][i] *= 0.125f;
            mt0 = fmaxf(mt0, fmaxf(accS[nf][0], accS[nf][1]));
            mt1 = fmaxf(mt1, fmaxf(accS[nf][2], accS[nf][3]));
        }
        #pragma unroll
        for (int o = 1; o <= 2; o <<= 1) {
            mt0 = fmaxf(mt0, __shfl_xor_sync(0xffffffffu, mt0, o));
            mt1 = fmaxf(mt1, __shfl_xor_sync(0xffffffffu, mt1, o));
        }
        float c0 = __expf(m0 - mt0), c1 = __expf(m1 - mt1);
        m0 = mt0; m1 = mt1;
        l0 *= c0; l1 *= c1;
        #pragma unroll
        for (int nf = 0; nf < 8; nf++) {
            accO[nf][0] *= c0; accO[nf][1] *= c0;
            accO[nf][2] *= c1; accO[nf][3] *= c1;
        }
        uint32_t ph[8][2], pl[8][2];
        #pragma unroll
        for (int nf = 0; nf < 8; nf++) {
            float p0 = __expf(accS[nf][0] - mt0);
            float p1 = __expf(accS[nf][1] - mt0);
            float p2 = __expf(accS[nf][2] - mt1);
            float p3 = __expf(accS[nf][3] - mt1);
            l0 += p0 + p1; l1 += p2 + p3;
            __nv_bfloat16 h0, e0, h1, e1, h2, e2, h3, e3;
            split1(p0, h0, e0); split1(p1, h1, e1);
            split1(p2, h2, e2); split1(p3, h3, e3);
            ph[nf][0] = packbf(h0, h1);
            ph[nf][1] = packbf(h2, h3);
            pl[nf][0] = packbf(e0, e1);
            pl[nf][1] = packbf(e2, e3);
        }
        #pragma unroll
        for (int kf = 0; kf < 4; kf++) {
            uint32_t pah[4] = {ph[2 * kf][0], ph[2 * kf][1], ph[2 * kf + 1][0], ph[2 * kf + 1][1]};
            uint32_t pal[4] = {pl[2 * kf][0], pl[2 * kf][1], pl[2 * kf + 1][0], pl[2 * kf + 1][1]};
            int vr = kf * 16 + arl;
            #pragma unroll
            for (int dp = 0; dp < 4; dp++) {
                uint32_t vh[4], vl[4];
                ldsm4t(vh, Vu + vr * 256 + (((dp * 2 + akc) ^ (vr & 7)) << 4));
                ldsm4t(vl, Vu + vr * 256 + (((8 + dp * 2 + akc) ^ (vr & 7)) << 4));
                mma2(accO[2 * dp], pah, vh[0], vh[1]);
                mma2(accO[2 * dp], pal, vh[0], vh[1]);
                mma2(accO[2 * dp], pah, vl[0], vl[1]);
                mma2(accO[2 * dp + 1], pah, vh[2], vh[3]);
                mma2(accO[2 * dp + 1], pal, vh[2], vh[3]);
                mma2(accO[2 * dp + 1], pah, vl[2], vl[3]);
            }
        }
        __syncthreads();
        if (kt + 2 < SEQ / 64) loadKV(kt + 2, st);
        else CPA_COMMIT();
    }
    #pragma unroll
    for (int o = 1; o <= 2; o <<= 1) {
        l0 += __shfl_xor_sync(0xffffffffu, l0, o);
        l1 += __shfl_xor_sync(0xffffffffu, l1, o);
    }
    float i0 = 1.f / l0, i1 = 1.f / l1;
    int r0 = q0 + w * 16 + quad;
    #pragma unroll
    for (int nf = 0; nf < 8; nf++) {
        int col = h * 64 + nf * 8 + tq * 2;
        put_cat2(g_ocat + (size_t)(b * SEQ + r0) * 2048 + col, DIM,
                 accO[nf][0] * i0, accO[nf][1] * i0);
        put_cat2(g_ocat + (size_t)(b * SEQ + r0 + 8) * 2048 + col, DIM,
                 accO[nf][2] * i1, accO[nf][3] * i1);
    }
}

// ---------------- gating ----------------
__global__ __launch_bounds__(128) void gate_kernel(const float* __restrict__ gate_w) {
    int t = blockIdx.x * 4 + (threadIdx.x >> 5);
    int lane = threadIdx.x & 31;
    const float* xr = g_h2 + (size_t)t * DIM;
    float p[8];
    #pragma unroll
    for (int e = 0; e < 8; e++) p[e] = 0.f;
    for (int it = 0; it < 32; it++) {
        int d = it * 32 + lane;
        float xv = xr[d];
        const float4* gw = (const float4*)(gate_w + d * 8);
        float4 g0 = gw[0], g1 = gw[1];
        p[0] += xv * g0.x; p[1] += xv * g0.y; p[2] += xv * g0.z; p[3] += xv * g0.w;
        p[4] += xv * g1.x; p[5] += xv * g1.y; p[6] += xv * g1.z; p[7] += xv * g1.w;
    }
    #pragma unroll
    for (int e = 0; e < 8; e++)
        #pragma unroll
        for (int o = 16; o; o >>= 1) p[e] += __shfl_xor_sync(0xffffffffu, p[e], o);
    if (lane == 0) {
        float mx = p[0];
        #pragma unroll
        for (int e = 1; e < 8; e++) mx = fmaxf(mx, p[e]);
        float ex[8], sum = 0.f;
        #pragma unroll
        for (int e = 0; e < 8; e++) { ex[e] = __expf(p[e] - mx); sum += ex[e]; }
        float inv = 1.f / sum;
        float pr[8];
        #pragma unroll
        for (int e = 0; e < 8; e++) { pr[e] = ex[e] * inv; g_probs[t * 8 + e] = pr[e]; }
        int i1 = 0;
        float v1 = pr[0];
        #pragma unroll
        for (int e = 1; e < 8; e++) if (pr[e] > v1) { v1 = pr[e]; i1 = e; }
        int i2 = -1;
        float v2 = -1.f;
        #pragma unroll
        for (int e = 0; e < 8; e++) if (e != i1 && pr[e] > v2) { v2 = pr[e]; i2 = e; }
        float dn = 1.f / (v1 + v2);
        g_eid[t] = i1;
        g_eid[TKN + t] = i2;
        g_wflat[t] = v1 * dn;
        g_wflat[TKN + t] = v2 * dn;
    }
}

// ---------------- per-expert positions + counts ----------------
__global__ void pos_kernel() {
    int e = threadIdx.x >> 5;
    int lane = threadIdx.x & 31;
    int base = 0;
    for (int a0 = 0; a0 < NA; a0 += 32) {
        int ea = g_eid[a0 + lane];
        unsigned mask = __ballot_sync(0xffffffffu, ea == e);
        if (ea == e) g_pos[a0 + lane] = base + __popc(mask & ((1u << lane) - 1));
        base += __popc(mask);
    }
    if (lane == 0) g_cnt[e] = base;
}

// ---------------- scatter tokens (hi-only fp16) into capacity buffer ----------------
__global__ __launch_bounds__(256) void scatter_kernel() {
    int a = blockIdx.x;
    int p = g_pos[a];
    if (p >= CAP) return;
    int e = g_eid[a];
    int tok = a & (TKN - 1);
    float4 v = ((const float4*)(g_h2 + (size_t)tok * DIM))[threadIdx.x];
    __half2 u0 = __floats2half2_rn(v.x, v.y);
    __half2 u1 = __floats2half2_rn(v.z, v.w);
    *(uint2*)(g_bufh + ((size_t)e * CAP + p) * 1024 + threadIdx.x * 4) =
        make_uint2(*(uint32_t*)&u0, *(uint32_t*)&u1);
}

// ---------------- aux loss ----------------
__global__ __launch_bounds__(256) void aux_kernel(float* __restrict__ out, int out_size) {
    __shared__ float red[256];
    int tid = threadIdx.x;
    float me[8], cnt[8];
    #pragma unroll
    for (int e = 0; e < 8; e++) { me[e] = 0.f; cnt[e] = 0.f; }
    for (int t = tid; t < TKN; t += 256) {
        #pragma unroll
        for (int e = 0; e < 8; e++) me[e] += g_probs[t * 8 + e];
    }
    for (int a = tid; a < NA; a += 256) cnt[g_eid[a]] += 1.f;
    float auxv = 0.f;
    for (int e = 0; e < 8; e++) {
        red[tid] = me[e];
        __syncthreads();
        for (int st = 128; st; st >>= 1) { if (tid < st) red[tid] += red[tid + st]; __syncthreads(); }
        float meS = red[0];
        __syncthreads();
        red[tid] = cnt[e];
        __syncthreads();
        for (int st = 128; st; st >>= 1) { if (tid < st) red[tid] += red[tid + st]; __syncthreads(); }
        float cS = red[0];
        __syncthreads();
        auxv += (meS / (float)TKN) * (cS / (float)NA);
    }
    if (tid == 0 && out_size > TKN * DIM) out[TKN * DIM] = 8.f * auxv;
}

// ---------------- combine ----------------
__global__ __launch_bounds__(256) void final_kernel(float* __restrict__ out) {
    int t = blockIdx.x;
    int tid = threadIdx.x;
    int p1 = g_pos[t], p2 = g_pos[TKN + t];
    int e1 = g_eid[t], e2 = g_eid[TKN + t];
    float w1 = (p1 < CAP) ? g_wflat[t] : 0.f;
    float w2 = (p2 < CAP) ? g_wflat[TKN + t] : 0.f;
    p1 = min(p1, CAP - 1);
    p2 = min(p2, CAP - 1);
    const float4* a = (const float4*)(g_oute + ((size_t)e1 * CAP + p1) * DIM);
    const float4* b = (const float4*)(g_oute + ((size_t)e2 * CAP + p2) * DIM);
    const float4* xr = (const float4*)(g_x2 + (size_t)t * DIM);
    float4 av = a[tid], bv = b[tid], xv = xr[tid];
    float4 r;
    r.x = xv.x + w1 * av.x + w2 * bv.x;
    r.y = xv.y + w1 * av.y + w2 * bv.y;
    r.z = xv.z + w1 * av.z + w2 * bv.z;
    r.w = xv.w + w1 * av.w + w2 * bv.w;
    ((float4*)(out + (size_t)t * DIM))[tid] = r;
}

// ---------------- host ----------------
extern "C" void kernel_launch(void* const* d_in, const int* in_sizes, int n_in,
                              void* d_out, int out_size) {
    const float* x     = (const float*)d_in[0];
    const float* cosT  = (const float*)d_in[1];
    const float* sinT  = (const float*)d_in[2];
    const float* ln1g  = (const float*)d_in[3];
    const float* ln1b  = (const float*)d_in[4];
    const float* ln2g  = (const float*)d_in[5];
    const float* ln2b  = (const float*)d_in[6];
    const float* wqkv  = (const float*)d_in[7];
    const float* bqkv  = (const float*)d_in[8];
    const float* wo    = (const float*)d_in[9];
    const float* bo    = (const float*)d_in[10];
    const float* gatew = (const float*)d_in[11];
    const float* w1    = (const float*)d_in[12];
    const float* b1    = (const float*)d_in[13];
    const float* w2    = (const float*)d_in[14];
    const float* b2    = (const float*)d_in[15];
    float* out = (float*)d_out;

    void *p_x2, *p_h2, *p_oute, *p_cnt;
    void *p_acat, *p_ocat, *p_wqkvc, *p_woc;
    void *p_bufh, *p_hhh, *p_w1h, *p_w2h;
    cudaGetSymbolAddress(&p_x2, g_x2);
    cudaGetSymbolAddress(&p_h2, g_h2);
    cudaGetSymbolAddress(&p_oute, g_oute);
    cudaGetSymbolAddress(&p_cnt, g_cnt);
    cudaGetSymbolAddress(&p_acat, g_acat);
    cudaGetSymbolAddress(&p_ocat, g_ocat);
    cudaGetSymbolAddress(&p_wqkvc, g_wqkvcat);
    cudaGetSymbolAddress(&p_woc, g_wocat);
    cudaGetSymbolAddress(&p_bufh, g_bufh);
    cudaGetSymbolAddress(&p_hhh, g_hhh);
    cudaGetSymbolAddress(&p_w1h, g_w1h);
    cudaGetSymbolAddress(&p_w2h, g_w2h);

    static int init_done = 0;
    static cudaStream_t s1, s2;
    static cudaEvent_t e0, e1, e2, e3, e4;
    if (!init_done) {
        cudaFuncSetAttribute(tgemm<EPI_QKV, 0>, cudaFuncAttributeMaxDynamicSharedMemorySize, GSMEM);
        cudaFuncSetAttribute(tgemm<EPI_WO, 0>, cudaFuncAttributeMaxDynamicSharedMemorySize, GSMEM);
        cudaFuncSetAttribute(tgemm<EPI_W1, 1>, cudaFuncAttributeMaxDynamicSharedMemorySize, GSMEM);
        cudaFuncSetAttribute(tgemm<EPI_PLAIN, 1>, cudaFuncAttributeMaxDynamicSharedMemorySize, GSMEM);
        cudaFuncSetAttribute(flash3_kernel, cudaFuncAttributeMaxDynamicSharedMemorySize, FSMEM);
        cudaStreamCreateWithFlags(&s1, cudaStreamNonBlocking);
        cudaStreamCreateWithFlags(&s2, cudaStreamNonBlocking);
        cudaEventCreateWithFlags(&e0, cudaEventDisableTiming);
        cudaEventCreateWithFlags(&e1, cudaEventDisableTiming);
        cudaEventCreateWithFlags(&e2, cudaEventDisableTiming);
        cudaEventCreateWithFlags(&e3, cudaEventDisableTiming);
        cudaEventCreateWithFlags(&e4, cudaEventDisableTiming);
        init_done = 1;
    }

    // fork side streams off the main (captured) stream
    cudaEventRecord(e0, 0);
    cudaStreamWaitEvent(s1, e0, 0);
    cudaStreamWaitEvent(s2, e0, 0);

    // s1: heavy weight conversions — overlap with qkv GEMM + flash
    wconv_kernel<<<dim3(32, 16, 1), 256, 0, s1>>>(wo, (__nv_bfloat16*)p_woc, 1024, 1024, 0, 0);
    wconvh_kernel<<<dim3(128, 16, 8), 256, 0, s1>>>(w1, (__half*)p_w1h, 1024, 4096,
                                                    (size_t)DIM * HID, (size_t)HID * 2048);
    wconvh_kernel<<<dim3(32, 64, 8), 256, 0, s1>>>(w2, (__half*)p_w2h, 4096, 1024,
                                                   (size_t)HID * DIM, (size_t)DIM * 8192);
    cudaEventRecord(e1, s1);

    // s2: ln1 (concurrent with wconv_qkv on main stream)
    ln_kernel<true><<<TKN, 256, 0, s2>>>(x, ln1g, ln1b, nullptr, (__nv_bfloat16*)p_acat);
    cudaEventRecord(e2, s2);

    // main: qkv weight conversion, then qkv GEMM (RoPE + q/k/v split fused)
    wconv_kernel<<<dim3(96, 16, 1), 256>>>(wqkv, (__nv_bfloat16*)p_wqkvc, 1024, 3072, 0, 0);
    cudaStreamWaitEvent(0, e2, 0);
    tgemm<EPI_QKV, 0><<<dim3(12, 32, 1), 256, GSMEM>>>(
        p_acat, p_wqkvc, bqkv, nullptr, nullptr, nullptr,
        1024, 3072, 0, 0, 0, 0, 0, nullptr, cosT, sinT);
    flash3_kernel<<<dim3(SEQ / 128, NH, 2), 256, FSMEM>>>();
    cudaStreamWaitEvent(0, e1, 0);
    tgemm<EPI_WO, 0><<<dim3(4, 32, 1), 256, GSMEM>>>(
        p_ocat, p_woc, bo, x, (float*)p_x2, nullptr,
        1024, 1024, 0, 0, 0, 0, 0, nullptr, nullptr, nullptr);
    ln_kernel<false><<<TKN, 256>>>((const float*)p_x2, ln2g, ln2b, (float*)p_h2, nullptr);
    gate_kernel<<<TKN / 4, 128>>>(gatew);
    pos_kernel<<<1, 256>>>();
    cudaEventRecord(e3, 0);
    cudaStreamWaitEvent(s2, e3, 0);
    aux_kernel<<<1, 256, 0, s2>>>(out, out_size);
    cudaEventRecord(e4, s2);
    // main: scatter + expert FFN (fp16 2-term)
    scatter_kernel<<<NA, 256>>>();
    tgemm<EPI_W1, 1><<<dim3(16, 10, 8), 256, GSMEM>>>(
        p_bufh, p_w1h, b1, nullptr, nullptr, p_hhh,
        1024, 0, HID,
        (size_t)CAP * 1024, (size_t)HID * 2048, (size_t)HID, (size_t)CAP * HID,
        (const int*)p_cnt, nullptr, nullptr);
    tgemm<EPI_PLAIN, 1><<<dim3(4, 10, 8), 256, GSMEM>>>(
        p_hhh, p_w2h, b2, nullptr, (float*)p_oute, nullptr,
        4096, 1024, 0,
        (size_t)CAP * 4096, (size_t)DIM * 8192, (size_t)DIM, (size_t)CAP * DIM,
        (const int*)p_cnt, nullptr, nullptr);
    final_kernel<<<TKN, 256>>>(out);
    cudaStreamWaitEvent(0, e4, 0);
}

// round 17
// speedup vs baseline: 4.5810x; 1.1374x over previous
#include <cuda_runtime.h>
#include <cuda_bf16.h>
#include <cuda_fp16.h>
#include <math.h>
#include <stdint.h>

#define TKN 4096
#define SEQ 2048
#define DIM 1024
#define NH 16
#define NE 8
#define HID 4096
#define CAP 1280
#define NA 8192

// ---------------- scratch ----------------
__device__ float g_x2[TKN * DIM];
__device__ float g_h2[TKN * DIM];
__device__ float g_probs[TKN * NE];
__device__ int   g_eid[NA];
__device__ float g_wflat[NA];
__device__ int   g_pos[NA];
__device__ int   g_cnt[NE];
__device__ float g_oute[NE * CAP * DIM];

// fp16 buffers. Activations: hi-only (stride K). Weights: [hi|lo] (stride 2K).
__device__ __half g_ah[(size_t)TKN * 1024];        // ln1 out
__device__ __half g_oh[(size_t)TKN * 1024];        // flash out
__device__ __half g_bufh[(size_t)NE * CAP * 1024];
__device__ __half g_hhh[(size_t)NE * CAP * 4096];
__device__ __half g_wqkvh[(size_t)3072 * 2048];
__device__ __half g_woh[(size_t)1024 * 2048];
__device__ __half g_w1h[(size_t)NE * HID * 2048];
__device__ __half g_w2h[(size_t)NE * DIM * 8192];
// attention operands: Q hi-only [..][seq][64]; K,V [hi(64)|lo(64)] [..][seq][128]
__device__ __half g_qsh[(size_t)2 * NH * SEQ * 64];
__device__ __half g_ksh[(size_t)2 * NH * SEQ * 128];
__device__ __half g_vsh[(size_t)2 * NH * SEQ * 128];

// ---------------- helpers ----------------
__device__ __forceinline__ uint32_t smem_u32(const void* p) {
    uint32_t a;
    asm("{ .reg .u64 t; cvta.to.shared.u64 t, %1; cvt.u32.u64 %0, t; }" : "=r"(a) : "l"(p));
    return a;
}
__device__ __forceinline__ void ldsm4(uint32_t* r, uint32_t a) {
    asm volatile("ldmatrix.sync.aligned.m8n8.x4.shared.b16 {%0,%1,%2,%3}, [%4];"
                 : "=r"(r[0]), "=r"(r[1]), "=r"(r[2]), "=r"(r[3]) : "r"(a));
}
__device__ __forceinline__ void ldsm4t(uint32_t* r, uint32_t a) {
    asm volatile("ldmatrix.sync.aligned.m8n8.x4.trans.shared.b16 {%0,%1,%2,%3}, [%4];"
                 : "=r"(r[0]), "=r"(r[1]), "=r"(r[2]), "=r"(r[3]) : "r"(a));
}
__device__ __forceinline__ void mma2h(float* c, const uint32_t* a, uint32_t b0, uint32_t b1) {
    asm volatile(
        "mma.sync.aligned.m16n8k16.row.col.f32.f16.f16.f32 "
        "{%0,%1,%2,%3}, {%4,%5,%6,%7}, {%8,%9}, {%0,%1,%2,%3};"
        : "+f"(c[0]), "+f"(c[1]), "+f"(c[2]), "+f"(c[3])
        : "r"(a[0]), "r"(a[1]), "r"(a[2]), "r"(a[3]), "r"(b0), "r"(b1));
}
__device__ __forceinline__ void cpa16(uint32_t dst, const void* src) {
    asm volatile("cp.async.cg.shared.global [%0], [%1], 16;" :: "r"(dst), "l"(src));
}
#define CPA_COMMIT() asm volatile("cp.async.commit_group;")
#define CPA_WAIT2()  asm volatile("cp.async.wait_group 2;")
#define CPA_WAIT1()  asm volatile("cp.async.wait_group 1;")

__device__ __forceinline__ float gelu_f(float x) {
    float x3 = x * x * x;
    float t = tanhf(0.7978845608028654f * (x + 0.044715f * x3));
    return 0.5f * x * (1.0f + t);
}
__device__ __forceinline__ uint32_t packh(__half a, __half b) {
    return ((uint32_t)__half_as_ushort(b) << 16) | __half_as_ushort(a);
}
// store fp16 [hi|lo] pair: hi half2 at p, lo half2 at p+stride
__device__ __forceinline__ void put_h2(__half* p, int stride, float a, float b) {
    __half ah = __float2half(a), bh = __float2half(b);
    __half al = __float2half(a - __half2float(ah));
    __half bl = __float2half(b - __half2float(bh));
    *(uint32_t*)(p) = packh(ah, bh);
    *(uint32_t*)(p + stride) = packh(al, bl);
}

// ---------------- weight transpose + split fp16: W[K][N] -> Wt[N][2K] = [hi|lo] ----------------
__global__ __launch_bounds__(256) void wconvh_kernel(const float* __restrict__ W,
                                                     __half* __restrict__ Wt,
                                                     int K, int N, size_t wOff, size_t oOff) {
    int z = blockIdx.z;
    W += wOff * z; Wt += oOff * z;
    __shared__ float t[64][33];
    int n0 = blockIdx.x * 32, k0 = blockIdx.y * 64;
    int tid = threadIdx.x;
    #pragma unroll
    for (int i = 0; i < 8; i++) {
        int id = tid + i * 256;
        int k = id >> 5, n = id & 31;
        t[k][n] = W[(size_t)(k0 + k) * N + n0 + n];
    }
    __syncthreads();
    int n = tid >> 3, kq = tid & 7;
    uint32_t hw[4], lw[4];
    #pragma unroll
    for (int j = 0; j < 4; j++) {
        float a = t[kq * 8 + 2 * j][n], b = t[kq * 8 + 2 * j + 1][n];
        __half ah = __float2half(a);
        __half bh = __float2half(b);
        __half al = __float2half(a - __half2float(ah));
        __half bl = __float2half(b - __half2float(bh));
        hw[j] = packh(ah, bh);
        lw[j] = packh(al, bl);
    }
    __half* p = Wt + (size_t)(n0 + n) * 2 * K + k0 + kq * 8;
    *(uint4*)p = make_uint4(hw[0], hw[1], hw[2], hw[3]);
    *(uint4*)(p + K) = make_uint4(lw[0], lw[1], lw[2], lw[3]);
}

// ---------------- layernorm ----------------
template <bool CAT>
__global__ __launch_bounds__(256) void ln_kernel(const float* __restrict__ x,
                                                 const float* __restrict__ g,
                                                 const float* __restrict__ b,
                                                 float* __restrict__ outf,
                                                 __half* __restrict__ outh) {
    int row = blockIdx.x, tid = threadIdx.x;
    const float4* xr = (const float4*)(x + (size_t)row * DIM);
    float4 v = xr[tid];
    float s = v.x + v.y + v.z + v.w;
    float q = v.x * v.x + v.y * v.y + v.z * v.z + v.w * v.w;
    __shared__ float ss[8], sq[8];
    #pragma unroll
    for (int o = 16; o; o >>= 1) {
        s += __shfl_xor_sync(0xffffffffu, s, o);
        q += __shfl_xor_sync(0xffffffffu, q, o);
    }
    int w = tid >> 5;
    if ((tid & 31) == 0) { ss[w] = s; sq[w] = q; }
    __syncthreads();
    __shared__ float mu_s, rs_s;
    if (tid == 0) {
        float S = 0.f, Q = 0.f;
        #pragma unroll
        for (int i = 0; i < 8; i++) { S += ss[i]; Q += sq[i]; }
        float mu = S / DIM;
        mu_s = mu;
        rs_s = rsqrtf(Q / DIM - mu * mu + 1e-6f);
    }
    __syncthreads();
    float mu = mu_s, rs = rs_s;
    float4 gg = ((const float4*)g)[tid];
    float4 bb = ((const float4*)b)[tid];
    float4 o4;
    o4.x = (v.x - mu) * rs * gg.x + bb.x;
    o4.y = (v.y - mu) * rs * gg.y + bb.y;
    o4.z = (v.z - mu) * rs * gg.z + bb.z;
    o4.w = (v.w - mu) * rs * gg.w + bb.w;
    if (CAT) {
        __half2 u0 = __floats2half2_rn(o4.x, o4.y);
        __half2 u1 = __floats2half2_rn(o4.z, o4.w);
        *(uint2*)(outh + (size_t)row * 1024 + tid * 4) =
            make_uint2(*(uint32_t*)&u0, *(uint32_t*)&u1);
    } else {
        ((float4*)(outf + (size_t)row * DIM))[tid] = o4;
    }
}

// ---------------- HMMA GEMM: fp16 2-term (A hi-only stride K, B [hi|lo] stride 2K) ----------------
#define EPI_PLAIN 0
#define EPI_WO 1
#define EPI_W1 2
#define EPI_QKV 3
#define STAGE_BYTES 49152
#define GSMEM (4 * STAGE_BYTES)

template <int EPI>
__global__ __launch_bounds__(256, 1) void tgemm(
    const __half* __restrict__ A, const __half* __restrict__ Bt,
    const float* __restrict__ bias, const float* __restrict__ res,
    float* __restrict__ Cf, __half* __restrict__ Cbh,
    int Klog, int Nstr, int HIDN,
    size_t aOff, size_t bOff, size_t biasOff, size_t cOff,
    const int* __restrict__ cnt,
    const float* __restrict__ cosT, const float* __restrict__ sinT) {
    extern __shared__ __align__(1024) char smem[];
    const uint32_t sb = smem_u32(smem);
    const int tid = threadIdx.x;
    const int z = blockIdx.z;
    const int m0 = blockIdx.y * 128;
    if (cnt != nullptr && m0 >= cnt[z]) return;
    A += aOff * z; Bt += bOff * z; bias += biasOff * z;
    Cbh += cOff * z;
    Cf += (EPI == EPI_W1) ? 0 : cOff * z;
    const int n0 = blockIdx.x * 256;
    const int bstr = 2 * Klog;
    const int nk = (2 * Klog) >> 6;

    auto loadStage = [&](int kt, int ss) {
        uint32_t sbase = sb + ss * STAGE_BYTES;
        int kb = kt << 6;
        int akb = kb < Klog ? kb : kb - Klog;   // A logical [hi|hi]
        const __half* Ag = A + (size_t)m0 * Klog + akb;
        #pragma unroll
        for (int i = 0; i < 4; i++) {
            int id = tid + i * 256;
            int r = id >> 3, c = id & 7;
            cpa16(sbase + r * 128 + ((c ^ (r & 7)) << 4), Ag + (size_t)r * Klog + c * 8);
        }
        const __half* Bg = Bt + (size_t)n0 * bstr + kb;
        #pragma unroll
        for (int i = 0; i < 8; i++) {
            int id = tid + i * 256;
            int r = id >> 3, c = id & 7;
            cpa16(sbase + 16384 + r * 128 + ((c ^ (r & 7)) << 4), Bg + (size_t)r * bstr + c * 8);
        }
        CPA_COMMIT();
    };

    loadStage(0, 0);
    loadStage(1, 1);
    loadStage(2, 2);

    const int lane = tid & 31, wid = tid >> 5;
    const int wm = wid >> 2, wn = wid & 3;
    const int arl = lane & 15, akc = lane >> 4;

    int arow[4];
    #pragma unroll
    for (int mf = 0; mf < 4; mf++) arow[mf] = wm * 64 + mf * 16 + arl;

    float acc[4][8][4];
    #pragma unroll
    for (int mf = 0; mf < 4; mf++)
        #pragma unroll
        for (int nf = 0; nf < 8; nf++)
            #pragma unroll
            for (int i = 0; i < 4; i++) acc[mf][nf][i] = 0.f;

    for (int kt = 0; kt < nk; kt++) {
        CPA_WAIT2();
        __syncthreads();
        if (kt + 3 < nk) loadStage(kt + 3, (kt + 3) & 3);
        else CPA_COMMIT();
        int ss = kt & 3;
        uint32_t Au = sb + ss * STAGE_BYTES;
        uint32_t Bu = Au + 16384;
        #pragma unroll
        for (int j = 0; j < 4; j++) {
            uint32_t af[4][4];
            #pragma unroll
            for (int mf = 0; mf < 4; mf++) {
                int r = arow[mf];
                ldsm4(af[mf], Au + r * 128 + (((j * 2 + akc) ^ (r & 7)) << 4));
            }
            uint32_t bf[4][4];
            #pragma unroll
            for (int pr = 0; pr < 4; pr++) {
                int r = wn * 64 + pr * 16 + arl;
                ldsm4(bf[pr], Bu + r * 128 + (((j * 2 + akc) ^ (r & 7)) << 4));
            }
            #pragma unroll
            for (int mf = 0; mf < 4; mf++)
                #pragma unroll
                for (int pr = 0; pr < 4; pr++) {
                    mma2h(acc[mf][2 * pr], af[mf], bf[pr][0], bf[pr][2]);
                    mma2h(acc[mf][2 * pr + 1], af[mf], bf[pr][1], bf[pr][3]);
                }
        }
    }

    const int quad = lane >> 2, tq = lane & 3;
    if (EPI == EPI_QKV && n0 < 2048) {
        // q or k tile: RoPE in-register
        const bool isQ = (n0 < 1024);
        #pragma unroll
        for (int mf = 0; mf < 4; mf++) {
            int m = m0 + wm * 64 + mf * 16 + quad;
            #pragma unroll
            for (int nf = 0; nf < 4; nf++) {
                int n = n0 + wn * 64 + nf * 8 + tq * 2;
                int h = (n & 1023) >> 6;
                int cc = n & 63;   // in [0,32); partner cc+32 in fragment nf+4
                const float* cA = acc[mf][nf];
                const float* cC = acc[mf][nf + 4];
                float b0 = bias[n], b1 = bias[n + 1];
                float b2 = bias[n + 32], b3 = bias[n + 33];
                #pragma unroll
                for (int half = 0; half < 2; half++) {
                    int mr = m + half * 8;
                    int s = mr & (SEQ - 1), bb = mr >> 11;
                    float a0 = cA[2 * half + 0] + b0;
                    float a1 = cA[2 * half + 1] + b1;
                    float g0 = cC[2 * half + 0] + b2;
                    float g1 = cC[2 * half + 1] + b3;
                    const float* cr = cosT + s * 64;
                    const float* sr = sinT + s * 64;
                    float na0 = a0 * cr[cc] - g0 * sr[cc];
                    float na1 = a1 * cr[cc + 1] - g1 * sr[cc + 1];
                    float nc0 = g0 * cr[cc + 32] + a0 * sr[cc + 32];
                    float nc1 = g1 * cr[cc + 33] + a1 * sr[cc + 33];
                    if (isQ) {
                        __half* D = g_qsh + ((size_t)(bb * NH + h) * SEQ + s) * 64;
                        __half2 u = __floats2half2_rn(na0, na1);
                        __half2 v = __floats2half2_rn(nc0, nc1);
                        *(uint32_t*)(D + cc) = *(uint32_t*)&u;
                        *(uint32_t*)(D + cc + 32) = *(uint32_t*)&v;
                    } else {
                        __half* D = g_ksh + ((size_t)(bb * NH + h) * SEQ + s) * 128;
                        put_h2(D + cc, 64, na0, na1);
                        put_h2(D + cc + 32, 64, nc0, nc1);
                    }
                }
            }
        }
        return;
    }
    #pragma unroll
    for (int mf = 0; mf < 4; mf++) {
        #pragma unroll
        for (int nf = 0; nf < 8; nf++) {
            int m = m0 + wm * 64 + mf * 16 + quad;
            int n = n0 + wn * 64 + nf * 8 + tq * 2;
            const float* c = acc[mf][nf];
            float b0 = bias[n], b1 = bias[n + 1];
            if (EPI == EPI_W1) {
                __half2 u = __floats2half2_rn(gelu_f(c[0] + b0), gelu_f(c[1] + b1));
                *(__half2*)(Cbh + (size_t)m * HIDN + n) = u;
                __half2 v = __floats2half2_rn(gelu_f(c[2] + b0), gelu_f(c[3] + b1));
                *(__half2*)(Cbh + (size_t)(m + 8) * HIDN + n) = v;
            } else {
                float2 v = make_float2(c[0] + b0, c[1] + b1);
                float2 w = make_float2(c[2] + b0, c[3] + b1);
                if (EPI == EPI_WO) {
                    float2 r1 = *(const float2*)&res[(size_t)m * Nstr + n];
                    float2 r2 = *(const float2*)&res[(size_t)(m + 8) * Nstr + n];
                    v.x += r1.x; v.y += r1.y;
                    w.x += r2.x; w.y += r2.y;
                }
                if (EPI == EPI_QKV) {
                    // V columns (n >= 2048): [hi|lo] fp16 attention layout
                    int h = (n - 2048) >> 6, cc = (n - 2048) & 63;
                    int b_ = m >> 11, s = m & (SEQ - 1);
                    put_h2(g_vsh + ((size_t)(b_ * NH + h) * SEQ + s) * 128 + cc, 64, v.x, v.y);
                    int b2_ = (m + 8) >> 11, s2 = (m + 8) & (SEQ - 1);
                    put_h2(g_vsh + ((size_t)(b2_ * NH + h) * SEQ + s2) * 128 + cc, 64, w.x, w.y);
                } else {
                    *(float2*)&Cf[(size_t)m * Nstr + n] = v;
                    *(float2*)&Cf[(size_t)(m + 8) * Nstr + n] = w;
                }
            }
        }
    }
}

// ---------------- HMMA flash attention, fp16 2-term ----------------
// smem: Q 128x128B @0 (16KB), K/V stages 64x256B each, double buffered
#define FSMEM 81920
__global__ __launch_bounds__(256, 2) void flash4_kernel() {
    extern __shared__ __align__(1024) char fsm[];
    const uint32_t Qu = smem_u32(fsm);
    const int b = blockIdx.z, h = blockIdx.y, q0 = blockIdx.x * 128;
    const int tid = threadIdx.x, lane = tid & 31, w = tid >> 5;
    const int arl = lane & 15, akc = lane >> 4;
    const int tq = lane & 3, quad = lane >> 2;
    const __half* qsrc = g_qsh + (size_t)(b * NH + h) * SEQ * 64;
    const __half* ksrc = g_ksh + (size_t)(b * NH + h) * SEQ * 128;
    const __half* vsrc = g_vsh + (size_t)(b * NH + h) * SEQ * 128;

    #pragma unroll
    for (int i = 0; i < 4; i++) {
        int id = tid + i * 256;
        int r = id >> 3, ch = id & 7;
        cpa16(Qu + r * 128 + ((ch ^ (r & 7)) << 4), qsrc + (size_t)(q0 + r) * 64 + ch * 8);
    }
    auto loadKV = [&](int kt, int st) {
        uint32_t Ks = Qu + 16384 + st * 32768;
        #pragma unroll
        for (int i = 0; i < 4; i++) {
            int id = tid + i * 256;
            int r = id >> 4, ch = id & 15;
            cpa16(Ks + r * 256 + ((ch ^ (r & 7)) << 4), ksrc + (size_t)(kt * 64 + r) * 128 + ch * 8);
        }
        uint32_t Vs = Ks + 16384;
        #pragma unroll
        for (int i = 0; i < 4; i++) {
            int id = tid + i * 256;
            int r = id >> 4, ch = id & 15;
            cpa16(Vs + r * 256 + ((ch ^ (r & 7)) << 4), vsrc + (size_t)(kt * 64 + r) * 128 + ch * 8);
        }
        CPA_COMMIT();
    };
    loadKV(0, 0);
    loadKV(1, 1);

    float accO[8][4];
    #pragma unroll
    for (int nf = 0; nf < 8; nf++)
        #pragma unroll
        for (int i = 0; i < 4; i++) accO[nf][i] = 0.f;
    float m0 = -1e30f, m1 = -1e30f, l0 = 0.f, l1 = 0.f;
    const int qr = w * 16 + arl;

    for (int kt = 0; kt < SEQ / 64; kt++) {
        int st = kt & 1;
        CPA_WAIT1();
        __syncthreads();
        uint32_t Ku = Qu + 16384 + st * 32768;
        uint32_t Vu = Ku + 16384;

        float accS[8][4];
        #pragma unroll
        for (int nf = 0; nf < 8; nf++)
            #pragma unroll
            for (int i = 0; i < 4; i++) accS[nf][i] = 0.f;
        #pragma unroll
        for (int j = 0; j < 4; j++) {
            uint32_t aq[4];
            ldsm4(aq, Qu + qr * 128 + (((j * 2 + akc) ^ (qr & 7)) << 4));
            #pragma unroll
            for (int pr = 0; pr < 4; pr++) {
                int kr = pr * 16 + arl;
                uint32_t bh[4], bl[4];
                ldsm4(bh, Ku + kr * 256 + (((j * 2 + akc) ^ (kr & 7)) << 4));
                ldsm4(bl, Ku + kr * 256 + (((8 + j * 2 + akc) ^ (kr & 7)) << 4));
                mma2h(accS[2 * pr], aq, bh[0], bh[2]);
                mma2h(accS[2 * pr], aq, bl[0], bl[2]);
                mma2h(accS[2 * pr + 1], aq, bh[1], bh[3]);
                mma2h(accS[2 * pr + 1], aq, bl[1], bl[3]);
            }
        }
        float mt0 = m0, mt1 = m1;
        #pragma unroll
        for (int nf = 0; nf < 8; nf++) {
            #pragma unroll
            for (int i = 0; i < 4; i++) accS[nf][i] *= 0.125f;
            mt0 = fmaxf(mt0, fmaxf(accS[nf][0], accS[nf][1]));
            mt1 = fmaxf(mt1, fmaxf(accS[nf][2], accS[nf][3]));
        }
        #pragma unroll
        for (int o = 1; o <= 2; o <<= 1) {
            mt0 = fmaxf(mt0, __shfl_xor_sync(0xffffffffu, mt0, o));
            mt1 = fmaxf(mt1, __shfl_xor_sync(0xffffffffu, mt1, o));
        }
        float c0 = __expf(m0 - mt0), c1 = __expf(m1 - mt1);
        m0 = mt0; m1 = mt1;
        l0 *= c0; l1 *= c1;
        #pragma unroll
        for (int nf = 0; nf < 8; nf++) {
            accO[nf][0] *= c0; accO[nf][1] *= c0;
            accO[nf][2] *= c1; accO[nf][3] *= c1;
        }
        uint32_t ph[8][2];
        #pragma unroll
        for (int nf = 0; nf < 8; nf++) {
            float p0 = __expf(accS[nf][0] - mt0);
            float p1 = __expf(accS[nf][1] - mt0);
            float p2 = __expf(accS[nf][2] - mt1);
            float p3 = __expf(accS[nf][3] - mt1);
            l0 += p0 + p1; l1 += p2 + p3;
            __half2 u = __floats2half2_rn(p0, p1);
            __half2 v = __floats2half2_rn(p2, p3);
            ph[nf][0] = *(uint32_t*)&u;
            ph[nf][1] = *(uint32_t*)&v;
        }
        #pragma unroll
        for (int kf = 0; kf < 4; kf++) {
            uint32_t pah[4] = {ph[2 * kf][0], ph[2 * kf][1], ph[2 * kf + 1][0], ph[2 * kf + 1][1]};
            int vr = kf * 16 + arl;
            #pragma unroll
            for (int dp = 0; dp < 4; dp++) {
                uint32_t vh[4], vl[4];
                ldsm4t(vh, Vu + vr * 256 + (((dp * 2 + akc) ^ (vr & 7)) << 4));
                ldsm4t(vl, Vu + vr * 256 + (((8 + dp * 2 + akc) ^ (vr & 7)) << 4));
                mma2h(accO[2 * dp], pah, vh[0], vh[1]);
                mma2h(accO[2 * dp], pah, vl[0], vl[1]);
                mma2h(accO[2 * dp + 1], pah, vh[2], vh[3]);
                mma2h(accO[2 * dp + 1], pah, vl[2], vl[3]);
            }
        }
        __syncthreads();
        if (kt + 2 < SEQ / 64) loadKV(kt + 2, st);
        else CPA_COMMIT();
    }
    #pragma unroll
    for (int o = 1; o <= 2; o <<= 1) {
        l0 += __shfl_xor_sync(0xffffffffu, l0, o);
        l1 += __shfl_xor_sync(0xffffffffu, l1, o);
    }
    float i0 = 1.f / l0, i1 = 1.f / l1;
    int r0 = q0 + w * 16 + quad;
    #pragma unroll
    for (int nf = 0; nf < 8; nf++) {
        int col = h * 64 + nf * 8 + tq * 2;
        __half2 u = __floats2half2_rn(accO[nf][0] * i0, accO[nf][1] * i0);
        __half2 v = __floats2half2_rn(accO[nf][2] * i1, accO[nf][3] * i1);
        *(uint32_t*)(g_oh + (size_t)(b * SEQ + r0) * 1024 + col) = *(uint32_t*)&u;
        *(uint32_t*)(g_oh + (size_t)(b * SEQ + r0 + 8) * 1024 + col) = *(uint32_t*)&v;
    }
}

// ---------------- gating ----------------
__global__ __launch_bounds__(128) void gate_kernel(const float* __restrict__ gate_w) {
    int t = blockIdx.x * 4 + (threadIdx.x >> 5);
    int lane = threadIdx.x & 31;
    const float* xr = g_h2 + (size_t)t * DIM;
    float p[8];
    #pragma unroll
    for (int e = 0; e < 8; e++) p[e] = 0.f;
    for (int it = 0; it < 32; it++) {
        int d = it * 32 + lane;
        float xv = xr[d];
        const float4* gw = (const float4*)(gate_w + d * 8);
        float4 g0 = gw[0], g1 = gw[1];
        p[0] += xv * g0.x; p[1] += xv * g0.y; p[2] += xv * g0.z; p[3] += xv * g0.w;
        p[4] += xv * g1.x; p[5] += xv * g1.y; p[6] += xv * g1.z; p[7] += xv * g1.w;
    }
    #pragma unroll
    for (int e = 0; e < 8; e++)
        #pragma unroll
        for (int o = 16; o; o >>= 1) p[e] += __shfl_xor_sync(0xffffffffu, p[e], o);
    if (lane == 0) {
        float mx = p[0];
        #pragma unroll
        for (int e = 1; e < 8; e++) mx = fmaxf(mx, p[e]);
        float ex[8], sum = 0.f;
        #pragma unroll
        for (int e = 0; e < 8; e++) { ex[e] = __expf(p[e] - mx); sum += ex[e]; }
        float inv = 1.f / sum;
        float pr[8];
        #pragma unroll
        for (int e = 0; e < 8; e++) { pr[e] = ex[e] * inv; g_probs[t * 8 + e] = pr[e]; }
        int i1 = 0;
        float v1 = pr[0];
        #pragma unroll
        for (int e = 1; e < 8; e++) if (pr[e] > v1) { v1 = pr[e]; i1 = e; }
        int i2 = -1;
        float v2 = -1.f;
        #pragma unroll
        for (int e = 0; e < 8; e++) if (e != i1 && pr[e] > v2) { v2 = pr[e]; i2 = e; }
        float dn = 1.f / (v1 + v2);
        g_eid[t] = i1;
        g_eid[TKN + t] = i2;
        g_wflat[t] = v1 * dn;
        g_wflat[TKN + t] = v2 * dn;
    }
}

// ---------------- per-expert positions + counts ----------------
__global__ void pos_kernel() {
    int e = threadIdx.x >> 5;
    int lane = threadIdx.x & 31;
    int base = 0;
    for (int a0 = 0; a0 < NA; a0 += 32) {
        int ea = g_eid[a0 + lane];
        unsigned mask = __ballot_sync(0xffffffffu, ea == e);
        if (ea == e) g_pos[a0 + lane] = base + __popc(mask & ((1u << lane) - 1));
        base += __popc(mask);
    }
    if (lane == 0) g_cnt[e] = base;
}

// ---------------- scatter tokens (hi-only fp16) into capacity buffer ----------------
__global__ __launch_bounds__(256) void scatter_kernel() {
    int a = blockIdx.x;
    int p = g_pos[a];
    if (p >= CAP) return;
    int e = g_eid[a];
    int tok = a & (TKN - 1);
    float4 v = ((const float4*)(g_h2 + (size_t)tok * DIM))[threadIdx.x];
    __half2 u0 = __floats2half2_rn(v.x, v.y);
    __half2 u1 = __floats2half2_rn(v.z, v.w);
    *(uint2*)(g_bufh + ((size_t)e * CAP + p) * 1024 + threadIdx.x * 4) =
        make_uint2(*(uint32_t*)&u0, *(uint32_t*)&u1);
}

// ---------------- aux loss ----------------
__global__ __launch_bounds__(256) void aux_kernel(float* __restrict__ out, int out_size) {
    __shared__ float red[256];
    int tid = threadIdx.x;
    float me[8], cnt[8];
    #pragma unroll
    for (int e = 0; e < 8; e++) { me[e] = 0.f; cnt[e] = 0.f; }
    for (int t = tid; t < TKN; t += 256) {
        #pragma unroll
        for (int e = 0; e < 8; e++) me[e] += g_probs[t * 8 + e];
    }
    for (int a = tid; a < NA; a += 256) cnt[g_eid[a]] += 1.f;
    float auxv = 0.f;
    for (int e = 0; e < 8; e++) {
        red[tid] = me[e];
        __syncthreads();
        for (int st = 128; st; st >>= 1) { if (tid < st) red[tid] += red[tid + st]; __syncthreads(); }
        float meS = red[0];
        __syncthreads();
        red[tid] = cnt[e];
        __syncthreads();
        for (int st = 128; st; st >>= 1) { if (tid < st) red[tid] += red[tid + st]; __syncthreads(); }
        float cS = red[0];
        __syncthreads();
        auxv += (meS / (float)TKN) * (cS / (float)NA);
    }
    if (tid == 0 && out_size > TKN * DIM) out[TKN * DIM] = 8.f * auxv;
}

// ---------------- combine ----------------
__global__ __launch_bounds__(256) void final_kernel(float* __restrict__ out) {
    int t = blockIdx.x;
    int tid = threadIdx.x;
    int p1 = g_pos[t], p2 = g_pos[TKN + t];
    int e1 = g_eid[t], e2 = g_eid[TKN + t];
    float w1 = (p1 < CAP) ? g_wflat[t] : 0.f;
    float w2 = (p2 < CAP) ? g_wflat[TKN + t] : 0.f;
    p1 = min(p1, CAP - 1);
    p2 = min(p2, CAP - 1);
    const float4* a = (const float4*)(g_oute + ((size_t)e1 * CAP + p1) * DIM);
    const float4* b = (const float4*)(g_oute + ((size_t)e2 * CAP + p2) * DIM);
    const float4* xr = (const float4*)(g_x2 + (size_t)t * DIM);
    float4 av = a[tid], bv = b[tid], xv = xr[tid];
    float4 r;
    r.x = xv.x + w1 * av.x + w2 * bv.x;
    r.y = xv.y + w1 * av.y + w2 * bv.y;
    r.z = xv.z + w1 * av.z + w2 * bv.z;
    r.w = xv.w + w1 * av.w + w2 * bv.w;
    ((float4*)(out + (size_t)t * DIM))[tid] = r;
}

// ---------------- host ----------------
extern "C" void kernel_launch(void* const* d_in, const int* in_sizes, int n_in,
                              void* d_out, int out_size) {
    const float* x     = (const float*)d_in[0];
    const float* cosT  = (const float*)d_in[1];
    const float* sinT  = (const float*)d_in[2];
    const float* ln1g  = (const float*)d_in[3];
    const float* ln1b  = (const float*)d_in[4];
    const float* ln2g  = (const float*)d_in[5];
    const float* ln2b  = (const float*)d_in[6];
    const float* wqkv  = (const float*)d_in[7];
    const float* bqkv  = (const float*)d_in[8];
    const float* wo    = (const float*)d_in[9];
    const float* bo    = (const float*)d_in[10];
    const float* gatew = (const float*)d_in[11];
    const float* w1    = (const float*)d_in[12];
    const float* b1    = (const float*)d_in[13];
    const float* w2    = (const float*)d_in[14];
    const float* b2    = (const float*)d_in[15];
    float* out = (float*)d_out;

    void *p_x2, *p_h2, *p_oute, *p_cnt;
    void *p_ah, *p_oh, *p_bufh, *p_hhh, *p_wqkvh, *p_woh, *p_w1h, *p_w2h;
    cudaGetSymbolAddress(&p_x2, g_x2);
    cudaGetSymbolAddress(&p_h2, g_h2);
    cudaGetSymbolAddress(&p_oute, g_oute);
    cudaGetSymbolAddress(&p_cnt, g_cnt);
    cudaGetSymbolAddress(&p_ah, g_ah);
    cudaGetSymbolAddress(&p_oh, g_oh);
    cudaGetSymbolAddress(&p_bufh, g_bufh);
    cudaGetSymbolAddress(&p_hhh, g_hhh);
    cudaGetSymbolAddress(&p_wqkvh, g_wqkvh);
    cudaGetSymbolAddress(&p_woh, g_woh);
    cudaGetSymbolAddress(&p_w1h, g_w1h);
    cudaGetSymbolAddress(&p_w2h, g_w2h);

    static int init_done = 0;
    static cudaStream_t s1, s2;
    static cudaEvent_t e0, e1, e2, e3, e4;
    if (!init_done) {
        cudaFuncSetAttribute(tgemm<EPI_QKV>, cudaFuncAttributeMaxDynamicSharedMemorySize, GSMEM);
        cudaFuncSetAttribute(tgemm<EPI_WO>, cudaFuncAttributeMaxDynamicSharedMemorySize, GSMEM);
        cudaFuncSetAttribute(tgemm<EPI_W1>, cudaFuncAttributeMaxDynamicSharedMemorySize, GSMEM);
        cudaFuncSetAttribute(tgemm<EPI_PLAIN>, cudaFuncAttributeMaxDynamicSharedMemorySize, GSMEM);
        cudaFuncSetAttribute(flash4_kernel, cudaFuncAttributeMaxDynamicSharedMemorySize, FSMEM);
        cudaStreamCreateWithFlags(&s1, cudaStreamNonBlocking);
        cudaStreamCreateWithFlags(&s2, cudaStreamNonBlocking);
        cudaEventCreateWithFlags(&e0, cudaEventDisableTiming);
        cudaEventCreateWithFlags(&e1, cudaEventDisableTiming);
        cudaEventCreateWithFlags(&e2, cudaEventDisableTiming);
        cudaEventCreateWithFlags(&e3, cudaEventDisableTiming);
        cudaEventCreateWithFlags(&e4, cudaEventDisableTiming);
        init_done = 1;
    }

    // fork side streams off the main (captured) stream
    cudaEventRecord(e0, 0);
    cudaStreamWaitEvent(s1, e0, 0);
    cudaStreamWaitEvent(s2, e0, 0);

    // s1: heavy weight conversions — overlap with qkv GEMM + flash
    wconvh_kernel<<<dim3(32, 16, 1), 256, 0, s1>>>(wo, (__half*)p_woh, 1024, 1024, 0, 0);
    wconvh_kernel<<<dim3(128, 16, 8), 256, 0, s1>>>(w1, (__half*)p_w1h, 1024, 4096,
                                                    (size_t)DIM * HID, (size_t)HID * 2048);
    wconvh_kernel<<<dim3(32, 64, 8), 256, 0, s1>>>(w2, (__half*)p_w2h, 4096, 1024,
                                                   (size_t)HID * DIM, (size_t)DIM * 8192);
    cudaEventRecord(e1, s1);

    // s2: ln1 (concurrent with wconv_qkv on main stream)
    ln_kernel<true><<<TKN, 256, 0, s2>>>(x, ln1g, ln1b, nullptr, (__half*)p_ah);
    cudaEventRecord(e2, s2);

    // main: qkv weight conversion, then qkv GEMM (RoPE + q/k/v split fused)
    wconvh_kernel<<<dim3(96, 16, 1), 256>>>(wqkv, (__half*)p_wqkvh, 1024, 3072, 0, 0);
    cudaStreamWaitEvent(0, e2, 0);
    tgemm<EPI_QKV><<<dim3(12, 32, 1), 256, GSMEM>>>(
        (const __half*)p_ah, (const __half*)p_wqkvh, bqkv, nullptr, nullptr, nullptr,
        1024, 3072, 0, 0, 0, 0, 0, nullptr, cosT, sinT);
    flash4_kernel<<<dim3(SEQ / 128, NH, 2), 256, FSMEM>>>();
    cudaStreamWaitEvent(0, e1, 0);
    tgemm<EPI_WO><<<dim3(4, 32, 1), 256, GSMEM>>>(
        (const __half*)p_oh, (const __half*)p_woh, bo, x, (float*)p_x2, nullptr,
        1024, 1024, 0, 0, 0, 0, 0, nullptr, nullptr, nullptr);
    ln_kernel<false><<<TKN, 256>>>((const float*)p_x2, ln2g, ln2b, (float*)p_h2, nullptr);
    gate_kernel<<<TKN / 4, 128>>>(gatew);
    pos_kernel<<<1, 256>>>();
    cudaEventRecord(e3, 0);
    cudaStreamWaitEvent(s2, e3, 0);
    aux_kernel<<<1, 256, 0, s2>>>(out, out_size);
    cudaEventRecord(e4, s2);
    // main: scatter + expert FFN (fp16 2-term)
    scatter_kernel<<<NA, 256>>>();
    tgemm<EPI_W1><<<dim3(16, 10, 8), 256, GSMEM>>>(
        (const __half*)p_bufh, (const __half*)p_w1h, b1, nullptr, nullptr, (__half*)p_hhh,
        1024, 0, HID,
        (size_t)CAP * 1024, (size_t)HID * 2048, (size_t)HID, (size_t)CAP * HID,
        (const int*)p_cnt, nullptr, nullptr);
    tgemm<EPI_PLAIN><<<dim3(4, 10, 8), 256, GSMEM>>>(
        (const __half*)p_hhh, (const __half*)p_w2h, b2, nullptr, (float*)p_oute, nullptr,
        4096, 1024, 0,
        (size_t)CAP * 4096, (size_t)DIM * 8192, (size_t)DIM, (size_t)CAP * DIM,
        (const int*)p_cnt, nullptr, nullptr);
    final_kernel<<<TKN, 256>>>(out);
    cudaStreamWaitEvent(0, e4, 0);
}